// round 7
// baseline (speedup 1.0000x reference)
#include <cuda_runtime.h>
#include <cuda_bf16.h>

#define BB 4
#define LL 128
#define DM 256
#define VV 50257
#define VPAD 50304          /* 393 * 128 */
#define NTILE 393
#define DW 768
#define HH 8
#define EE 32
#define SPLITS 9
#define SPL4 (SPLITS * 4)

// ---- scratch (static device allocations; no cudaMalloc anywhere) ----
__device__ float g_query[BB * LL * DM];
__device__ float g_part[BB * HH * SPL4 * LL * EE];
__device__ float g_reprog[BB * LL * DM];
__device__ float g_sg[4 * BB * LL * DM];
__device__ __nv_bfloat16 g_Wkh[(size_t)DM * DW];
__device__ __nv_bfloat16 g_Wkl[(size_t)DM * DW];
__device__ __nv_bfloat16 g_Wvh[(size_t)DM * DW];
__device__ __nv_bfloat16 g_Wvl[(size_t)DM * DW];
__device__ __nv_bfloat16 g_Kh[(size_t)VPAD * DM];
__device__ __nv_bfloat16 g_Kl[(size_t)VPAD * DM];
__device__ __nv_bfloat16 g_Vh[(size_t)VPAD * DM];
__device__ __nv_bfloat16 g_Vl[(size_t)VPAD * DM];
__device__ __nv_bfloat16 g_Qh[BB * LL * DM];
__device__ __nv_bfloat16 g_Ql[BB * LL * DM];

// ============================================================
// portable PTX helpers
// ============================================================
__device__ __forceinline__ unsigned smem_u32(const void* p) {
    unsigned a;
    asm("{ .reg .u64 t; cvta.to.shared.u64 t, %1; cvt.u32.u64 %0, t; }" : "=r"(a) : "l"(p));
    return a;
}
__device__ __forceinline__ void cp_async16(unsigned dst, const void* src) {
    asm volatile("cp.async.cg.shared.global [%0], [%1], 16;" :: "r"(dst), "l"(src));
}
#define CP_COMMIT() asm volatile("cp.async.commit_group;" ::: "memory")
#define CP_WAIT(n)  asm volatile("cp.async.wait_group %0;" :: "n"(n) : "memory")

__device__ __forceinline__ void ldsm_x4(unsigned* r, unsigned addr) {
    asm volatile("ldmatrix.sync.aligned.m8n8.x4.shared.b16 {%0,%1,%2,%3}, [%4];"
                 : "=r"(r[0]), "=r"(r[1]), "=r"(r[2]), "=r"(r[3]) : "r"(addr));
}
__device__ __forceinline__ void ldsm_x2(unsigned* r, unsigned addr) {
    asm volatile("ldmatrix.sync.aligned.m8n8.x2.shared.b16 {%0,%1}, [%2];"
                 : "=r"(r[0]), "=r"(r[1]) : "r"(addr));
}
__device__ __forceinline__ void ldsm_x2_t(unsigned* r, unsigned addr) {
    asm volatile("ldmatrix.sync.aligned.m8n8.x2.trans.shared.b16 {%0,%1}, [%2];"
                 : "=r"(r[0]), "=r"(r[1]) : "r"(addr));
}
__device__ __forceinline__ void mma16816(float* c, const unsigned* a, const unsigned* b) {
    asm volatile("mma.sync.aligned.m16n8k16.row.col.f32.bf16.bf16.f32 "
                 "{%0,%1,%2,%3}, {%4,%5,%6,%7}, {%8,%9}, {%0,%1,%2,%3};"
                 : "+f"(c[0]), "+f"(c[1]), "+f"(c[2]), "+f"(c[3])
                 : "r"(a[0]), "r"(a[1]), "r"(a[2]), "r"(a[3]), "r"(b[0]), "r"(b[1]));
}
__device__ __forceinline__ float ex2(float x) {
    float r;
    asm("ex2.approx.ftz.f32 %0, %1;" : "=f"(r) : "f"(x));
    return r;
}
__device__ __forceinline__ unsigned pack_bf16(float a, float b) {
    __nv_bfloat162 t(__float2bfloat16(a), __float2bfloat16(b));
    return *(unsigned*)&t;
}

// ============================================================
// conversion kernels
// ============================================================
__global__ void conv_w(const float* __restrict__ W, __nv_bfloat16* __restrict__ Wh,
                       __nv_bfloat16* __restrict__ Wl)
{
    __shared__ float tile[32][33];
    int k0 = blockIdx.x * 32, n0 = blockIdx.y * 32;
    int tx = threadIdx.x, ty = threadIdx.y;
    for (int r = ty; r < 32; r += 8)
        tile[r][tx] = W[(size_t)(k0 + r) * DM + n0 + tx];
    __syncthreads();
    for (int r = ty; r < 32; r += 8) {
        float v = tile[tx][r];
        __nv_bfloat16 h = __float2bfloat16(v);
        __nv_bfloat16 l = __float2bfloat16(v - __bfloat162float(h));
        Wh[(size_t)(n0 + r) * DW + k0 + tx] = h;
        Wl[(size_t)(n0 + r) * DW + k0 + tx] = l;
    }
}

__global__ void conv_q(const float* __restrict__ Q, __nv_bfloat16* __restrict__ Qh,
                       __nv_bfloat16* __restrict__ Ql)
{
    int i = blockIdx.x * blockDim.x + threadIdx.x;
    if (i >= BB * LL * DM) return;
    float v = Q[i];
    __nv_bfloat16 h = __float2bfloat16(v);
    Qh[i] = h;
    Ql[i] = __float2bfloat16(v - __bfloat162float(h));
}

// ============================================================
// merged KV projection GEMM (K and V in one kernel, N = 512).
// A loaded as fp32 from word_embedding, split to bf16 hi/lo in-kernel.
// CTA: 64 M-rows x 512 N-cols, 16 warps each 32x64. BK=32, double-buffered.
// 3-term split: D = Ah*Wh + Ah*Wl + Al*Wh.
// ============================================================
#define MROWS 64
#define KBK 32
#define SAF 0                        /* A fp32: 64 rows * 128B = 8192 */
#define SAH 8192                     /* A hi:   64 * 80 = 5120 */
#define SAL 13312                    /* A lo:   5120 */
#define SWH 18432                    /* W hi:   512 * 80 = 40960 */
#define SWL 59392                    /* W lo:   40960 */
#define KSTG 100352
#define KVM_SMEM (2 * KSTG)          /* 200704 */
#define KV_NCH (DW / KBK)            /* 24 */

__global__ void __launch_bounds__(512, 1)
kv_merged(const float* __restrict__ we,
          const __nv_bfloat16* __restrict__ Wkh, const __nv_bfloat16* __restrict__ Wkl,
          const __nv_bfloat16* __restrict__ Wvh, const __nv_bfloat16* __restrict__ Wvl,
          const float* __restrict__ bk, const float* __restrict__ bv,
          __nv_bfloat16* __restrict__ Kh, __nv_bfloat16* __restrict__ Kl,
          __nv_bfloat16* __restrict__ Vh, __nv_bfloat16* __restrict__ Vl)
{
    extern __shared__ char smem[];
    unsigned sb = smem_u32(smem);
    int t = threadIdx.x, lane = t & 31, wid = t >> 5;
    int mBase = blockIdx.x * MROWS;
    int wm = (wid & 1) * 32;
    int wn = (wid >> 1) * 64;

    float acc[2][8][4];
#pragma unroll
    for (int i = 0; i < 2; i++)
#pragma unroll
        for (int j = 0; j < 8; j++)
#pragma unroll
            for (int q = 0; q < 4; q++) acc[i][j][q] = 0.f;

    unsigned a_lof = (unsigned)((lane & 15) * 80 + (lane >> 4) * 16);
    int l2 = lane & 15;
    unsigned w_lof = (unsigned)((l2 & 7) * 80 + (l2 >> 3) * 16);

    int arow = t >> 3, ac = t & 7;          // A loader mapping (1 cp16/thread)
    bool avalid = (mBase + arow) < VV;

    auto load_stage = [&](int s, int k0) {
        unsigned stg = sb + s * KSTG;
        if (avalid)
            cp_async16(stg + SAF + arow * 128 + ac * 16,
                       we + (size_t)(mBase + arow) * DW + k0 + ac * 4);
#pragma unroll
        for (int i = t; i < 2048; i += 512) {
            int row = i >> 2, c = i & 3;
            const __nv_bfloat16 *ph, *pl;
            size_t go;
            if (row < 256) { ph = Wkh; pl = Wkl; go = (size_t)row * DW + k0 + c * 8; }
            else           { ph = Wvh; pl = Wvl; go = (size_t)(row - 256) * DW + k0 + c * 8; }
            unsigned d = stg + SWH + row * 80 + c * 16;
            cp_async16(d, ph + go);
            cp_async16(d + (SWL - SWH), pl + go);
        }
    };

    load_stage(0, 0);
    CP_COMMIT();

    for (int c = 0; c < KV_NCH; c++) {
        if (c + 1 < KV_NCH) {
            load_stage((c + 1) & 1, (c + 1) * KBK);
            CP_COMMIT();
            CP_WAIT(1);
        } else {
            CP_WAIT(0);
        }
        __syncthreads();

        unsigned stg = sb + (c & 1) * KSTG;

        // ---- convert A fp32 -> bf16 hi/lo (smem -> smem) ----
        {
            float4 v = make_float4(0.f, 0.f, 0.f, 0.f);
            if (avalid)
                v = *(const float4*)(smem + (c & 1) * KSTG + SAF + arow * 128 + ac * 16);
            float vv[4] = {v.x, v.y, v.z, v.w};
            unsigned hi0 = pack_bf16(vv[0], vv[1]);
            unsigned hi1 = pack_bf16(vv[2], vv[3]);
            float r0 = vv[0] - __bfloat162float(__float2bfloat16(vv[0]));
            float r1 = vv[1] - __bfloat162float(__float2bfloat16(vv[1]));
            float r2 = vv[2] - __bfloat162float(__float2bfloat16(vv[2]));
            float r3 = vv[3] - __bfloat162float(__float2bfloat16(vv[3]));
            unsigned lo0 = pack_bf16(r0, r1);
            unsigned lo1 = pack_bf16(r2, r3);
            *(uint2*)(smem + (c & 1) * KSTG + SAH + arow * 80 + ac * 8) = make_uint2(hi0, hi1);
            *(uint2*)(smem + (c & 1) * KSTG + SAL + arow * 80 + ac * 8) = make_uint2(lo0, lo1);
        }
        __syncthreads();

        unsigned aHb = stg + SAH + wm * 80 + a_lof;
        unsigned aLb = stg + SAL + wm * 80 + a_lof;
        unsigned wHb = stg + SWH + wn * 80 + w_lof;

#pragma unroll
        for (int ks = 0; ks < 2; ks++) {
            unsigned kb = ks * 32;
            unsigned ah[2][4], al2[2][4];
#pragma unroll
            for (int mt = 0; mt < 2; mt++) {
                ldsm_x4(ah[mt],  aHb + mt * (16 * 80) + kb);
                ldsm_x4(al2[mt], aLb + mt * (16 * 80) + kb);
            }
#pragma unroll
            for (int nt = 0; nt < 8; nt++) {
                unsigned bh[2], bl[2];
                unsigned waddr = wHb + nt * (8 * 80) + kb;
                ldsm_x2(bh, waddr);
                ldsm_x2(bl, waddr + (SWL - SWH));
#pragma unroll
                for (int mt = 0; mt < 2; mt++) {
                    mma16816(acc[mt][nt], ah[mt], bh);
                    mma16816(acc[mt][nt], ah[mt], bl);
                    mma16816(acc[mt][nt], al2[mt], bh);
                }
            }
        }
        __syncthreads();
    }

    // ---- epilogue: bf16 hi/lo, zeros on padded rows, K or V by column ----
    int gid = lane >> 2, tig = lane & 3;
#pragma unroll
    for (int nt = 0; nt < 8; nt++) {
        int col = wn + nt * 8 + tig * 2;
        bool isK = col < 256;
        int cc = isK ? col : col - 256;
        float2 bv2 = *(const float2*)((isK ? bk : bv) + cc);
        __nv_bfloat16* oH = isK ? Kh : Vh;
        __nv_bfloat16* oL = isK ? Kl : Vl;
#pragma unroll
        for (int mt = 0; mt < 2; mt++) {
            int r0 = mBase + wm + mt * 16 + gid;
            int r1 = r0 + 8;
            float x0 = (r0 < VV) ? acc[mt][nt][0] + bv2.x : 0.f;
            float x1 = (r0 < VV) ? acc[mt][nt][1] + bv2.y : 0.f;
            float x2 = (r1 < VV) ? acc[mt][nt][2] + bv2.x : 0.f;
            float x3 = (r1 < VV) ? acc[mt][nt][3] + bv2.y : 0.f;
            *(unsigned*)(oH + (size_t)r0 * DM + cc) = pack_bf16(x0, x1);
            *(unsigned*)(oL + (size_t)r0 * DM + cc) =
                pack_bf16(x0 - __bfloat162float(__float2bfloat16(x0)),
                          x1 - __bfloat162float(__float2bfloat16(x1)));
            *(unsigned*)(oH + (size_t)r1 * DM + cc) = pack_bf16(x2, x3);
            *(unsigned*)(oL + (size_t)r1 * DM + cc) =
                pack_bf16(x2 - __bfloat162float(__float2bfloat16(x2)),
                          x3 - __bfloat162float(__float2bfloat16(x3)));
        }
    }
}

// ============================================================
// split-K fp32 SGEMM (Q / O projections)
// ============================================================
__global__ __launch_bounds__(256) void sgemm64s(
    const float* __restrict__ A, const float* __restrict__ Bw,
    float* __restrict__ Cp, int M, int N, int K)
{
    __shared__ float As[16][68];
    __shared__ float Bs[16][68];
    int t = threadIdx.x, tx = t & 15, ty = t >> 4;
    int mB = blockIdx.x * 64, nB = blockIdx.y * 64;
    int kc = K / 4;
    int kBeg = blockIdx.z * kc, kEnd = kBeg + kc;
    float acc[4][4];
#pragma unroll
    for (int i = 0; i < 4; i++)
#pragma unroll
        for (int j = 0; j < 4; j++) acc[i][j] = 0.f;

    for (int k0 = kBeg; k0 < kEnd; k0 += 16) {
        {
            int row = t >> 2, kk = (t & 3) * 4;
            float4 av = *(const float4*)(A + (size_t)(mB + row) * K + k0 + kk);
            As[kk + 0][row] = av.x; As[kk + 1][row] = av.y;
            As[kk + 2][row] = av.z; As[kk + 3][row] = av.w;
        }
        {
            int kr = t >> 4, c4 = (t & 15) * 4;
            *(float4*)&Bs[kr][c4] = *(const float4*)(Bw + (size_t)(k0 + kr) * N + nB + c4);
        }
        __syncthreads();
#pragma unroll
        for (int kk = 0; kk < 16; kk++) {
            float4 a = *(const float4*)&As[kk][ty * 4];
            float4 b = *(const float4*)&Bs[kk][tx * 4];
            float am[4] = {a.x, a.y, a.z, a.w};
            float bn[4] = {b.x, b.y, b.z, b.w};
#pragma unroll
            for (int i = 0; i < 4; i++)
#pragma unroll
                for (int j = 0; j < 4; j++) acc[i][j] += am[i] * bn[j];
        }
        __syncthreads();
    }
    float* outz = Cp + (size_t)blockIdx.z * M * N;
#pragma unroll
    for (int i = 0; i < 4; i++) {
        int m = mB + ty * 4 + i;
#pragma unroll
        for (int j = 0; j < 4; j++) {
            int n = nB + tx * 4 + j;
            outz[(size_t)m * N + n] = acc[i][j];
        }
    }
}

__global__ void combine_bias(const float* __restrict__ Cp, const float* __restrict__ bias,
                             float* __restrict__ out)
{
    int i = blockIdx.x * blockDim.x + threadIdx.x;
    const int MN = BB * LL * DM;
    if (i >= MN) return;
    out[i] = Cp[i] + Cp[MN + i] + Cp[2 * MN + i] + Cp[3 * MN + i] + bias[i & (DM - 1)];
}

// ============================================================
// Tensor-core fused attention (S' = Q K^T, P in registers)
// ============================================================
#define KSTR 80
#define OFF_QH 0
#define OFF_QL 10240
#define OFF_KV 20480
#define KVBUF 40960
#define OFF_RED (OFF_KV + 2 * KVBUF)
#define OFF_RN  (OFF_RED + 2048)
#define ATTN_SMEM (OFF_RN + 512)

__global__ void __launch_bounds__(512, 1)
attn_tc(const __nv_bfloat16* __restrict__ Qh, const __nv_bfloat16* __restrict__ Ql,
        const __nv_bfloat16* __restrict__ Kh, const __nv_bfloat16* __restrict__ Kl,
        const __nv_bfloat16* __restrict__ Vh, const __nv_bfloat16* __restrict__ Vl,
        float* __restrict__ part)
{
    extern __shared__ char smem[];
    unsigned sb = smem_u32(smem);
    float* red = (float*)(smem + OFF_RED);
    float* rn  = (float*)(smem + OFF_RN);

    int t = threadIdx.x, lane = t & 31, wid = t >> 5;
    int s = blockIdx.x, h = blockIdx.y, b = blockIdx.z;
    int gid = lane >> 2, tig = lane & 3;
    int lg = wid & 3, vg = wid >> 2;
    int wl = lg * 32, wv = vg * 32;

    {
        size_t qbase = (size_t)(b * LL) * DM + h * EE;
        int row = t >> 2, c = t & 3;
        size_t go = qbase + (size_t)row * DM + c * 8;
        unsigned d = sb + row * KSTR + c * 16;
        cp_async16(d + OFF_QH, Qh + go);
        cp_async16(d + OFF_QL, Ql + go);
    }
    CP_COMMIT();
    CP_WAIT(0);
    __syncthreads();

    unsigned qhf[2][2][4], qlf[2][2][4];
    {
        unsigned alof = (unsigned)((lane & 15) * KSTR + (lane >> 4) * 16);
#pragma unroll
        for (int mt = 0; mt < 2; mt++)
#pragma unroll
            for (int k = 0; k < 2; k++) {
                unsigned off = (wl + 16 * mt) * KSTR + alof + k * 32;
                ldsm_x4(qhf[mt][k], sb + OFF_QH + off);
                ldsm_x4(qlf[mt][k], sb + OFF_QL + off);
            }
    }

    float accO[2][4][4];
#pragma unroll
    for (int i = 0; i < 2; i++)
#pragma unroll
        for (int j = 0; j < 4; j++)
#pragma unroll
            for (int q = 0; q < 4; q++) accO[i][j][q] = 0.f;

    size_t hof = (size_t)h * EE;
    auto load_kv = [&](int buf, int v0) {
        unsigned base = sb + OFF_KV + buf * KVBUF;
        int row = t >> 2, c = t & 3;
        size_t go = (size_t)(v0 + row) * DM + hof + c * 8;
        unsigned d = base + row * KSTR + c * 16;
        cp_async16(d,         Kh + go);
        cp_async16(d + 10240, Kl + go);
        cp_async16(d + 20480, Vh + go);
        cp_async16(d + 30720, Vl + go);
    };

    load_kv(0, s * 128);
    CP_COMMIT();

    const float CC = 0.25503327723425473f;
    int l2 = lane & 15;
    unsigned kb_lof = (unsigned)((l2 & 7) * KSTR + (l2 >> 3) * 16);

    int it = 0;
    for (int tile = s; tile < NTILE; tile += SPLITS, it++) {
        CP_WAIT(0);
        __syncthreads();

        int nxt = tile + SPLITS;
        if (nxt < NTILE) {
            load_kv((it + 1) & 1, nxt * 128);
            CP_COMMIT();
        }
        unsigned kvb = sb + OFF_KV + (it & 1) * KVBUF;

        float accS[2][4][4];
#pragma unroll
        for (int mt = 0; mt < 2; mt++)
#pragma unroll
            for (int n = 0; n < 4; n++)
#pragma unroll
                for (int q = 0; q < 4; q++) accS[mt][n][q] = 0.f;

#pragma unroll
        for (int k = 0; k < 2; k++) {
            unsigned kbh[4][2], kbl[4][2];
#pragma unroll
            for (int n = 0; n < 4; n++) {
                unsigned addr = kvb + (wv + n * 8) * KSTR + kb_lof + k * 32;
                ldsm_x2(kbh[n], addr);
                ldsm_x2(kbl[n], addr + 10240);
            }
#pragma unroll
            for (int mt = 0; mt < 2; mt++)
#pragma unroll
                for (int n = 0; n < 4; n++) {
                    mma16816(accS[mt][n], qhf[mt][k], kbh[n]);
                    mma16816(accS[mt][n], qlf[mt][k], kbh[n]);
                    mma16816(accS[mt][n], qhf[mt][k], kbl[n]);
                }
        }

        float s0[4], s1[4];
#pragma unroll
        for (int n = 0; n < 4; n++) { s0[n] = 0.f; s1[n] = 0.f; }
#pragma unroll
        for (int mt = 0; mt < 2; mt++)
#pragma unroll
            for (int n = 0; n < 4; n++) {
                accS[mt][n][0] = ex2(accS[mt][n][0] * CC);
                accS[mt][n][1] = ex2(accS[mt][n][1] * CC);
                accS[mt][n][2] = ex2(accS[mt][n][2] * CC);
                accS[mt][n][3] = ex2(accS[mt][n][3] * CC);
                s0[n] += accS[mt][n][0] + accS[mt][n][2];
                s1[n] += accS[mt][n][1] + accS[mt][n][3];
            }
#pragma unroll
        for (int n = 0; n < 4; n++) {
#pragma unroll
            for (int ofs = 4; ofs < 32; ofs <<= 1) {
                s0[n] += __shfl_xor_sync(0xffffffffu, s0[n], ofs);
                s1[n] += __shfl_xor_sync(0xffffffffu, s1[n], ofs);
            }
        }
        if (gid == 0) {
#pragma unroll
            for (int n = 0; n < 4; n++) {
                red[(wv + n * 8 + tig * 2) * 4 + lg] = s0[n];
                red[(wv + n * 8 + tig * 2 + 1) * 4 + lg] = s1[n];
            }
        }
        __syncthreads();
        if (t < 128) {
            float v = red[t * 4] + red[t * 4 + 1] + red[t * 4 + 2] + red[t * 4 + 3];
            rn[t] = 1.f / v;
        }
        __syncthreads();

#pragma unroll
        for (int n = 0; n < 4; n++) {
            float r0 = rn[wv + n * 8 + tig * 2];
            float r1 = rn[wv + n * 8 + tig * 2 + 1];
#pragma unroll
            for (int mt = 0; mt < 2; mt++) {
                accS[mt][n][0] *= r0;
                accS[mt][n][1] *= r1;
                accS[mt][n][2] *= r0;
                accS[mt][n][3] *= r1;
            }
        }

#pragma unroll
        for (int ks = 0; ks < 2; ks++) {
            unsigned vbh[4][2], vbl[4][2];
#pragma unroll
            for (int ne = 0; ne < 4; ne++) {
                unsigned addr = kvb + 20480 + (wv + ks * 16 + l2) * KSTR + ne * 16;
                ldsm_x2_t(vbh[ne], addr);
                ldsm_x2_t(vbl[ne], addr + 10240);
            }
#pragma unroll
            for (int mt = 0; mt < 2; mt++) {
                float p0 = accS[mt][2 * ks][0], p1 = accS[mt][2 * ks][1];
                float p2 = accS[mt][2 * ks][2], p3 = accS[mt][2 * ks][3];
                float p4 = accS[mt][2 * ks + 1][0], p5 = accS[mt][2 * ks + 1][1];
                float p6 = accS[mt][2 * ks + 1][2], p7 = accS[mt][2 * ks + 1][3];
                unsigned aph[4], apl[4];
                aph[0] = pack_bf16(p0, p1);
                aph[1] = pack_bf16(p2, p3);
                aph[2] = pack_bf16(p4, p5);
                aph[3] = pack_bf16(p6, p7);
                apl[0] = pack_bf16(p0 - __bfloat162float(__float2bfloat16(p0)),
                                   p1 - __bfloat162float(__float2bfloat16(p1)));
                apl[1] = pack_bf16(p2 - __bfloat162float(__float2bfloat16(p2)),
                                   p3 - __bfloat162float(__float2bfloat16(p3)));
                apl[2] = pack_bf16(p4 - __bfloat162float(__float2bfloat16(p4)),
                                   p5 - __bfloat162float(__float2bfloat16(p5)));
                apl[3] = pack_bf16(p6 - __bfloat162float(__float2bfloat16(p6)),
                                   p7 - __bfloat162float(__float2bfloat16(p7)));
#pragma unroll
                for (int ne = 0; ne < 4; ne++) {
                    mma16816(accO[mt][ne], aph, vbh[ne]);
                    mma16816(accO[mt][ne], aph, vbl[ne]);
                    mma16816(accO[mt][ne], apl, vbh[ne]);
                }
            }
        }
    }

    float* pout = part + (size_t)(((b * HH + h) * SPLITS + s) * 4 + vg) * LL * EE;
#pragma unroll
    for (int mt = 0; mt < 2; mt++) {
        int l = wl + mt * 16 + gid;
#pragma unroll
        for (int ne = 0; ne < 4; ne++) {
            int e = ne * 8 + tig * 2;
            *(float2*)(pout + l * EE + e) = make_float2(accO[mt][ne][0], accO[mt][ne][1]);
            *(float2*)(pout + (l + 8) * EE + e) = make_float2(accO[mt][ne][2], accO[mt][ne][3]);
        }
    }
}

__global__ void reduce_part(const float* __restrict__ part, float* __restrict__ reprog)
{
    int t = blockIdx.x * blockDim.x + threadIdx.x;
    if (t >= BB * LL * DM) return;
    int e = t & 31;
    int h = (t >> 5) & 7;
    int l = (t >> 8) & 127;
    int b = t >> 15;
    const float* p = part + (size_t)(b * HH + h) * SPL4 * LL * EE + l * EE + e;
    float acc = 0.f;
#pragma unroll
    for (int s2 = 0; s2 < SPL4; s2++) acc += p[(size_t)s2 * LL * EE];
    reprog[t] = acc;
}

// ============================================================
// Launch  (kv_merged deliberately at launch index 3 for ncu)
// ============================================================
extern "C" void kernel_launch(void* const* d_in, const int* in_sizes, int n_in,
                              void* d_out, int out_size)
{
    (void)in_sizes; (void)n_in; (void)out_size;
    const float* ts = (const float*)d_in[0];
    const float* we = (const float*)d_in[1];
    const float* Wq = (const float*)d_in[2];
    const float* bq = (const float*)d_in[3];
    const float* Wk = (const float*)d_in[4];
    const float* bk = (const float*)d_in[5];
    const float* Wv = (const float*)d_in[6];
    const float* bv = (const float*)d_in[7];
    const float* Wo = (const float*)d_in[8];
    const float* bo = (const float*)d_in[9];
    float* out = (float*)d_out;

    float *gq, *gp, *gr, *gsg;
    __nv_bfloat16 *wkh, *wkl, *wvh, *wvl, *kh, *kl, *vh, *vl, *qh, *ql;
    cudaGetSymbolAddress((void**)&gq, g_query);
    cudaGetSymbolAddress((void**)&gp, g_part);
    cudaGetSymbolAddress((void**)&gr, g_reprog);
    cudaGetSymbolAddress((void**)&gsg, g_sg);
    cudaGetSymbolAddress((void**)&wkh, g_Wkh);
    cudaGetSymbolAddress((void**)&wkl, g_Wkl);
    cudaGetSymbolAddress((void**)&wvh, g_Wvh);
    cudaGetSymbolAddress((void**)&wvl, g_Wvl);
    cudaGetSymbolAddress((void**)&kh, g_Kh);
    cudaGetSymbolAddress((void**)&kl, g_Kl);
    cudaGetSymbolAddress((void**)&vh, g_Vh);
    cudaGetSymbolAddress((void**)&vl, g_Vl);
    cudaGetSymbolAddress((void**)&qh, g_Qh);
    cudaGetSymbolAddress((void**)&ql, g_Ql);

    cudaFuncSetAttribute(kv_merged, cudaFuncAttributeMaxDynamicSharedMemorySize, KVM_SMEM);
    cudaFuncSetAttribute(attn_tc, cudaFuncAttributeMaxDynamicSharedMemorySize, ATTN_SMEM);

    dim3 wb(32, 8);
    conv_w<<<dim3(DW / 32, DM / 32), wb>>>(Wk, wkh, wkl);                       // idx 0
    conv_w<<<dim3(DW / 32, DM / 32), wb>>>(Wv, wvh, wvl);                       // idx 1
    sgemm64s<<<dim3(BB * LL / 64, DM / 64, 4), 256>>>(ts, Wq, gsg, BB * LL, DM, DM); // idx 2
    kv_merged<<<VPAD / MROWS, 512, KVM_SMEM>>>(we, wkh, wkl, wvh, wvl,
                                               bk, bv, kh, kl, vh, vl);         // idx 3 (profiled)
    combine_bias<<<(BB * LL * DM + 255) / 256, 256>>>(gsg, bq, gq);             // idx 4
    conv_q<<<(BB * LL * DM + 255) / 256, 256>>>(gq, qh, ql);                    // idx 5
    attn_tc<<<dim3(SPLITS, HH, BB), 512, ATTN_SMEM>>>(qh, ql, kh, kl, vh, vl, gp); // idx 6
    reduce_part<<<(BB * LL * DM + 255) / 256, 256>>>(gp, gr);                   // idx 7
    sgemm64s<<<dim3(BB * LL / 64, DM / 64, 4), 256>>>(gr, Wo, gsg, BB * LL, DM, DM); // idx 8
    combine_bias<<<(BB * LL * DM + 255) / 256, 256>>>(gsg, bo, out);            // idx 9
}

// round 8
// speedup vs baseline: 1.0292x; 1.0292x over previous
#include <cuda_runtime.h>
#include <cuda_bf16.h>

#define BB 4
#define LL 128
#define DM 256
#define VV 50257
#define VPAD 50304          /* 393 * 128 */
#define NTILE 393
#define DW 768
#define HH 8
#define EE 32
#define SPLITS 9
#define SPL4 (SPLITS * 4)

// ---- scratch (static device allocations; no cudaMalloc anywhere) ----
__device__ float g_query[BB * LL * DM];
__device__ float g_part[BB * HH * SPL4 * LL * EE];
__device__ float g_reprog[BB * LL * DM];
__device__ float g_sg[4 * BB * LL * DM];
__device__ __nv_bfloat16 g_Wkh[(size_t)DM * DW];
__device__ __nv_bfloat16 g_Wkl[(size_t)DM * DW];
__device__ __nv_bfloat16 g_Wvh[(size_t)DM * DW];
__device__ __nv_bfloat16 g_Wvl[(size_t)DM * DW];
__device__ __nv_bfloat16 g_Kh[(size_t)VPAD * DM];
__device__ __nv_bfloat16 g_Kl[(size_t)VPAD * DM];
__device__ __nv_bfloat16 g_Vh[(size_t)VPAD * DM];
__device__ __nv_bfloat16 g_Vl[(size_t)VPAD * DM];
__device__ __nv_bfloat16 g_Qh[BB * LL * DM];
__device__ __nv_bfloat16 g_Ql[BB * LL * DM];

// ============================================================
// portable PTX helpers
// ============================================================
__device__ __forceinline__ unsigned smem_u32(const void* p) {
    unsigned a;
    asm("{ .reg .u64 t; cvta.to.shared.u64 t, %1; cvt.u32.u64 %0, t; }" : "=r"(a) : "l"(p));
    return a;
}
__device__ __forceinline__ void cp_async16(unsigned dst, const void* src) {
    asm volatile("cp.async.cg.shared.global [%0], [%1], 16;" :: "r"(dst), "l"(src));
}
#define CP_COMMIT() asm volatile("cp.async.commit_group;" ::: "memory")
#define CP_WAIT(n)  asm volatile("cp.async.wait_group %0;" :: "n"(n) : "memory")

__device__ __forceinline__ void ldsm_x4(unsigned* r, unsigned addr) {
    asm volatile("ldmatrix.sync.aligned.m8n8.x4.shared.b16 {%0,%1,%2,%3}, [%4];"
                 : "=r"(r[0]), "=r"(r[1]), "=r"(r[2]), "=r"(r[3]) : "r"(addr));
}
__device__ __forceinline__ void ldsm_x2(unsigned* r, unsigned addr) {
    asm volatile("ldmatrix.sync.aligned.m8n8.x2.shared.b16 {%0,%1}, [%2];"
                 : "=r"(r[0]), "=r"(r[1]) : "r"(addr));
}
__device__ __forceinline__ void ldsm_x2_t(unsigned* r, unsigned addr) {
    asm volatile("ldmatrix.sync.aligned.m8n8.x2.trans.shared.b16 {%0,%1}, [%2];"
                 : "=r"(r[0]), "=r"(r[1]) : "r"(addr));
}
__device__ __forceinline__ void mma16816(float* c, const unsigned* a, const unsigned* b) {
    asm volatile("mma.sync.aligned.m16n8k16.row.col.f32.bf16.bf16.f32 "
                 "{%0,%1,%2,%3}, {%4,%5,%6,%7}, {%8,%9}, {%0,%1,%2,%3};"
                 : "+f"(c[0]), "+f"(c[1]), "+f"(c[2]), "+f"(c[3])
                 : "r"(a[0]), "r"(a[1]), "r"(a[2]), "r"(a[3]), "r"(b[0]), "r"(b[1]));
}
__device__ __forceinline__ float ex2(float x) {
    float r;
    asm("ex2.approx.ftz.f32 %0, %1;" : "=f"(r) : "f"(x));
    return r;
}
__device__ __forceinline__ unsigned pack_bf16(float a, float b) {
    __nv_bfloat162 t(__float2bfloat16(a), __float2bfloat16(b));
    return *(unsigned*)&t;
}

// ============================================================
// conversion kernels
// ============================================================
__global__ void conv_w(const float* __restrict__ W, __nv_bfloat16* __restrict__ Wh,
                       __nv_bfloat16* __restrict__ Wl)
{
    __shared__ float tile[32][33];
    int k0 = blockIdx.x * 32, n0 = blockIdx.y * 32;
    int tx = threadIdx.x, ty = threadIdx.y;
    for (int r = ty; r < 32; r += 8)
        tile[r][tx] = W[(size_t)(k0 + r) * DM + n0 + tx];
    __syncthreads();
    for (int r = ty; r < 32; r += 8) {
        float v = tile[tx][r];
        __nv_bfloat16 h = __float2bfloat16(v);
        __nv_bfloat16 l = __float2bfloat16(v - __bfloat162float(h));
        Wh[(size_t)(n0 + r) * DW + k0 + tx] = h;
        Wl[(size_t)(n0 + r) * DW + k0 + tx] = l;
    }
}

__global__ void conv_q(const float* __restrict__ Q, __nv_bfloat16* __restrict__ Qh,
                       __nv_bfloat16* __restrict__ Ql)
{
    int i = blockIdx.x * blockDim.x + threadIdx.x;
    if (i >= BB * LL * DM) return;
    float v = Q[i];
    __nv_bfloat16 h = __float2bfloat16(v);
    Qh[i] = h;
    Ql[i] = __float2bfloat16(v - __bfloat162float(h));
}

// ============================================================
// merged KV projection GEMM, software-pipelined:
//   A fp32: LDG -> regs -> bf16 hi/lo STS (no fp32 smem staging)
//   W bf16 hi/lo: cp.async double-buffered
//   one __syncthreads per K-chunk; conversion/copies overlap MMAs
// CTA: 64 M x 512 N, 16 warps (32x64 each). 3-term split.
// ============================================================
#define MROWS 64
#define KBK 32
#define SAH 0                        /* A hi: 64 * 80 = 5120 */
#define SAL 5120                     /* A lo: 5120 */
#define SWH 10240                    /* W hi: 512 * 80 = 40960 */
#define SWL 51200                    /* W lo: 40960 */
#define KSTG 92160
#define KVM_SMEM (2 * KSTG)          /* 184320 */
#define KV_NCH (DW / KBK)            /* 24 */

__global__ void __launch_bounds__(512, 1)
kv_merged(const float* __restrict__ we,
          const __nv_bfloat16* __restrict__ Wkh, const __nv_bfloat16* __restrict__ Wkl,
          const __nv_bfloat16* __restrict__ Wvh, const __nv_bfloat16* __restrict__ Wvl,
          const float* __restrict__ bk, const float* __restrict__ bv,
          __nv_bfloat16* __restrict__ Kh, __nv_bfloat16* __restrict__ Kl,
          __nv_bfloat16* __restrict__ Vh, __nv_bfloat16* __restrict__ Vl)
{
    extern __shared__ char smem[];
    unsigned sb = smem_u32(smem);
    int t = threadIdx.x, lane = t & 31, wid = t >> 5;
    int mBase = blockIdx.x * MROWS;
    int wm = (wid & 1) * 32;
    int wn = (wid >> 1) * 64;

    float acc[2][8][4];
#pragma unroll
    for (int i = 0; i < 2; i++)
#pragma unroll
        for (int j = 0; j < 8; j++)
#pragma unroll
            for (int q = 0; q < 4; q++) acc[i][j][q] = 0.f;

    unsigned a_lof = (unsigned)((lane & 15) * 80 + (lane >> 4) * 16);
    int l2 = lane & 31 & 15;
    unsigned w_lof = (unsigned)((l2 & 7) * 80 + (l2 >> 3) * 16);

    // A loader mapping: one float4 per thread per chunk
    int arow = t >> 3, ac = t & 7;
    bool avalid = (mBase + arow) < VV;
    const float* abase = we + (size_t)(mBase + arow) * DW + ac * 4;

    auto ldA = [&](int c) -> float4 {
        if (avalid) return *(const float4*)(abase + c * KBK);
        return make_float4(0.f, 0.f, 0.f, 0.f);
    };
    auto convSTS = [&](int s, float4 v) {
        float r0 = v.x - __bfloat162float(__float2bfloat16(v.x));
        float r1 = v.y - __bfloat162float(__float2bfloat16(v.y));
        float r2 = v.z - __bfloat162float(__float2bfloat16(v.z));
        float r3 = v.w - __bfloat162float(__float2bfloat16(v.w));
        *(uint2*)(smem + s * KSTG + SAH + arow * 80 + ac * 8) =
            make_uint2(pack_bf16(v.x, v.y), pack_bf16(v.z, v.w));
        *(uint2*)(smem + s * KSTG + SAL + arow * 80 + ac * 8) =
            make_uint2(pack_bf16(r0, r1), pack_bf16(r2, r3));
    };
    auto loadW = [&](int s, int k0) {
        unsigned stg = sb + s * KSTG;
#pragma unroll
        for (int i = t; i < 2048; i += 512) {
            int row = i >> 2, c = i & 3;
            const __nv_bfloat16 *ph, *pl;
            size_t go;
            if (row < 256) { ph = Wkh; pl = Wkl; go = (size_t)row * DW + k0 + c * 8; }
            else           { ph = Wvh; pl = Wvl; go = (size_t)(row - 256) * DW + k0 + c * 8; }
            unsigned d = stg + SWH + row * 80 + c * 16;
            cp_async16(d, ph + go);
            cp_async16(d + (SWL - SWH), pl + go);
        }
    };

    // ---- prologue: fill both stages ----
    float4 aCur = ldA(0);
    convSTS(0, aCur);
    loadW(0, 0);
    CP_COMMIT();
    aCur = ldA(1);
    convSTS(1, aCur);
    loadW(1, KBK);
    CP_COMMIT();
    CP_WAIT(1);            // stage0 W landed
    __syncthreads();       // stage0 fully published

    for (int c = 0; c < KV_NCH; c++) {
        int s = c & 1;
        if (c > 0) {
            CP_WAIT(0);        // W[c] landed
            __syncthreads();   // all warps done with MMAs of c-1 -> stage 1-s free
        }
        if (c >= 1 && c + 1 < KV_NCH) {
            convSTS(1 - s, aCur);            // A[c+1] into freed stage
            loadW(1 - s, (c + 1) * KBK);     // W[c+1]
            CP_COMMIT();
        }
        if (c + 2 < KV_NCH) aCur = ldA(c + 2);  // prefetch A[c+2]

        unsigned stg = sb + s * KSTG;
        unsigned aHb = stg + SAH + wm * 80 + a_lof;
        unsigned aLb = stg + SAL + wm * 80 + a_lof;
        unsigned wHb = stg + SWH + wn * 80 + w_lof;

#pragma unroll
        for (int ks = 0; ks < 2; ks++) {
            unsigned kb = ks * 32;
            unsigned ah[2][4], al2[2][4];
#pragma unroll
            for (int mt = 0; mt < 2; mt++) {
                ldsm_x4(ah[mt],  aHb + mt * (16 * 80) + kb);
                ldsm_x4(al2[mt], aLb + mt * (16 * 80) + kb);
            }
#pragma unroll
            for (int nt = 0; nt < 8; nt++) {
                unsigned bh[2], bl[2];
                unsigned waddr = wHb + nt * (8 * 80) + kb;
                ldsm_x2(bh, waddr);
                ldsm_x2(bl, waddr + (SWL - SWH));
#pragma unroll
                for (int mt = 0; mt < 2; mt++) {
                    mma16816(acc[mt][nt], ah[mt], bh);
                    mma16816(acc[mt][nt], ah[mt], bl);
                    mma16816(acc[mt][nt], al2[mt], bh);
                }
            }
        }
    }

    // ---- epilogue: bf16 hi/lo, zeros on padded rows, K or V by column ----
    int gid = lane >> 2, tig = lane & 3;
#pragma unroll
    for (int nt = 0; nt < 8; nt++) {
        int col = wn + nt * 8 + tig * 2;
        bool isK = col < 256;
        int cc = isK ? col : col - 256;
        float2 bv2 = *(const float2*)((isK ? bk : bv) + cc);
        __nv_bfloat16* oH = isK ? Kh : Vh;
        __nv_bfloat16* oL = isK ? Kl : Vl;
#pragma unroll
        for (int mt = 0; mt < 2; mt++) {
            int r0 = mBase + wm + mt * 16 + gid;
            int r1 = r0 + 8;
            float x0 = (r0 < VV) ? acc[mt][nt][0] + bv2.x : 0.f;
            float x1 = (r0 < VV) ? acc[mt][nt][1] + bv2.y : 0.f;
            float x2 = (r1 < VV) ? acc[mt][nt][2] + bv2.x : 0.f;
            float x3 = (r1 < VV) ? acc[mt][nt][3] + bv2.y : 0.f;
            *(unsigned*)(oH + (size_t)r0 * DM + cc) = pack_bf16(x0, x1);
            *(unsigned*)(oL + (size_t)r0 * DM + cc) =
                pack_bf16(x0 - __bfloat162float(__float2bfloat16(x0)),
                          x1 - __bfloat162float(__float2bfloat16(x1)));
            *(unsigned*)(oH + (size_t)r1 * DM + cc) = pack_bf16(x2, x3);
            *(unsigned*)(oL + (size_t)r1 * DM + cc) =
                pack_bf16(x2 - __bfloat162float(__float2bfloat16(x2)),
                          x3 - __bfloat162float(__float2bfloat16(x3)));
        }
    }
}

// ============================================================
// split-K fp32 SGEMM (Q / O projections)
// ============================================================
__global__ __launch_bounds__(256) void sgemm64s(
    const float* __restrict__ A, const float* __restrict__ Bw,
    float* __restrict__ Cp, int M, int N, int K)
{
    __shared__ float As[16][68];
    __shared__ float Bs[16][68];
    int t = threadIdx.x, tx = t & 15, ty = t >> 4;
    int mB = blockIdx.x * 64, nB = blockIdx.y * 64;
    int kc = K / 4;
    int kBeg = blockIdx.z * kc, kEnd = kBeg + kc;
    float acc[4][4];
#pragma unroll
    for (int i = 0; i < 4; i++)
#pragma unroll
        for (int j = 0; j < 4; j++) acc[i][j] = 0.f;

    for (int k0 = kBeg; k0 < kEnd; k0 += 16) {
        {
            int row = t >> 2, kk = (t & 3) * 4;
            float4 av = *(const float4*)(A + (size_t)(mB + row) * K + k0 + kk);
            As[kk + 0][row] = av.x; As[kk + 1][row] = av.y;
            As[kk + 2][row] = av.z; As[kk + 3][row] = av.w;
        }
        {
            int kr = t >> 4, c4 = (t & 15) * 4;
            *(float4*)&Bs[kr][c4] = *(const float4*)(Bw + (size_t)(k0 + kr) * N + nB + c4);
        }
        __syncthreads();
#pragma unroll
        for (int kk = 0; kk < 16; kk++) {
            float4 a = *(const float4*)&As[kk][ty * 4];
            float4 b = *(const float4*)&Bs[kk][tx * 4];
            float am[4] = {a.x, a.y, a.z, a.w};
            float bn[4] = {b.x, b.y, b.z, b.w};
#pragma unroll
            for (int i = 0; i < 4; i++)
#pragma unroll
                for (int j = 0; j < 4; j++) acc[i][j] += am[i] * bn[j];
        }
        __syncthreads();
    }
    float* outz = Cp + (size_t)blockIdx.z * M * N;
#pragma unroll
    for (int i = 0; i < 4; i++) {
        int m = mB + ty * 4 + i;
#pragma unroll
        for (int j = 0; j < 4; j++) {
            int n = nB + tx * 4 + j;
            outz[(size_t)m * N + n] = acc[i][j];
        }
    }
}

__global__ void combine_bias(const float* __restrict__ Cp, const float* __restrict__ bias,
                             float* __restrict__ out)
{
    int i = blockIdx.x * blockDim.x + threadIdx.x;
    const int MN = BB * LL * DM;
    if (i >= MN) return;
    out[i] = Cp[i] + Cp[MN + i] + Cp[2 * MN + i] + Cp[3 * MN + i] + bias[i & (DM - 1)];
}

// ============================================================
// Tensor-core fused attention (S' = Q K^T, P in registers)
// ============================================================
#define KSTR 80
#define OFF_QH 0
#define OFF_QL 10240
#define OFF_KV 20480
#define KVBUF 40960
#define OFF_RED (OFF_KV + 2 * KVBUF)
#define OFF_RN  (OFF_RED + 2048)
#define ATTN_SMEM (OFF_RN + 512)

__global__ void __launch_bounds__(512, 1)
attn_tc(const __nv_bfloat16* __restrict__ Qh, const __nv_bfloat16* __restrict__ Ql,
        const __nv_bfloat16* __restrict__ Kh, const __nv_bfloat16* __restrict__ Kl,
        const __nv_bfloat16* __restrict__ Vh, const __nv_bfloat16* __restrict__ Vl,
        float* __restrict__ part)
{
    extern __shared__ char smem[];
    unsigned sb = smem_u32(smem);
    float* red = (float*)(smem + OFF_RED);
    float* rn  = (float*)(smem + OFF_RN);

    int t = threadIdx.x, lane = t & 31, wid = t >> 5;
    int s = blockIdx.x, h = blockIdx.y, b = blockIdx.z;
    int gid = lane >> 2, tig = lane & 3;
    int lg = wid & 3, vg = wid >> 2;
    int wl = lg * 32, wv = vg * 32;

    {
        size_t qbase = (size_t)(b * LL) * DM + h * EE;
        int row = t >> 2, c = t & 3;
        size_t go = qbase + (size_t)row * DM + c * 8;
        unsigned d = sb + row * KSTR + c * 16;
        cp_async16(d + OFF_QH, Qh + go);
        cp_async16(d + OFF_QL, Ql + go);
    }
    CP_COMMIT();
    CP_WAIT(0);
    __syncthreads();

    unsigned qhf[2][2][4], qlf[2][2][4];
    {
        unsigned alof = (unsigned)((lane & 15) * KSTR + (lane >> 4) * 16);
#pragma unroll
        for (int mt = 0; mt < 2; mt++)
#pragma unroll
            for (int k = 0; k < 2; k++) {
                unsigned off = (wl + 16 * mt) * KSTR + alof + k * 32;
                ldsm_x4(qhf[mt][k], sb + OFF_QH + off);
                ldsm_x4(qlf[mt][k], sb + OFF_QL + off);
            }
    }

    float accO[2][4][4];
#pragma unroll
    for (int i = 0; i < 2; i++)
#pragma unroll
        for (int j = 0; j < 4; j++)
#pragma unroll
            for (int q = 0; q < 4; q++) accO[i][j][q] = 0.f;

    size_t hof = (size_t)h * EE;
    auto load_kv = [&](int buf, int v0) {
        unsigned base = sb + OFF_KV + buf * KVBUF;
        int row = t >> 2, c = t & 3;
        size_t go = (size_t)(v0 + row) * DM + hof + c * 8;
        unsigned d = base + row * KSTR + c * 16;
        cp_async16(d,         Kh + go);
        cp_async16(d + 10240, Kl + go);
        cp_async16(d + 20480, Vh + go);
        cp_async16(d + 30720, Vl + go);
    };

    load_kv(0, s * 128);
    CP_COMMIT();

    const float CC = 0.25503327723425473f;
    int l2 = lane & 15;
    unsigned kb_lof = (unsigned)((l2 & 7) * KSTR + (l2 >> 3) * 16);

    int it = 0;
    for (int tile = s; tile < NTILE; tile += SPLITS, it++) {
        CP_WAIT(0);
        __syncthreads();

        int nxt = tile + SPLITS;
        if (nxt < NTILE) {
            load_kv((it + 1) & 1, nxt * 128);
            CP_COMMIT();
        }
        unsigned kvb = sb + OFF_KV + (it & 1) * KVBUF;

        float accS[2][4][4];
#pragma unroll
        for (int mt = 0; mt < 2; mt++)
#pragma unroll
            for (int n = 0; n < 4; n++)
#pragma unroll
                for (int q = 0; q < 4; q++) accS[mt][n][q] = 0.f;

#pragma unroll
        for (int k = 0; k < 2; k++) {
            unsigned kbh[4][2], kbl[4][2];
#pragma unroll
            for (int n = 0; n < 4; n++) {
                unsigned addr = kvb + (wv + n * 8) * KSTR + kb_lof + k * 32;
                ldsm_x2(kbh[n], addr);
                ldsm_x2(kbl[n], addr + 10240);
            }
#pragma unroll
            for (int mt = 0; mt < 2; mt++)
#pragma unroll
                for (int n = 0; n < 4; n++) {
                    mma16816(accS[mt][n], qhf[mt][k], kbh[n]);
                    mma16816(accS[mt][n], qlf[mt][k], kbh[n]);
                    mma16816(accS[mt][n], qhf[mt][k], kbl[n]);
                }
        }

        float s0[4], s1[4];
#pragma unroll
        for (int n = 0; n < 4; n++) { s0[n] = 0.f; s1[n] = 0.f; }
#pragma unroll
        for (int mt = 0; mt < 2; mt++)
#pragma unroll
            for (int n = 0; n < 4; n++) {
                accS[mt][n][0] = ex2(accS[mt][n][0] * CC);
                accS[mt][n][1] = ex2(accS[mt][n][1] * CC);
                accS[mt][n][2] = ex2(accS[mt][n][2] * CC);
                accS[mt][n][3] = ex2(accS[mt][n][3] * CC);
                s0[n] += accS[mt][n][0] + accS[mt][n][2];
                s1[n] += accS[mt][n][1] + accS[mt][n][3];
            }
#pragma unroll
        for (int n = 0; n < 4; n++) {
#pragma unroll
            for (int ofs = 4; ofs < 32; ofs <<= 1) {
                s0[n] += __shfl_xor_sync(0xffffffffu, s0[n], ofs);
                s1[n] += __shfl_xor_sync(0xffffffffu, s1[n], ofs);
            }
        }
        if (gid == 0) {
#pragma unroll
            for (int n = 0; n < 4; n++) {
                red[(wv + n * 8 + tig * 2) * 4 + lg] = s0[n];
                red[(wv + n * 8 + tig * 2 + 1) * 4 + lg] = s1[n];
            }
        }
        __syncthreads();
        if (t < 128) {
            float v = red[t * 4] + red[t * 4 + 1] + red[t * 4 + 2] + red[t * 4 + 3];
            rn[t] = 1.f / v;
        }
        __syncthreads();

#pragma unroll
        for (int n = 0; n < 4; n++) {
            float r0 = rn[wv + n * 8 + tig * 2];
            float r1 = rn[wv + n * 8 + tig * 2 + 1];
#pragma unroll
            for (int mt = 0; mt < 2; mt++) {
                accS[mt][n][0] *= r0;
                accS[mt][n][1] *= r1;
                accS[mt][n][2] *= r0;
                accS[mt][n][3] *= r1;
            }
        }

#pragma unroll
        for (int ks = 0; ks < 2; ks++) {
            unsigned vbh[4][2], vbl[4][2];
#pragma unroll
            for (int ne = 0; ne < 4; ne++) {
                unsigned addr = kvb + 20480 + (wv + ks * 16 + l2) * KSTR + ne * 16;
                ldsm_x2_t(vbh[ne], addr);
                ldsm_x2_t(vbl[ne], addr + 10240);
            }
#pragma unroll
            for (int mt = 0; mt < 2; mt++) {
                float p0 = accS[mt][2 * ks][0], p1 = accS[mt][2 * ks][1];
                float p2 = accS[mt][2 * ks][2], p3 = accS[mt][2 * ks][3];
                float p4 = accS[mt][2 * ks + 1][0], p5 = accS[mt][2 * ks + 1][1];
                float p6 = accS[mt][2 * ks + 1][2], p7 = accS[mt][2 * ks + 1][3];
                unsigned aph[4], apl[4];
                aph[0] = pack_bf16(p0, p1);
                aph[1] = pack_bf16(p2, p3);
                aph[2] = pack_bf16(p4, p5);
                aph[3] = pack_bf16(p6, p7);
                apl[0] = pack_bf16(p0 - __bfloat162float(__float2bfloat16(p0)),
                                   p1 - __bfloat162float(__float2bfloat16(p1)));
                apl[1] = pack_bf16(p2 - __bfloat162float(__float2bfloat16(p2)),
                                   p3 - __bfloat162float(__float2bfloat16(p3)));
                apl[2] = pack_bf16(p4 - __bfloat162float(__float2bfloat16(p4)),
                                   p5 - __bfloat162float(__float2bfloat16(p5)));
                apl[3] = pack_bf16(p6 - __bfloat162float(__float2bfloat16(p6)),
                                   p7 - __bfloat162float(__float2bfloat16(p7)));
#pragma unroll
                for (int ne = 0; ne < 4; ne++) {
                    mma16816(accO[mt][ne], aph, vbh[ne]);
                    mma16816(accO[mt][ne], aph, vbl[ne]);
                    mma16816(accO[mt][ne], apl, vbh[ne]);
                }
            }
        }
    }

    float* pout = part + (size_t)(((b * HH + h) * SPLITS + s) * 4 + vg) * LL * EE;
#pragma unroll
    for (int mt = 0; mt < 2; mt++) {
        int l = wl + mt * 16 + gid;
#pragma unroll
        for (int ne = 0; ne < 4; ne++) {
            int e = ne * 8 + tig * 2;
            *(float2*)(pout + l * EE + e) = make_float2(accO[mt][ne][0], accO[mt][ne][1]);
            *(float2*)(pout + (l + 8) * EE + e) = make_float2(accO[mt][ne][2], accO[mt][ne][3]);
        }
    }
}

__global__ void reduce_part(const float* __restrict__ part, float* __restrict__ reprog)
{
    int t = blockIdx.x * blockDim.x + threadIdx.x;
    if (t >= BB * LL * DM) return;
    int e = t & 31;
    int h = (t >> 5) & 7;
    int l = (t >> 8) & 127;
    int b = t >> 15;
    const float* p = part + (size_t)(b * HH + h) * SPL4 * LL * EE + l * EE + e;
    float acc = 0.f;
#pragma unroll
    for (int s2 = 0; s2 < SPL4; s2++) acc += p[(size_t)s2 * LL * EE];
    reprog[t] = acc;
}

// ============================================================
// Launch  (kv_merged at launch index 3 for ncu)
// ============================================================
extern "C" void kernel_launch(void* const* d_in, const int* in_sizes, int n_in,
                              void* d_out, int out_size)
{
    (void)in_sizes; (void)n_in; (void)out_size;
    const float* ts = (const float*)d_in[0];
    const float* we = (const float*)d_in[1];
    const float* Wq = (const float*)d_in[2];
    const float* bq = (const float*)d_in[3];
    const float* Wk = (const float*)d_in[4];
    const float* bk = (const float*)d_in[5];
    const float* Wv = (const float*)d_in[6];
    const float* bv = (const float*)d_in[7];
    const float* Wo = (const float*)d_in[8];
    const float* bo = (const float*)d_in[9];
    float* out = (float*)d_out;

    float *gq, *gp, *gr, *gsg;
    __nv_bfloat16 *wkh, *wkl, *wvh, *wvl, *kh, *kl, *vh, *vl, *qh, *ql;
    cudaGetSymbolAddress((void**)&gq, g_query);
    cudaGetSymbolAddress((void**)&gp, g_part);
    cudaGetSymbolAddress((void**)&gr, g_reprog);
    cudaGetSymbolAddress((void**)&gsg, g_sg);
    cudaGetSymbolAddress((void**)&wkh, g_Wkh);
    cudaGetSymbolAddress((void**)&wkl, g_Wkl);
    cudaGetSymbolAddress((void**)&wvh, g_Wvh);
    cudaGetSymbolAddress((void**)&wvl, g_Wvl);
    cudaGetSymbolAddress((void**)&kh, g_Kh);
    cudaGetSymbolAddress((void**)&kl, g_Kl);
    cudaGetSymbolAddress((void**)&vh, g_Vh);
    cudaGetSymbolAddress((void**)&vl, g_Vl);
    cudaGetSymbolAddress((void**)&qh, g_Qh);
    cudaGetSymbolAddress((void**)&ql, g_Ql);

    cudaFuncSetAttribute(kv_merged, cudaFuncAttributeMaxDynamicSharedMemorySize, KVM_SMEM);
    cudaFuncSetAttribute(attn_tc, cudaFuncAttributeMaxDynamicSharedMemorySize, ATTN_SMEM);

    dim3 wb(32, 8);
    conv_w<<<dim3(DW / 32, DM / 32), wb>>>(Wk, wkh, wkl);                       // idx 0
    conv_w<<<dim3(DW / 32, DM / 32), wb>>>(Wv, wvh, wvl);                       // idx 1
    sgemm64s<<<dim3(BB * LL / 64, DM / 64, 4), 256>>>(ts, Wq, gsg, BB * LL, DM, DM); // idx 2
    kv_merged<<<VPAD / MROWS, 512, KVM_SMEM>>>(we, wkh, wkl, wvh, wvl,
                                               bk, bv, kh, kl, vh, vl);         // idx 3 (profiled)
    combine_bias<<<(BB * LL * DM + 255) / 256, 256>>>(gsg, bq, gq);             // idx 4
    conv_q<<<(BB * LL * DM + 255) / 256, 256>>>(gq, qh, ql);                    // idx 5
    attn_tc<<<dim3(SPLITS, HH, BB), 512, ATTN_SMEM>>>(qh, ql, kh, kl, vh, vl, gp); // idx 6
    reduce_part<<<(BB * LL * DM + 255) / 256, 256>>>(gp, gr);                   // idx 7
    sgemm64s<<<dim3(BB * LL / 64, DM / 64, 4), 256>>>(gr, Wo, gsg, BB * LL, DM, DM); // idx 8
    combine_bias<<<(BB * LL * DM + 255) / 256, 256>>>(gsg, bo, out);            // idx 9
}

// round 9
// speedup vs baseline: 1.0831x; 1.0524x over previous
#include <cuda_runtime.h>
#include <cuda_bf16.h>

#define BB 4
#define LL 128
#define DM 256
#define VV 50257
#define VPAD 50304          /* 393 * 128 */
#define NTILE 393
#define DW 768
#define HH 8
#define EE 32
#define SPLITS 9
#define SPL4 (SPLITS * 4)

// ---- scratch (static device allocations; no cudaMalloc anywhere) ----
__device__ float g_part[BB * HH * SPL4 * LL * EE];
__device__ float g_reprog[BB * LL * DM];
__device__ float g_sg[4 * BB * LL * DM];
__device__ __nv_bfloat16 g_Wkh[(size_t)DM * DW];
__device__ __nv_bfloat16 g_Wkl[(size_t)DM * DW];
__device__ __nv_bfloat16 g_Wvh[(size_t)DM * DW];
__device__ __nv_bfloat16 g_Wvl[(size_t)DM * DW];
__device__ __nv_bfloat16 g_Kh[(size_t)VPAD * DM];
__device__ __nv_bfloat16 g_Kl[(size_t)VPAD * DM];
__device__ __nv_bfloat16 g_Vh[(size_t)VPAD * DM];
__device__ __nv_bfloat16 g_Vl[(size_t)VPAD * DM];
__device__ __nv_bfloat16 g_Qh[BB * LL * DM];
__device__ __nv_bfloat16 g_Ql[BB * LL * DM];

// ============================================================
// portable PTX helpers
// ============================================================
__device__ __forceinline__ unsigned smem_u32(const void* p) {
    unsigned a;
    asm("{ .reg .u64 t; cvta.to.shared.u64 t, %1; cvt.u32.u64 %0, t; }" : "=r"(a) : "l"(p));
    return a;
}
__device__ __forceinline__ void cp_async16(unsigned dst, const void* src) {
    asm volatile("cp.async.cg.shared.global [%0], [%1], 16;" :: "r"(dst), "l"(src));
}
#define CP_COMMIT() asm volatile("cp.async.commit_group;" ::: "memory")
#define CP_WAIT(n)  asm volatile("cp.async.wait_group %0;" :: "n"(n) : "memory")

__device__ __forceinline__ void ldsm_x4(unsigned* r, unsigned addr) {
    asm volatile("ldmatrix.sync.aligned.m8n8.x4.shared.b16 {%0,%1,%2,%3}, [%4];"
                 : "=r"(r[0]), "=r"(r[1]), "=r"(r[2]), "=r"(r[3]) : "r"(addr));
}
__device__ __forceinline__ void ldsm_x2(unsigned* r, unsigned addr) {
    asm volatile("ldmatrix.sync.aligned.m8n8.x2.shared.b16 {%0,%1}, [%2];"
                 : "=r"(r[0]), "=r"(r[1]) : "r"(addr));
}
__device__ __forceinline__ void ldsm_x2_t(unsigned* r, unsigned addr) {
    asm volatile("ldmatrix.sync.aligned.m8n8.x2.trans.shared.b16 {%0,%1}, [%2];"
                 : "=r"(r[0]), "=r"(r[1]) : "r"(addr));
}
__device__ __forceinline__ void mma16816(float* c, const unsigned* a, const unsigned* b) {
    asm volatile("mma.sync.aligned.m16n8k16.row.col.f32.bf16.bf16.f32 "
                 "{%0,%1,%2,%3}, {%4,%5,%6,%7}, {%8,%9}, {%0,%1,%2,%3};"
                 : "+f"(c[0]), "+f"(c[1]), "+f"(c[2]), "+f"(c[3])
                 : "r"(a[0]), "r"(a[1]), "r"(a[2]), "r"(a[3]), "r"(b[0]), "r"(b[1]));
}
__device__ __forceinline__ float ex2(float x) {
    float r;
    asm("ex2.approx.ftz.f32 %0, %1;" : "=f"(r) : "f"(x));
    return r;
}
__device__ __forceinline__ unsigned pack_bf16(float a, float b) {
    __nv_bfloat162 t(__float2bfloat16(a), __float2bfloat16(b));
    return *(unsigned*)&t;
}

// ============================================================
// weight conversion: both K and V weights in one launch (z axis)
// ============================================================
__global__ void conv_w2(const float* __restrict__ Wk, const float* __restrict__ Wv,
                        __nv_bfloat16* __restrict__ Wkh, __nv_bfloat16* __restrict__ Wkl,
                        __nv_bfloat16* __restrict__ Wvh, __nv_bfloat16* __restrict__ Wvl)
{
    __shared__ float tile[32][33];
    const float* W = blockIdx.z ? Wv : Wk;
    __nv_bfloat16* Wh = blockIdx.z ? Wvh : Wkh;
    __nv_bfloat16* Wl = blockIdx.z ? Wvl : Wkl;
    int k0 = blockIdx.x * 32, n0 = blockIdx.y * 32;
    int tx = threadIdx.x, ty = threadIdx.y;
    for (int r = ty; r < 32; r += 8)
        tile[r][tx] = W[(size_t)(k0 + r) * DM + n0 + tx];
    __syncthreads();
    for (int r = ty; r < 32; r += 8) {
        float v = tile[tx][r];
        __nv_bfloat16 h = __float2bfloat16(v);
        __nv_bfloat16 l = __float2bfloat16(v - __bfloat162float(h));
        Wh[(size_t)(n0 + r) * DW + k0 + tx] = h;
        Wl[(size_t)(n0 + r) * DW + k0 + tx] = l;
    }
}

// ============================================================
// KV projection GEMM: one output (K or V) per blockIdx.y.
// CTA: 256 threads (8 warps), 64 M x 256 N, warp tile 32x64.
// __launch_bounds__(256,2): 2 CTAs/SM -> stall interleaving.
// A fp32 LDG->regs->bf16 hi/lo STS; W cp.async double-buffered.
// 3-term split: D = Ah*Wh + Ah*Wl + Al*Wh.
// ============================================================
#define MROWS 64
#define KBK 32
#define SAH 0                        /* A hi: 64*80 = 5120 */
#define SAL 5120
#define SWH 10240                    /* W hi: 256*80 = 20480 */
#define SWL 30720
#define KP_STG 51200
#define KP_SMEM (2 * KP_STG)         /* 102400 */
#define KV_NCH (DW / KBK)            /* 24 */

__global__ void __launch_bounds__(256, 2)
kv_proj(const float* __restrict__ we,
        const __nv_bfloat16* __restrict__ Wkh, const __nv_bfloat16* __restrict__ Wkl,
        const __nv_bfloat16* __restrict__ Wvh, const __nv_bfloat16* __restrict__ Wvl,
        const float* __restrict__ bk, const float* __restrict__ bv,
        __nv_bfloat16* __restrict__ Kh, __nv_bfloat16* __restrict__ Kl,
        __nv_bfloat16* __restrict__ Vh, __nv_bfloat16* __restrict__ Vl)
{
    extern __shared__ char smem[];
    unsigned sb = smem_u32(smem);
    int t = threadIdx.x, lane = t & 31, wid = t >> 5;
    int mBase = blockIdx.x * MROWS;
    int sel = blockIdx.y;
    const __nv_bfloat16* Wh = sel ? Wvh : Wkh;
    const __nv_bfloat16* Wl = sel ? Wvl : Wkl;
    const float* bias = sel ? bv : bk;
    __nv_bfloat16* oH = sel ? Vh : Kh;
    __nv_bfloat16* oL = sel ? Vl : Kl;

    int wm = (wid & 1) * 32;
    int wn = (wid >> 1) * 64;

    float acc[2][8][4];
#pragma unroll
    for (int i = 0; i < 2; i++)
#pragma unroll
        for (int j = 0; j < 8; j++)
#pragma unroll
            for (int q = 0; q < 4; q++) acc[i][j][q] = 0.f;

    unsigned a_lof = (unsigned)((lane & 15) * 80 + (lane >> 4) * 16);
    int l2 = lane & 15;
    unsigned w_lof = (unsigned)((l2 & 7) * 80 + (l2 >> 3) * 16);

    // A loader: 2 float4 per thread per chunk
    int ar0 = t >> 3, ac0 = t & 7;
    int ar1 = ar0 + 32;
    bool av0 = (mBase + ar0) < VV;
    bool av1 = (mBase + ar1) < VV;
    const float* ab0 = we + (size_t)(mBase + ar0) * DW + ac0 * 4;
    const float* ab1 = we + (size_t)(mBase + ar1) * DW + ac0 * 4;

    float4 aCur0, aCur1;
    auto ldA = [&](int c) {
        aCur0 = av0 ? *(const float4*)(ab0 + c * KBK) : make_float4(0.f, 0.f, 0.f, 0.f);
        aCur1 = av1 ? *(const float4*)(ab1 + c * KBK) : make_float4(0.f, 0.f, 0.f, 0.f);
    };
    auto convSTS = [&](int s) {
        {
            float4 v = aCur0;
            float r0 = v.x - __bfloat162float(__float2bfloat16(v.x));
            float r1 = v.y - __bfloat162float(__float2bfloat16(v.y));
            float r2 = v.z - __bfloat162float(__float2bfloat16(v.z));
            float r3 = v.w - __bfloat162float(__float2bfloat16(v.w));
            *(uint2*)(smem + s * KP_STG + SAH + ar0 * 80 + ac0 * 8) =
                make_uint2(pack_bf16(v.x, v.y), pack_bf16(v.z, v.w));
            *(uint2*)(smem + s * KP_STG + SAL + ar0 * 80 + ac0 * 8) =
                make_uint2(pack_bf16(r0, r1), pack_bf16(r2, r3));
        }
        {
            float4 v = aCur1;
            float r0 = v.x - __bfloat162float(__float2bfloat16(v.x));
            float r1 = v.y - __bfloat162float(__float2bfloat16(v.y));
            float r2 = v.z - __bfloat162float(__float2bfloat16(v.z));
            float r3 = v.w - __bfloat162float(__float2bfloat16(v.w));
            *(uint2*)(smem + s * KP_STG + SAH + ar1 * 80 + ac0 * 8) =
                make_uint2(pack_bf16(v.x, v.y), pack_bf16(v.z, v.w));
            *(uint2*)(smem + s * KP_STG + SAL + ar1 * 80 + ac0 * 8) =
                make_uint2(pack_bf16(r0, r1), pack_bf16(r2, r3));
        }
    };
    auto loadW = [&](int s, int k0) {
        unsigned stg = sb + s * KP_STG;
#pragma unroll
        for (int i = t; i < 1024; i += 256) {
            int row = i >> 2, c = i & 3;
            size_t go = (size_t)row * DW + k0 + c * 8;
            unsigned d = stg + SWH + row * 80 + c * 16;
            cp_async16(d, Wh + go);
            cp_async16(d + (SWL - SWH), Wl + go);
        }
    };

    // ---- prologue: fill both stages ----
    ldA(0);
    convSTS(0);
    loadW(0, 0);
    CP_COMMIT();
    ldA(1);
    convSTS(1);
    loadW(1, KBK);
    CP_COMMIT();
    CP_WAIT(1);
    __syncthreads();

    for (int c = 0; c < KV_NCH; c++) {
        int s = c & 1;
        if (c > 0) {
            CP_WAIT(0);
            __syncthreads();
        }
        if (c >= 1 && c + 1 < KV_NCH) {
            convSTS(1 - s);
            loadW(1 - s, (c + 1) * KBK);
            CP_COMMIT();
        }
        if (c + 2 < KV_NCH) ldA(c + 2);

        unsigned stg = sb + s * KP_STG;
        unsigned aHb = stg + SAH + wm * 80 + a_lof;
        unsigned aLb = stg + SAL + wm * 80 + a_lof;
        unsigned wHb = stg + SWH + wn * 80 + w_lof;

#pragma unroll
        for (int ks = 0; ks < 2; ks++) {
            unsigned kb = ks * 32;
            unsigned ah[2][4], al2[2][4];
#pragma unroll
            for (int mt = 0; mt < 2; mt++) {
                ldsm_x4(ah[mt],  aHb + mt * (16 * 80) + kb);
                ldsm_x4(al2[mt], aLb + mt * (16 * 80) + kb);
            }
#pragma unroll
            for (int nt = 0; nt < 8; nt++) {
                unsigned bh[2], bl[2];
                unsigned waddr = wHb + nt * (8 * 80) + kb;
                ldsm_x2(bh, waddr);
                ldsm_x2(bl, waddr + (SWL - SWH));
#pragma unroll
                for (int mt = 0; mt < 2; mt++) {
                    mma16816(acc[mt][nt], ah[mt], bh);
                    mma16816(acc[mt][nt], ah[mt], bl);
                    mma16816(acc[mt][nt], al2[mt], bh);
                }
            }
        }
    }

    // ---- epilogue: bf16 hi/lo, zeros on padded rows ----
    int gid = lane >> 2, tig = lane & 3;
#pragma unroll
    for (int nt = 0; nt < 8; nt++) {
        int col = wn + nt * 8 + tig * 2;
        float2 bv2 = *(const float2*)(bias + col);
#pragma unroll
        for (int mt = 0; mt < 2; mt++) {
            int r0 = mBase + wm + mt * 16 + gid;
            int r1 = r0 + 8;
            float x0 = (r0 < VV) ? acc[mt][nt][0] + bv2.x : 0.f;
            float x1 = (r0 < VV) ? acc[mt][nt][1] + bv2.y : 0.f;
            float x2 = (r1 < VV) ? acc[mt][nt][2] + bv2.x : 0.f;
            float x3 = (r1 < VV) ? acc[mt][nt][3] + bv2.y : 0.f;
            *(unsigned*)(oH + (size_t)r0 * DM + col) = pack_bf16(x0, x1);
            *(unsigned*)(oL + (size_t)r0 * DM + col) =
                pack_bf16(x0 - __bfloat162float(__float2bfloat16(x0)),
                          x1 - __bfloat162float(__float2bfloat16(x1)));
            *(unsigned*)(oH + (size_t)r1 * DM + col) = pack_bf16(x2, x3);
            *(unsigned*)(oL + (size_t)r1 * DM + col) =
                pack_bf16(x2 - __bfloat162float(__float2bfloat16(x2)),
                          x3 - __bfloat162float(__float2bfloat16(x3)));
        }
    }
}

// ============================================================
// split-K fp32 SGEMM (Q / O projections)
// ============================================================
__global__ __launch_bounds__(256) void sgemm64s(
    const float* __restrict__ A, const float* __restrict__ Bw,
    float* __restrict__ Cp, int M, int N, int K)
{
    __shared__ float As[16][68];
    __shared__ float Bs[16][68];
    int t = threadIdx.x, tx = t & 15, ty = t >> 4;
    int mB = blockIdx.x * 64, nB = blockIdx.y * 64;
    int kc = K / 4;
    int kBeg = blockIdx.z * kc, kEnd = kBeg + kc;
    float acc[4][4];
#pragma unroll
    for (int i = 0; i < 4; i++)
#pragma unroll
        for (int j = 0; j < 4; j++) acc[i][j] = 0.f;

    for (int k0 = kBeg; k0 < kEnd; k0 += 16) {
        {
            int row = t >> 2, kk = (t & 3) * 4;
            float4 av = *(const float4*)(A + (size_t)(mB + row) * K + k0 + kk);
            As[kk + 0][row] = av.x; As[kk + 1][row] = av.y;
            As[kk + 2][row] = av.z; As[kk + 3][row] = av.w;
        }
        {
            int kr = t >> 4, c4 = (t & 15) * 4;
            *(float4*)&Bs[kr][c4] = *(const float4*)(Bw + (size_t)(k0 + kr) * N + nB + c4);
        }
        __syncthreads();
#pragma unroll
        for (int kk = 0; kk < 16; kk++) {
            float4 a = *(const float4*)&As[kk][ty * 4];
            float4 b = *(const float4*)&Bs[kk][tx * 4];
            float am[4] = {a.x, a.y, a.z, a.w};
            float bn[4] = {b.x, b.y, b.z, b.w};
#pragma unroll
            for (int i = 0; i < 4; i++)
#pragma unroll
                for (int j = 0; j < 4; j++) acc[i][j] += am[i] * bn[j];
        }
        __syncthreads();
    }
    float* outz = Cp + (size_t)blockIdx.z * M * N;
#pragma unroll
    for (int i = 0; i < 4; i++) {
        int m = mB + ty * 4 + i;
#pragma unroll
        for (int j = 0; j < 4; j++) {
            int n = nB + tx * 4 + j;
            outz[(size_t)m * N + n] = acc[i][j];
        }
    }
}

// combine split-K partials + bias -> fp32 out
__global__ void combine_bias(const float* __restrict__ Cp, const float* __restrict__ bias,
                             float* __restrict__ out)
{
    int i = blockIdx.x * blockDim.x + threadIdx.x;
    const int MN = BB * LL * DM;
    if (i >= MN) return;
    out[i] = Cp[i] + Cp[MN + i] + Cp[2 * MN + i] + Cp[3 * MN + i] + bias[i & (DM - 1)];
}

// combine split-K partials + bias -> bf16 hi/lo (Q path; skips fp32 round-trip)
__global__ void combine_q(const float* __restrict__ Cp, const float* __restrict__ bias,
                          __nv_bfloat16* __restrict__ Qh, __nv_bfloat16* __restrict__ Ql)
{
    int i = blockIdx.x * blockDim.x + threadIdx.x;
    const int MN = BB * LL * DM;
    if (i >= MN) return;
    float v = Cp[i] + Cp[MN + i] + Cp[2 * MN + i] + Cp[3 * MN + i] + bias[i & (DM - 1)];
    __nv_bfloat16 h = __float2bfloat16(v);
    Qh[i] = h;
    Ql[i] = __float2bfloat16(v - __bfloat162float(h));
}

// ============================================================
// Tensor-core fused attention (S' = Q K^T, P in registers)
// ============================================================
#define KSTR 80
#define OFF_QH 0
#define OFF_QL 10240
#define OFF_KV 20480
#define KVBUF 40960
#define OFF_RED (OFF_KV + 2 * KVBUF)
#define OFF_RN  (OFF_RED + 2048)
#define ATTN_SMEM (OFF_RN + 512)

__global__ void __launch_bounds__(512, 1)
attn_tc(const __nv_bfloat16* __restrict__ Qh, const __nv_bfloat16* __restrict__ Ql,
        const __nv_bfloat16* __restrict__ Kh, const __nv_bfloat16* __restrict__ Kl,
        const __nv_bfloat16* __restrict__ Vh, const __nv_bfloat16* __restrict__ Vl,
        float* __restrict__ part)
{
    extern __shared__ char smem[];
    unsigned sb = smem_u32(smem);
    float* red = (float*)(smem + OFF_RED);
    float* rn  = (float*)(smem + OFF_RN);

    int t = threadIdx.x, lane = t & 31, wid = t >> 5;
    int s = blockIdx.x, h = blockIdx.y, b = blockIdx.z;
    int gid = lane >> 2, tig = lane & 3;
    int lg = wid & 3, vg = wid >> 2;
    int wl = lg * 32, wv = vg * 32;

    {
        size_t qbase = (size_t)(b * LL) * DM + h * EE;
        int row = t >> 2, c = t & 3;
        size_t go = qbase + (size_t)row * DM + c * 8;
        unsigned d = sb + row * KSTR + c * 16;
        cp_async16(d + OFF_QH, Qh + go);
        cp_async16(d + OFF_QL, Ql + go);
    }
    CP_COMMIT();
    CP_WAIT(0);
    __syncthreads();

    unsigned qhf[2][2][4], qlf[2][2][4];
    {
        unsigned alof = (unsigned)((lane & 15) * KSTR + (lane >> 4) * 16);
#pragma unroll
        for (int mt = 0; mt < 2; mt++)
#pragma unroll
            for (int k = 0; k < 2; k++) {
                unsigned off = (wl + 16 * mt) * KSTR + alof + k * 32;
                ldsm_x4(qhf[mt][k], sb + OFF_QH + off);
                ldsm_x4(qlf[mt][k], sb + OFF_QL + off);
            }
    }

    float accO[2][4][4];
#pragma unroll
    for (int i = 0; i < 2; i++)
#pragma unroll
        for (int j = 0; j < 4; j++)
#pragma unroll
            for (int q = 0; q < 4; q++) accO[i][j][q] = 0.f;

    size_t hof = (size_t)h * EE;
    auto load_kv = [&](int buf, int v0) {
        unsigned base = sb + OFF_KV + buf * KVBUF;
        int row = t >> 2, c = t & 3;
        size_t go = (size_t)(v0 + row) * DM + hof + c * 8;
        unsigned d = base + row * KSTR + c * 16;
        cp_async16(d,         Kh + go);
        cp_async16(d + 10240, Kl + go);
        cp_async16(d + 20480, Vh + go);
        cp_async16(d + 30720, Vl + go);
    };

    load_kv(0, s * 128);
    CP_COMMIT();

    const float CC = 0.25503327723425473f;
    int l2 = lane & 15;
    unsigned kb_lof = (unsigned)((l2 & 7) * KSTR + (l2 >> 3) * 16);

    int it = 0;
    for (int tile = s; tile < NTILE; tile += SPLITS, it++) {
        CP_WAIT(0);
        __syncthreads();

        int nxt = tile + SPLITS;
        if (nxt < NTILE) {
            load_kv((it + 1) & 1, nxt * 128);
            CP_COMMIT();
        }
        unsigned kvb = sb + OFF_KV + (it & 1) * KVBUF;

        float accS[2][4][4];
#pragma unroll
        for (int mt = 0; mt < 2; mt++)
#pragma unroll
            for (int n = 0; n < 4; n++)
#pragma unroll
                for (int q = 0; q < 4; q++) accS[mt][n][q] = 0.f;

#pragma unroll
        for (int k = 0; k < 2; k++) {
            unsigned kbh[4][2], kbl[4][2];
#pragma unroll
            for (int n = 0; n < 4; n++) {
                unsigned addr = kvb + (wv + n * 8) * KSTR + kb_lof + k * 32;
                ldsm_x2(kbh[n], addr);
                ldsm_x2(kbl[n], addr + 10240);
            }
#pragma unroll
            for (int mt = 0; mt < 2; mt++)
#pragma unroll
                for (int n = 0; n < 4; n++) {
                    mma16816(accS[mt][n], qhf[mt][k], kbh[n]);
                    mma16816(accS[mt][n], qlf[mt][k], kbh[n]);
                    mma16816(accS[mt][n], qhf[mt][k], kbl[n]);
                }
        }

        float s0[4], s1[4];
#pragma unroll
        for (int n = 0; n < 4; n++) { s0[n] = 0.f; s1[n] = 0.f; }
#pragma unroll
        for (int mt = 0; mt < 2; mt++)
#pragma unroll
            for (int n = 0; n < 4; n++) {
                accS[mt][n][0] = ex2(accS[mt][n][0] * CC);
                accS[mt][n][1] = ex2(accS[mt][n][1] * CC);
                accS[mt][n][2] = ex2(accS[mt][n][2] * CC);
                accS[mt][n][3] = ex2(accS[mt][n][3] * CC);
                s0[n] += accS[mt][n][0] + accS[mt][n][2];
                s1[n] += accS[mt][n][1] + accS[mt][n][3];
            }
#pragma unroll
        for (int n = 0; n < 4; n++) {
#pragma unroll
            for (int ofs = 4; ofs < 32; ofs <<= 1) {
                s0[n] += __shfl_xor_sync(0xffffffffu, s0[n], ofs);
                s1[n] += __shfl_xor_sync(0xffffffffu, s1[n], ofs);
            }
        }
        if (gid == 0) {
#pragma unroll
            for (int n = 0; n < 4; n++) {
                red[(wv + n * 8 + tig * 2) * 4 + lg] = s0[n];
                red[(wv + n * 8 + tig * 2 + 1) * 4 + lg] = s1[n];
            }
        }
        __syncthreads();
        if (t < 128) {
            float v = red[t * 4] + red[t * 4 + 1] + red[t * 4 + 2] + red[t * 4 + 3];
            rn[t] = 1.f / v;
        }
        __syncthreads();

#pragma unroll
        for (int n = 0; n < 4; n++) {
            float r0 = rn[wv + n * 8 + tig * 2];
            float r1 = rn[wv + n * 8 + tig * 2 + 1];
#pragma unroll
            for (int mt = 0; mt < 2; mt++) {
                accS[mt][n][0] *= r0;
                accS[mt][n][1] *= r1;
                accS[mt][n][2] *= r0;
                accS[mt][n][3] *= r1;
            }
        }

#pragma unroll
        for (int ks = 0; ks < 2; ks++) {
            unsigned vbh[4][2], vbl[4][2];
#pragma unroll
            for (int ne = 0; ne < 4; ne++) {
                unsigned addr = kvb + 20480 + (wv + ks * 16 + l2) * KSTR + ne * 16;
                ldsm_x2_t(vbh[ne], addr);
                ldsm_x2_t(vbl[ne], addr + 10240);
            }
#pragma unroll
            for (int mt = 0; mt < 2; mt++) {
                float p0 = accS[mt][2 * ks][0], p1 = accS[mt][2 * ks][1];
                float p2 = accS[mt][2 * ks][2], p3 = accS[mt][2 * ks][3];
                float p4 = accS[mt][2 * ks + 1][0], p5 = accS[mt][2 * ks + 1][1];
                float p6 = accS[mt][2 * ks + 1][2], p7 = accS[mt][2 * ks + 1][3];
                unsigned aph[4], apl[4];
                aph[0] = pack_bf16(p0, p1);
                aph[1] = pack_bf16(p2, p3);
                aph[2] = pack_bf16(p4, p5);
                aph[3] = pack_bf16(p6, p7);
                apl[0] = pack_bf16(p0 - __bfloat162float(__float2bfloat16(p0)),
                                   p1 - __bfloat162float(__float2bfloat16(p1)));
                apl[1] = pack_bf16(p2 - __bfloat162float(__float2bfloat16(p2)),
                                   p3 - __bfloat162float(__float2bfloat16(p3)));
                apl[2] = pack_bf16(p4 - __bfloat162float(__float2bfloat16(p4)),
                                   p5 - __bfloat162float(__float2bfloat16(p5)));
                apl[3] = pack_bf16(p6 - __bfloat162float(__float2bfloat16(p6)),
                                   p7 - __bfloat162float(__float2bfloat16(p7)));
#pragma unroll
                for (int ne = 0; ne < 4; ne++) {
                    mma16816(accO[mt][ne], aph, vbh[ne]);
                    mma16816(accO[mt][ne], aph, vbl[ne]);
                    mma16816(accO[mt][ne], apl, vbh[ne]);
                }
            }
        }
    }

    float* pout = part + (size_t)(((b * HH + h) * SPLITS + s) * 4 + vg) * LL * EE;
#pragma unroll
    for (int mt = 0; mt < 2; mt++) {
        int l = wl + mt * 16 + gid;
#pragma unroll
        for (int ne = 0; ne < 4; ne++) {
            int e = ne * 8 + tig * 2;
            *(float2*)(pout + l * EE + e) = make_float2(accO[mt][ne][0], accO[mt][ne][1]);
            *(float2*)(pout + (l + 8) * EE + e) = make_float2(accO[mt][ne][2], accO[mt][ne][3]);
        }
    }
}

__global__ void reduce_part(const float* __restrict__ part, float* __restrict__ reprog)
{
    int t = blockIdx.x * blockDim.x + threadIdx.x;
    if (t >= BB * LL * DM) return;
    int e = t & 31;
    int h = (t >> 5) & 7;
    int l = (t >> 8) & 127;
    int b = t >> 15;
    const float* p = part + (size_t)(b * HH + h) * SPL4 * LL * EE + l * EE + e;
    float acc = 0.f;
#pragma unroll
    for (int s2 = 0; s2 < SPL4; s2++) acc += p[(size_t)s2 * LL * EE];
    reprog[t] = acc;
}

// ============================================================
// Launch  (kv_proj at launch index 3 for ncu)
// ============================================================
extern "C" void kernel_launch(void* const* d_in, const int* in_sizes, int n_in,
                              void* d_out, int out_size)
{
    (void)in_sizes; (void)n_in; (void)out_size;
    const float* ts = (const float*)d_in[0];
    const float* we = (const float*)d_in[1];
    const float* Wq = (const float*)d_in[2];
    const float* bq = (const float*)d_in[3];
    const float* Wk = (const float*)d_in[4];
    const float* bk = (const float*)d_in[5];
    const float* Wv = (const float*)d_in[6];
    const float* bv = (const float*)d_in[7];
    const float* Wo = (const float*)d_in[8];
    const float* bo = (const float*)d_in[9];
    float* out = (float*)d_out;

    float *gp, *gr, *gsg;
    __nv_bfloat16 *wkh, *wkl, *wvh, *wvl, *kh, *kl, *vh, *vl, *qh, *ql;
    cudaGetSymbolAddress((void**)&gp, g_part);
    cudaGetSymbolAddress((void**)&gr, g_reprog);
    cudaGetSymbolAddress((void**)&gsg, g_sg);
    cudaGetSymbolAddress((void**)&wkh, g_Wkh);
    cudaGetSymbolAddress((void**)&wkl, g_Wkl);
    cudaGetSymbolAddress((void**)&wvh, g_Wvh);
    cudaGetSymbolAddress((void**)&wvl, g_Wvl);
    cudaGetSymbolAddress((void**)&kh, g_Kh);
    cudaGetSymbolAddress((void**)&kl, g_Kl);
    cudaGetSymbolAddress((void**)&vh, g_Vh);
    cudaGetSymbolAddress((void**)&vl, g_Vl);
    cudaGetSymbolAddress((void**)&qh, g_Qh);
    cudaGetSymbolAddress((void**)&ql, g_Ql);

    cudaFuncSetAttribute(kv_proj, cudaFuncAttributeMaxDynamicSharedMemorySize, KP_SMEM);
    cudaFuncSetAttribute(attn_tc, cudaFuncAttributeMaxDynamicSharedMemorySize, ATTN_SMEM);

    dim3 wb(32, 8);
    conv_w2<<<dim3(DW / 32, DM / 32, 2), wb>>>(Wk, Wv, wkh, wkl, wvh, wvl);     // idx 0
    sgemm64s<<<dim3(BB * LL / 64, DM / 64, 4), 256>>>(ts, Wq, gsg, BB * LL, DM, DM); // idx 1
    combine_q<<<(BB * LL * DM + 255) / 256, 256>>>(gsg, bq, qh, ql);            // idx 2
    kv_proj<<<dim3(VPAD / MROWS, 2), 256, KP_SMEM>>>(we, wkh, wkl, wvh, wvl,
                                                     bk, bv, kh, kl, vh, vl);   // idx 3 (profiled)
    attn_tc<<<dim3(SPLITS, HH, BB), 512, ATTN_SMEM>>>(qh, ql, kh, kl, vh, vl, gp); // idx 4
    reduce_part<<<(BB * LL * DM + 255) / 256, 256>>>(gp, gr);                   // idx 5
    sgemm64s<<<dim3(BB * LL / 64, DM / 64, 4), 256>>>(gr, Wo, gsg, BB * LL, DM, DM); // idx 6
    combine_bias<<<(BB * LL * DM + 255) / 256, 256>>>(gsg, bo, out);            // idx 7
}

// round 10
// speedup vs baseline: 1.1405x; 1.0530x over previous
#include <cuda_runtime.h>
#include <cuda_bf16.h>

#define BB 4
#define LL 128
#define DM 256
#define VV 50257
#define VPAD 50304          /* 393 * 128 */
#define NTILE 393
#define DW 768
#define HH 8
#define EE 32
#define SPLITS 9
#define SPL4 (SPLITS * 4)

// ---- scratch ----
__device__ float g_part[BB * HH * SPL4 * LL * EE];
__device__ float g_reprog[BB * LL * DM];
__device__ float g_sg[4 * BB * LL * DM];
__device__ __nv_bfloat16 g_Wkh[(size_t)DM * DW];
__device__ __nv_bfloat16 g_Wkl[(size_t)DM * DW];
__device__ __nv_bfloat16 g_Wvh[(size_t)DM * DW];
__device__ __nv_bfloat16 g_Wvl[(size_t)DM * DW];
__device__ __nv_bfloat16 g_Kh[(size_t)VPAD * DM];
__device__ __nv_bfloat16 g_Kl[(size_t)VPAD * DM];
__device__ __nv_bfloat16 g_Vh[(size_t)VPAD * DM];
__device__ __nv_bfloat16 g_Vl[(size_t)VPAD * DM];
__device__ __nv_bfloat16 g_Qh[BB * LL * DM];
__device__ __nv_bfloat16 g_Ql[BB * LL * DM];

// ============================================================
// portable PTX helpers
// ============================================================
__device__ __forceinline__ unsigned smem_u32(const void* p) {
    unsigned a;
    asm("{ .reg .u64 t; cvta.to.shared.u64 t, %1; cvt.u32.u64 %0, t; }" : "=r"(a) : "l"(p));
    return a;
}
__device__ __forceinline__ void cp_async16(unsigned dst, const void* src) {
    asm volatile("cp.async.cg.shared.global [%0], [%1], 16;" :: "r"(dst), "l"(src));
}
#define CP_COMMIT() asm volatile("cp.async.commit_group;" ::: "memory")
#define CP_WAIT(n)  asm volatile("cp.async.wait_group %0;" :: "n"(n) : "memory")

__device__ __forceinline__ void ldsm_x4(unsigned* r, unsigned addr) {
    asm volatile("ldmatrix.sync.aligned.m8n8.x4.shared.b16 {%0,%1,%2,%3}, [%4];"
                 : "=r"(r[0]), "=r"(r[1]), "=r"(r[2]), "=r"(r[3]) : "r"(addr));
}
__device__ __forceinline__ void ldsm_x2(unsigned* r, unsigned addr) {
    asm volatile("ldmatrix.sync.aligned.m8n8.x2.shared.b16 {%0,%1}, [%2];"
                 : "=r"(r[0]), "=r"(r[1]) : "r"(addr));
}
__device__ __forceinline__ void ldsm_x2_t(unsigned* r, unsigned addr) {
    asm volatile("ldmatrix.sync.aligned.m8n8.x2.trans.shared.b16 {%0,%1}, [%2];"
                 : "=r"(r[0]), "=r"(r[1]) : "r"(addr));
}
__device__ __forceinline__ void mma16816(float* c, const unsigned* a, const unsigned* b) {
    asm volatile("mma.sync.aligned.m16n8k16.row.col.f32.bf16.bf16.f32 "
                 "{%0,%1,%2,%3}, {%4,%5,%6,%7}, {%8,%9}, {%0,%1,%2,%3};"
                 : "+f"(c[0]), "+f"(c[1]), "+f"(c[2]), "+f"(c[3])
                 : "r"(a[0]), "r"(a[1]), "r"(a[2]), "r"(a[3]), "r"(b[0]), "r"(b[1]));
}
__device__ __forceinline__ float ex2(float x) {
    float r;
    asm("ex2.approx.ftz.f32 %0, %1;" : "=f"(r) : "f"(x));
    return r;
}
__device__ __forceinline__ unsigned pack_bf16(float a, float b) {
    __nv_bfloat162 t(__float2bfloat16(a), __float2bfloat16(b));
    return *(unsigned*)&t;
}

// ============================================================
// weight conversion (K and V in one launch)
// ============================================================
__global__ void conv_w2(const float* __restrict__ Wk, const float* __restrict__ Wv,
                        __nv_bfloat16* __restrict__ Wkh, __nv_bfloat16* __restrict__ Wkl,
                        __nv_bfloat16* __restrict__ Wvh, __nv_bfloat16* __restrict__ Wvl)
{
    __shared__ float tile[32][33];
    const float* W = blockIdx.z ? Wv : Wk;
    __nv_bfloat16* Wh = blockIdx.z ? Wvh : Wkh;
    __nv_bfloat16* Wl = blockIdx.z ? Wvl : Wkl;
    int k0 = blockIdx.x * 32, n0 = blockIdx.y * 32;
    int tx = threadIdx.x, ty = threadIdx.y;
    for (int r = ty; r < 32; r += 8)
        tile[r][tx] = W[(size_t)(k0 + r) * DM + n0 + tx];
    __syncthreads();
    for (int r = ty; r < 32; r += 8) {
        float v = tile[tx][r];
        __nv_bfloat16 h = __float2bfloat16(v);
        __nv_bfloat16 l = __float2bfloat16(v - __bfloat162float(h));
        Wh[(size_t)(n0 + r) * DW + k0 + tx] = h;
        Wl[(size_t)(n0 + r) * DW + k0 + tx] = l;
    }
}

// ============================================================
// KV projection GEMM — term-major MMA ordering (no acc chains)
// ============================================================
#define MROWS 64
#define KBK 32
#define SAH 0
#define SAL 5120
#define SWH 10240
#define SWL 30720
#define KP_STG 51200
#define KP_SMEM (2 * KP_STG)
#define KV_NCH (DW / KBK)

__global__ void __launch_bounds__(256, 2)
kv_proj(const float* __restrict__ we,
        const __nv_bfloat16* __restrict__ Wkh, const __nv_bfloat16* __restrict__ Wkl,
        const __nv_bfloat16* __restrict__ Wvh, const __nv_bfloat16* __restrict__ Wvl,
        const float* __restrict__ bk, const float* __restrict__ bv,
        __nv_bfloat16* __restrict__ Kh, __nv_bfloat16* __restrict__ Kl,
        __nv_bfloat16* __restrict__ Vh, __nv_bfloat16* __restrict__ Vl)
{
    extern __shared__ char smem[];
    unsigned sb = smem_u32(smem);
    int t = threadIdx.x, lane = t & 31, wid = t >> 5;
    int mBase = blockIdx.x * MROWS;
    int sel = blockIdx.y;
    const __nv_bfloat16* Wh = sel ? Wvh : Wkh;
    const __nv_bfloat16* Wl = sel ? Wvl : Wkl;
    const float* bias = sel ? bv : bk;
    __nv_bfloat16* oH = sel ? Vh : Kh;
    __nv_bfloat16* oL = sel ? Vl : Kl;

    int wm = (wid & 1) * 32;
    int wn = (wid >> 1) * 64;

    float acc[2][8][4];
#pragma unroll
    for (int i = 0; i < 2; i++)
#pragma unroll
        for (int j = 0; j < 8; j++)
#pragma unroll
            for (int q = 0; q < 4; q++) acc[i][j][q] = 0.f;

    unsigned a_lof = (unsigned)((lane & 15) * 80 + (lane >> 4) * 16);
    int l2 = lane & 15;
    unsigned w_lof = (unsigned)((l2 & 7) * 80 + (l2 >> 3) * 16);

    int ar0 = t >> 3, ac0 = t & 7;
    int ar1 = ar0 + 32;
    bool av0 = (mBase + ar0) < VV;
    bool av1 = (mBase + ar1) < VV;
    const float* ab0 = we + (size_t)(mBase + ar0) * DW + ac0 * 4;
    const float* ab1 = we + (size_t)(mBase + ar1) * DW + ac0 * 4;

    float4 aCur0, aCur1;
    auto ldA = [&](int c) {
        aCur0 = av0 ? *(const float4*)(ab0 + c * KBK) : make_float4(0.f, 0.f, 0.f, 0.f);
        aCur1 = av1 ? *(const float4*)(ab1 + c * KBK) : make_float4(0.f, 0.f, 0.f, 0.f);
    };
    auto convSTS = [&](int s) {
        {
            float4 v = aCur0;
            float r0 = v.x - __bfloat162float(__float2bfloat16(v.x));
            float r1 = v.y - __bfloat162float(__float2bfloat16(v.y));
            float r2 = v.z - __bfloat162float(__float2bfloat16(v.z));
            float r3 = v.w - __bfloat162float(__float2bfloat16(v.w));
            *(uint2*)(smem + s * KP_STG + SAH + ar0 * 80 + ac0 * 8) =
                make_uint2(pack_bf16(v.x, v.y), pack_bf16(v.z, v.w));
            *(uint2*)(smem + s * KP_STG + SAL + ar0 * 80 + ac0 * 8) =
                make_uint2(pack_bf16(r0, r1), pack_bf16(r2, r3));
        }
        {
            float4 v = aCur1;
            float r0 = v.x - __bfloat162float(__float2bfloat16(v.x));
            float r1 = v.y - __bfloat162float(__float2bfloat16(v.y));
            float r2 = v.z - __bfloat162float(__float2bfloat16(v.z));
            float r3 = v.w - __bfloat162float(__float2bfloat16(v.w));
            *(uint2*)(smem + s * KP_STG + SAH + ar1 * 80 + ac0 * 8) =
                make_uint2(pack_bf16(v.x, v.y), pack_bf16(v.z, v.w));
            *(uint2*)(smem + s * KP_STG + SAL + ar1 * 80 + ac0 * 8) =
                make_uint2(pack_bf16(r0, r1), pack_bf16(r2, r3));
        }
    };
    auto loadW = [&](int s, int k0) {
        unsigned stg = sb + s * KP_STG;
#pragma unroll
        for (int i = t; i < 1024; i += 256) {
            int row = i >> 2, c = i & 3;
            size_t go = (size_t)row * DW + k0 + c * 8;
            unsigned d = stg + SWH + row * 80 + c * 16;
            cp_async16(d, Wh + go);
            cp_async16(d + (SWL - SWH), Wl + go);
        }
    };

    ldA(0);
    convSTS(0);
    loadW(0, 0);
    CP_COMMIT();
    ldA(1);
    convSTS(1);
    loadW(1, KBK);
    CP_COMMIT();
    CP_WAIT(1);
    __syncthreads();

    for (int c = 0; c < KV_NCH; c++) {
        int s = c & 1;
        if (c > 0) {
            CP_WAIT(0);
            __syncthreads();
        }
        if (c >= 1 && c + 1 < KV_NCH) {
            convSTS(1 - s);
            loadW(1 - s, (c + 1) * KBK);
            CP_COMMIT();
        }
        if (c + 2 < KV_NCH) ldA(c + 2);

        unsigned stg = sb + s * KP_STG;
        unsigned aHb = stg + SAH + wm * 80 + a_lof;
        unsigned aLb = stg + SAL + wm * 80 + a_lof;
        unsigned wHb = stg + SWH + wn * 80 + w_lof;

#pragma unroll
        for (int ks = 0; ks < 2; ks++) {
            unsigned kb = ks * 32;
            unsigned ah[2][4], al2[2][4], bh[8][2], bl[8][2];
#pragma unroll
            for (int mt = 0; mt < 2; mt++) {
                ldsm_x4(ah[mt],  aHb + mt * (16 * 80) + kb);
                ldsm_x4(al2[mt], aLb + mt * (16 * 80) + kb);
            }
#pragma unroll
            for (int nt = 0; nt < 8; nt++) {
                unsigned waddr = wHb + nt * (8 * 80) + kb;
                ldsm_x2(bh[nt], waddr);
                ldsm_x2(bl[nt], waddr + (SWL - SWH));
            }
            // term-major: 16 independent MMAs between same-acc reuses
#pragma unroll
            for (int nt = 0; nt < 8; nt++)
#pragma unroll
                for (int mt = 0; mt < 2; mt++) mma16816(acc[mt][nt], ah[mt], bh[nt]);
#pragma unroll
            for (int nt = 0; nt < 8; nt++)
#pragma unroll
                for (int mt = 0; mt < 2; mt++) mma16816(acc[mt][nt], ah[mt], bl[nt]);
#pragma unroll
            for (int nt = 0; nt < 8; nt++)
#pragma unroll
                for (int mt = 0; mt < 2; mt++) mma16816(acc[mt][nt], al2[mt], bh[nt]);
        }
    }

    int gid = lane >> 2, tig = lane & 3;
#pragma unroll
    for (int nt = 0; nt < 8; nt++) {
        int col = wn + nt * 8 + tig * 2;
        float2 bv2 = *(const float2*)(bias + col);
#pragma unroll
        for (int mt = 0; mt < 2; mt++) {
            int r0 = mBase + wm + mt * 16 + gid;
            int r1 = r0 + 8;
            float x0 = (r0 < VV) ? acc[mt][nt][0] + bv2.x : 0.f;
            float x1 = (r0 < VV) ? acc[mt][nt][1] + bv2.y : 0.f;
            float x2 = (r1 < VV) ? acc[mt][nt][2] + bv2.x : 0.f;
            float x3 = (r1 < VV) ? acc[mt][nt][3] + bv2.y : 0.f;
            *(unsigned*)(oH + (size_t)r0 * DM + col) = pack_bf16(x0, x1);
            *(unsigned*)(oL + (size_t)r0 * DM + col) =
                pack_bf16(x0 - __bfloat162float(__float2bfloat16(x0)),
                          x1 - __bfloat162float(__float2bfloat16(x1)));
            *(unsigned*)(oH + (size_t)r1 * DM + col) = pack_bf16(x2, x3);
            *(unsigned*)(oL + (size_t)r1 * DM + col) =
                pack_bf16(x2 - __bfloat162float(__float2bfloat16(x2)),
                          x3 - __bfloat162float(__float2bfloat16(x3)));
        }
    }
}

// ============================================================
// split-K fp32 SGEMM (Q / O projections)
// ============================================================
__global__ __launch_bounds__(256) void sgemm64s(
    const float* __restrict__ A, const float* __restrict__ Bw,
    float* __restrict__ Cp, int M, int N, int K)
{
    __shared__ float As[16][68];
    __shared__ float Bs[16][68];
    int t = threadIdx.x, tx = t & 15, ty = t >> 4;
    int mB = blockIdx.x * 64, nB = blockIdx.y * 64;
    int kc = K / 4;
    int kBeg = blockIdx.z * kc, kEnd = kBeg + kc;
    float acc[4][4];
#pragma unroll
    for (int i = 0; i < 4; i++)
#pragma unroll
        for (int j = 0; j < 4; j++) acc[i][j] = 0.f;

    for (int k0 = kBeg; k0 < kEnd; k0 += 16) {
        {
            int row = t >> 2, kk = (t & 3) * 4;
            float4 av = *(const float4*)(A + (size_t)(mB + row) * K + k0 + kk);
            As[kk + 0][row] = av.x; As[kk + 1][row] = av.y;
            As[kk + 2][row] = av.z; As[kk + 3][row] = av.w;
        }
        {
            int kr = t >> 4, c4 = (t & 15) * 4;
            *(float4*)&Bs[kr][c4] = *(const float4*)(Bw + (size_t)(k0 + kr) * N + nB + c4);
        }
        __syncthreads();
#pragma unroll
        for (int kk = 0; kk < 16; kk++) {
            float4 a = *(const float4*)&As[kk][ty * 4];
            float4 b = *(const float4*)&Bs[kk][tx * 4];
            float am[4] = {a.x, a.y, a.z, a.w};
            float bn[4] = {b.x, b.y, b.z, b.w};
#pragma unroll
            for (int i = 0; i < 4; i++)
#pragma unroll
                for (int j = 0; j < 4; j++) acc[i][j] += am[i] * bn[j];
        }
        __syncthreads();
    }
    float* outz = Cp + (size_t)blockIdx.z * M * N;
#pragma unroll
    for (int i = 0; i < 4; i++) {
        int m = mB + ty * 4 + i;
#pragma unroll
        for (int j = 0; j < 4; j++) {
            int n = nB + tx * 4 + j;
            outz[(size_t)m * N + n] = acc[i][j];
        }
    }
}

__global__ void combine_bias(const float* __restrict__ Cp, const float* __restrict__ bias,
                             float* __restrict__ out)
{
    int i = blockIdx.x * blockDim.x + threadIdx.x;
    const int MN = BB * LL * DM;
    if (i >= MN) return;
    out[i] = Cp[i] + Cp[MN + i] + Cp[2 * MN + i] + Cp[3 * MN + i] + bias[i & (DM - 1)];
}

__global__ void combine_q(const float* __restrict__ Cp, const float* __restrict__ bias,
                          __nv_bfloat16* __restrict__ Qh, __nv_bfloat16* __restrict__ Ql)
{
    int i = blockIdx.x * blockDim.x + threadIdx.x;
    const int MN = BB * LL * DM;
    if (i >= MN) return;
    float v = Cp[i] + Cp[MN + i] + Cp[2 * MN + i] + Cp[3 * MN + i] + bias[i & (DM - 1)];
    __nv_bfloat16 h = __float2bfloat16(v);
    Qh[i] = h;
    Ql[i] = __float2bfloat16(v - __bfloat162float(h));
}

// ============================================================
// Tensor-core fused attention — term-major MMA ordering
// ============================================================
#define KSTR 80
#define OFF_QH 0
#define OFF_QL 10240
#define OFF_KV 20480
#define KVBUF 40960
#define OFF_RED (OFF_KV + 2 * KVBUF)
#define OFF_RN  (OFF_RED + 2048)
#define ATTN_SMEM (OFF_RN + 512)

__global__ void __launch_bounds__(512, 1)
attn_tc(const __nv_bfloat16* __restrict__ Qh, const __nv_bfloat16* __restrict__ Ql,
        const __nv_bfloat16* __restrict__ Kh, const __nv_bfloat16* __restrict__ Kl,
        const __nv_bfloat16* __restrict__ Vh, const __nv_bfloat16* __restrict__ Vl,
        float* __restrict__ part)
{
    extern __shared__ char smem[];
    unsigned sb = smem_u32(smem);
    float* red = (float*)(smem + OFF_RED);
    float* rn  = (float*)(smem + OFF_RN);

    int t = threadIdx.x, lane = t & 31, wid = t >> 5;
    int s = blockIdx.x, h = blockIdx.y, b = blockIdx.z;
    int gid = lane >> 2, tig = lane & 3;
    int lg = wid & 3, vg = wid >> 2;
    int wl = lg * 32, wv = vg * 32;

    {
        size_t qbase = (size_t)(b * LL) * DM + h * EE;
        int row = t >> 2, c = t & 3;
        size_t go = qbase + (size_t)row * DM + c * 8;
        unsigned d = sb + row * KSTR + c * 16;
        cp_async16(d + OFF_QH, Qh + go);
        cp_async16(d + OFF_QL, Ql + go);
    }
    CP_COMMIT();
    CP_WAIT(0);
    __syncthreads();

    unsigned qhf[2][2][4], qlf[2][2][4];
    {
        unsigned alof = (unsigned)((lane & 15) * KSTR + (lane >> 4) * 16);
#pragma unroll
        for (int mt = 0; mt < 2; mt++)
#pragma unroll
            for (int k = 0; k < 2; k++) {
                unsigned off = (wl + 16 * mt) * KSTR + alof + k * 32;
                ldsm_x4(qhf[mt][k], sb + OFF_QH + off);
                ldsm_x4(qlf[mt][k], sb + OFF_QL + off);
            }
    }

    float accO[2][4][4];
#pragma unroll
    for (int i = 0; i < 2; i++)
#pragma unroll
        for (int j = 0; j < 4; j++)
#pragma unroll
            for (int q = 0; q < 4; q++) accO[i][j][q] = 0.f;

    size_t hof = (size_t)h * EE;
    auto load_kv = [&](int buf, int v0) {
        unsigned base = sb + OFF_KV + buf * KVBUF;
        int row = t >> 2, c = t & 3;
        size_t go = (size_t)(v0 + row) * DM + hof + c * 8;
        unsigned d = base + row * KSTR + c * 16;
        cp_async16(d,         Kh + go);
        cp_async16(d + 10240, Kl + go);
        cp_async16(d + 20480, Vh + go);
        cp_async16(d + 30720, Vl + go);
    };

    load_kv(0, s * 128);
    CP_COMMIT();

    const float CC = 0.25503327723425473f;
    int l2 = lane & 15;
    unsigned kb_lof = (unsigned)((l2 & 7) * KSTR + (l2 >> 3) * 16);

    int it = 0;
    for (int tile = s; tile < NTILE; tile += SPLITS, it++) {
        CP_WAIT(0);
        __syncthreads();

        int nxt = tile + SPLITS;
        if (nxt < NTILE) {
            load_kv((it + 1) & 1, nxt * 128);
            CP_COMMIT();
        }
        unsigned kvb = sb + OFF_KV + (it & 1) * KVBUF;

        float accS[2][4][4];
#pragma unroll
        for (int mt = 0; mt < 2; mt++)
#pragma unroll
            for (int n = 0; n < 4; n++)
#pragma unroll
                for (int q = 0; q < 4; q++) accS[mt][n][q] = 0.f;

#pragma unroll
        for (int k = 0; k < 2; k++) {
            unsigned kbh[4][2], kbl[4][2];
#pragma unroll
            for (int n = 0; n < 4; n++) {
                unsigned addr = kvb + (wv + n * 8) * KSTR + kb_lof + k * 32;
                ldsm_x2(kbh[n], addr);
                ldsm_x2(kbl[n], addr + 10240);
            }
            // term-major: 8 independent MMAs between same-acc reuses
#pragma unroll
            for (int n = 0; n < 4; n++)
#pragma unroll
                for (int mt = 0; mt < 2; mt++) mma16816(accS[mt][n], qhf[mt][k], kbh[n]);
#pragma unroll
            for (int n = 0; n < 4; n++)
#pragma unroll
                for (int mt = 0; mt < 2; mt++) mma16816(accS[mt][n], qlf[mt][k], kbh[n]);
#pragma unroll
            for (int n = 0; n < 4; n++)
#pragma unroll
                for (int mt = 0; mt < 2; mt++) mma16816(accS[mt][n], qhf[mt][k], kbl[n]);
        }

        float s0[4], s1[4];
#pragma unroll
        for (int n = 0; n < 4; n++) { s0[n] = 0.f; s1[n] = 0.f; }
#pragma unroll
        for (int mt = 0; mt < 2; mt++)
#pragma unroll
            for (int n = 0; n < 4; n++) {
                accS[mt][n][0] = ex2(accS[mt][n][0] * CC);
                accS[mt][n][1] = ex2(accS[mt][n][1] * CC);
                accS[mt][n][2] = ex2(accS[mt][n][2] * CC);
                accS[mt][n][3] = ex2(accS[mt][n][3] * CC);
                s0[n] += accS[mt][n][0] + accS[mt][n][2];
                s1[n] += accS[mt][n][1] + accS[mt][n][3];
            }
#pragma unroll
        for (int n = 0; n < 4; n++) {
#pragma unroll
            for (int ofs = 4; ofs < 32; ofs <<= 1) {
                s0[n] += __shfl_xor_sync(0xffffffffu, s0[n], ofs);
                s1[n] += __shfl_xor_sync(0xffffffffu, s1[n], ofs);
            }
        }
        if (gid == 0) {
#pragma unroll
            for (int n = 0; n < 4; n++) {
                red[(wv + n * 8 + tig * 2) * 4 + lg] = s0[n];
                red[(wv + n * 8 + tig * 2 + 1) * 4 + lg] = s1[n];
            }
        }
        __syncthreads();
        if (t < 128) {
            float v = red[t * 4] + red[t * 4 + 1] + red[t * 4 + 2] + red[t * 4 + 3];
            rn[t] = 1.f / v;
        }
        __syncthreads();

#pragma unroll
        for (int n = 0; n < 4; n++) {
            float r0 = rn[wv + n * 8 + tig * 2];
            float r1 = rn[wv + n * 8 + tig * 2 + 1];
#pragma unroll
            for (int mt = 0; mt < 2; mt++) {
                accS[mt][n][0] *= r0;
                accS[mt][n][1] *= r1;
                accS[mt][n][2] *= r0;
                accS[mt][n][3] *= r1;
            }
        }

#pragma unroll
        for (int ks = 0; ks < 2; ks++) {
            unsigned vbh[4][2], vbl[4][2];
#pragma unroll
            for (int ne = 0; ne < 4; ne++) {
                unsigned addr = kvb + 20480 + (wv + ks * 16 + l2) * KSTR + ne * 16;
                ldsm_x2_t(vbh[ne], addr);
                ldsm_x2_t(vbl[ne], addr + 10240);
            }
            // build P fragments for both mt first
            unsigned aph[2][4], apl[2][4];
#pragma unroll
            for (int mt = 0; mt < 2; mt++) {
                float p0 = accS[mt][2 * ks][0], p1 = accS[mt][2 * ks][1];
                float p2 = accS[mt][2 * ks][2], p3 = accS[mt][2 * ks][3];
                float p4 = accS[mt][2 * ks + 1][0], p5 = accS[mt][2 * ks + 1][1];
                float p6 = accS[mt][2 * ks + 1][2], p7 = accS[mt][2 * ks + 1][3];
                aph[mt][0] = pack_bf16(p0, p1);
                aph[mt][1] = pack_bf16(p2, p3);
                aph[mt][2] = pack_bf16(p4, p5);
                aph[mt][3] = pack_bf16(p6, p7);
                apl[mt][0] = pack_bf16(p0 - __bfloat162float(__float2bfloat16(p0)),
                                       p1 - __bfloat162float(__float2bfloat16(p1)));
                apl[mt][1] = pack_bf16(p2 - __bfloat162float(__float2bfloat16(p2)),
                                       p3 - __bfloat162float(__float2bfloat16(p3)));
                apl[mt][2] = pack_bf16(p4 - __bfloat162float(__float2bfloat16(p4)),
                                       p5 - __bfloat162float(__float2bfloat16(p5)));
                apl[mt][3] = pack_bf16(p6 - __bfloat162float(__float2bfloat16(p6)),
                                       p7 - __bfloat162float(__float2bfloat16(p7)));
            }
            // term-major: 8 independent MMAs between same-acc reuses
#pragma unroll
            for (int ne = 0; ne < 4; ne++)
#pragma unroll
                for (int mt = 0; mt < 2; mt++) mma16816(accO[mt][ne], aph[mt], vbh[ne]);
#pragma unroll
            for (int ne = 0; ne < 4; ne++)
#pragma unroll
                for (int mt = 0; mt < 2; mt++) mma16816(accO[mt][ne], aph[mt], vbl[ne]);
#pragma unroll
            for (int ne = 0; ne < 4; ne++)
#pragma unroll
                for (int mt = 0; mt < 2; mt++) mma16816(accO[mt][ne], apl[mt], vbh[ne]);
        }
    }

    float* pout = part + (size_t)(((b * HH + h) * SPLITS + s) * 4 + vg) * LL * EE;
#pragma unroll
    for (int mt = 0; mt < 2; mt++) {
        int l = wl + mt * 16 + gid;
#pragma unroll
        for (int ne = 0; ne < 4; ne++) {
            int e = ne * 8 + tig * 2;
            *(float2*)(pout + l * EE + e) = make_float2(accO[mt][ne][0], accO[mt][ne][1]);
            *(float2*)(pout + (l + 8) * EE + e) = make_float2(accO[mt][ne][2], accO[mt][ne][3]);
        }
    }
}

__global__ void reduce_part(const float* __restrict__ part, float* __restrict__ reprog)
{
    int t = blockIdx.x * blockDim.x + threadIdx.x;
    if (t >= BB * LL * DM) return;
    int e = t & 31;
    int h = (t >> 5) & 7;
    int l = (t >> 8) & 127;
    int b = t >> 15;
    const float* p = part + (size_t)(b * HH + h) * SPL4 * LL * EE + l * EE + e;
    float acc = 0.f;
#pragma unroll
    for (int s2 = 0; s2 < SPL4; s2++) acc += p[(size_t)s2 * LL * EE];
    reprog[t] = acc;
}

// ============================================================
// Launch (kv_proj at index 3 for ncu)
// ============================================================
extern "C" void kernel_launch(void* const* d_in, const int* in_sizes, int n_in,
                              void* d_out, int out_size)
{
    (void)in_sizes; (void)n_in; (void)out_size;
    const float* ts = (const float*)d_in[0];
    const float* we = (const float*)d_in[1];
    const float* Wq = (const float*)d_in[2];
    const float* bq = (const float*)d_in[3];
    const float* Wk = (const float*)d_in[4];
    const float* bk = (const float*)d_in[5];
    const float* Wv = (const float*)d_in[6];
    const float* bv = (const float*)d_in[7];
    const float* Wo = (const float*)d_in[8];
    const float* bo = (const float*)d_in[9];
    float* out = (float*)d_out;

    float *gp, *gr, *gsg;
    __nv_bfloat16 *wkh, *wkl, *wvh, *wvl, *kh, *kl, *vh, *vl, *qh, *ql;
    cudaGetSymbolAddress((void**)&gp, g_part);
    cudaGetSymbolAddress((void**)&gr, g_reprog);
    cudaGetSymbolAddress((void**)&gsg, g_sg);
    cudaGetSymbolAddress((void**)&wkh, g_Wkh);
    cudaGetSymbolAddress((void**)&wkl, g_Wkl);
    cudaGetSymbolAddress((void**)&wvh, g_Wvh);
    cudaGetSymbolAddress((void**)&wvl, g_Wvl);
    cudaGetSymbolAddress((void**)&kh, g_Kh);
    cudaGetSymbolAddress((void**)&kl, g_Kl);
    cudaGetSymbolAddress((void**)&vh, g_Vh);
    cudaGetSymbolAddress((void**)&vl, g_Vl);
    cudaGetSymbolAddress((void**)&qh, g_Qh);
    cudaGetSymbolAddress((void**)&ql, g_Ql);

    cudaFuncSetAttribute(kv_proj, cudaFuncAttributeMaxDynamicSharedMemorySize, KP_SMEM);
    cudaFuncSetAttribute(attn_tc, cudaFuncAttributeMaxDynamicSharedMemorySize, ATTN_SMEM);

    dim3 wb(32, 8);
    conv_w2<<<dim3(DW / 32, DM / 32, 2), wb>>>(Wk, Wv, wkh, wkl, wvh, wvl);     // idx 0
    sgemm64s<<<dim3(BB * LL / 64, DM / 64, 4), 256>>>(ts, Wq, gsg, BB * LL, DM, DM); // idx 1
    combine_q<<<(BB * LL * DM + 255) / 256, 256>>>(gsg, bq, qh, ql);            // idx 2
    kv_proj<<<dim3(VPAD / MROWS, 2), 256, KP_SMEM>>>(we, wkh, wkl, wvh, wvl,
                                                     bk, bv, kh, kl, vh, vl);   // idx 3 (profiled)
    attn_tc<<<dim3(SPLITS, HH, BB), 512, ATTN_SMEM>>>(qh, ql, kh, kl, vh, vl, gp); // idx 4
    reduce_part<<<(BB * LL * DM + 255) / 256, 256>>>(gp, gr);                   // idx 5
    sgemm64s<<<dim3(BB * LL / 64, DM / 64, 4), 256>>>(gr, Wo, gsg, BB * LL, DM, DM); // idx 6
    combine_bias<<<(BB * LL * DM + 255) / 256, 256>>>(gsg, bo, out);            // idx 7
}

// round 11
// speedup vs baseline: 1.4160x; 1.2415x over previous
#include <cuda_runtime.h>
#include <cuda_bf16.h>
#include <cuda_fp16.h>

#define BB 4
#define LL 128
#define DM 256
#define VV 50257
#define VPAD 50304          /* 393 * 128 */
#define NTILE 393
#define DW 768
#define HH 8
#define EE 32
#define SPLITS 9
#define SPL4 (SPLITS * 4)

// ---- scratch ----
__device__ float g_part[BB * HH * SPL4 * LL * EE];
__device__ float g_reprog[BB * LL * DM];
__device__ float g_sg[4 * BB * LL * DM];
__device__ __half g_Wk16[(size_t)DM * DW];
__device__ __half g_Wv16[(size_t)DM * DW];
__device__ __nv_bfloat16 g_Kh[(size_t)VPAD * DM];
__device__ __nv_bfloat16 g_Kl[(size_t)VPAD * DM];
__device__ __nv_bfloat16 g_Vh[(size_t)VPAD * DM];
__device__ __nv_bfloat16 g_Vl[(size_t)VPAD * DM];
__device__ __nv_bfloat16 g_Qh[BB * LL * DM];
__device__ __nv_bfloat16 g_Ql[BB * LL * DM];

// ============================================================
// portable PTX helpers
// ============================================================
__device__ __forceinline__ unsigned smem_u32(const void* p) {
    unsigned a;
    asm("{ .reg .u64 t; cvta.to.shared.u64 t, %1; cvt.u32.u64 %0, t; }" : "=r"(a) : "l"(p));
    return a;
}
__device__ __forceinline__ void cp_async16(unsigned dst, const void* src) {
    asm volatile("cp.async.cg.shared.global [%0], [%1], 16;" :: "r"(dst), "l"(src));
}
#define CP_COMMIT() asm volatile("cp.async.commit_group;" ::: "memory")
#define CP_WAIT(n)  asm volatile("cp.async.wait_group %0;" :: "n"(n) : "memory")

__device__ __forceinline__ void ldsm_x4(unsigned* r, unsigned addr) {
    asm volatile("ldmatrix.sync.aligned.m8n8.x4.shared.b16 {%0,%1,%2,%3}, [%4];"
                 : "=r"(r[0]), "=r"(r[1]), "=r"(r[2]), "=r"(r[3]) : "r"(addr));
}
__device__ __forceinline__ void ldsm_x2(unsigned* r, unsigned addr) {
    asm volatile("ldmatrix.sync.aligned.m8n8.x2.shared.b16 {%0,%1}, [%2];"
                 : "=r"(r[0]), "=r"(r[1]) : "r"(addr));
}
__device__ __forceinline__ void ldsm_x2_t(unsigned* r, unsigned addr) {
    asm volatile("ldmatrix.sync.aligned.m8n8.x2.trans.shared.b16 {%0,%1}, [%2];"
                 : "=r"(r[0]), "=r"(r[1]) : "r"(addr));
}
__device__ __forceinline__ void mma16816(float* c, const unsigned* a, const unsigned* b) {
    asm volatile("mma.sync.aligned.m16n8k16.row.col.f32.bf16.bf16.f32 "
                 "{%0,%1,%2,%3}, {%4,%5,%6,%7}, {%8,%9}, {%0,%1,%2,%3};"
                 : "+f"(c[0]), "+f"(c[1]), "+f"(c[2]), "+f"(c[3])
                 : "r"(a[0]), "r"(a[1]), "r"(a[2]), "r"(a[3]), "r"(b[0]), "r"(b[1]));
}
__device__ __forceinline__ void mma16816h(float* c, const unsigned* a, const unsigned* b) {
    asm volatile("mma.sync.aligned.m16n8k16.row.col.f32.f16.f16.f32 "
                 "{%0,%1,%2,%3}, {%4,%5,%6,%7}, {%8,%9}, {%0,%1,%2,%3};"
                 : "+f"(c[0]), "+f"(c[1]), "+f"(c[2]), "+f"(c[3])
                 : "r"(a[0]), "r"(a[1]), "r"(a[2]), "r"(a[3]), "r"(b[0]), "r"(b[1]));
}
__device__ __forceinline__ float ex2(float x) {
    float r;
    asm("ex2.approx.ftz.f32 %0, %1;" : "=f"(r) : "f"(x));
    return r;
}
__device__ __forceinline__ unsigned pack_bf16(float a, float b) {
    __nv_bfloat162 t(__float2bfloat16(a), __float2bfloat16(b));
    return *(unsigned*)&t;
}
__device__ __forceinline__ unsigned pack_h16(float a, float b) {
    __half2 t(__float2half(a), __float2half(b));
    return *(unsigned*)&t;
}

// ============================================================
// weight conversion: fp32 -> single fp16, transposed [N][K], K and V
// ============================================================
__global__ void conv_w2(const float* __restrict__ Wk, const float* __restrict__ Wv,
                        __half* __restrict__ Wk16, __half* __restrict__ Wv16)
{
    __shared__ float tile[32][33];
    const float* W = blockIdx.z ? Wv : Wk;
    __half* Wo = blockIdx.z ? Wv16 : Wk16;
    int k0 = blockIdx.x * 32, n0 = blockIdx.y * 32;
    int tx = threadIdx.x, ty = threadIdx.y;
    for (int r = ty; r < 32; r += 8)
        tile[r][tx] = W[(size_t)(k0 + r) * DM + n0 + tx];
    __syncthreads();
    for (int r = ty; r < 32; r += 8)
        Wo[(size_t)(n0 + r) * DW + k0 + tx] = __float2half(tile[tx][r]);
}

// ============================================================
// KV projection GEMM — fp16 2-term split:
//   A' = 1024*A = Ah + Al (both fp16, exact to ~2^-22)
//   acc = Ah*Wh + Al*Wh  (Wh = fp16(W));  out = acc/1024 + bias
// CTA: 256 thr (8 warps), 64M x 256N, warp 32x64, 2 CTAs/SM.
// ============================================================
#define MROWS 64
#define KBK 32
#define SAH 0                        /* A hi: 64*80 = 5120 */
#define SAL 5120
#define SWH 10240                    /* W: 256*80 = 20480 */
#define KP_STG 30720
#define KP_SMEM (2 * KP_STG)         /* 61440 */
#define KV_NCH (DW / KBK)            /* 24 */
#define ASCALE 1024.0f
#define RSCALE 0.0009765625f

__global__ void __launch_bounds__(256, 2)
kv_proj(const float* __restrict__ we,
        const __half* __restrict__ Wk16, const __half* __restrict__ Wv16,
        const float* __restrict__ bk, const float* __restrict__ bv,
        __nv_bfloat16* __restrict__ Kh, __nv_bfloat16* __restrict__ Kl,
        __nv_bfloat16* __restrict__ Vh, __nv_bfloat16* __restrict__ Vl)
{
    extern __shared__ char smem[];
    unsigned sb = smem_u32(smem);
    int t = threadIdx.x, lane = t & 31, wid = t >> 5;
    int mBase = blockIdx.x * MROWS;
    int sel = blockIdx.y;
    const __half* Wh = sel ? Wv16 : Wk16;
    const float* bias = sel ? bv : bk;
    __nv_bfloat16* oH = sel ? Vh : Kh;
    __nv_bfloat16* oL = sel ? Vl : Kl;

    int wm = (wid & 1) * 32;
    int wn = (wid >> 1) * 64;

    float acc[2][8][4];
#pragma unroll
    for (int i = 0; i < 2; i++)
#pragma unroll
        for (int j = 0; j < 8; j++)
#pragma unroll
            for (int q = 0; q < 4; q++) acc[i][j][q] = 0.f;

    unsigned a_lof = (unsigned)((lane & 15) * 80 + (lane >> 4) * 16);
    int l2 = lane & 15;
    unsigned w_lof = (unsigned)((l2 & 7) * 80 + (l2 >> 3) * 16);

    int ar0 = t >> 3, ac0 = t & 7;
    int ar1 = ar0 + 32;
    bool av0 = (mBase + ar0) < VV;
    bool av1 = (mBase + ar1) < VV;
    const float* ab0 = we + (size_t)(mBase + ar0) * DW + ac0 * 4;
    const float* ab1 = we + (size_t)(mBase + ar1) * DW + ac0 * 4;

    float4 aCur0, aCur1;
    auto ldA = [&](int c) {
        aCur0 = av0 ? *(const float4*)(ab0 + c * KBK) : make_float4(0.f, 0.f, 0.f, 0.f);
        aCur1 = av1 ? *(const float4*)(ab1 + c * KBK) : make_float4(0.f, 0.f, 0.f, 0.f);
    };
    auto convSTS = [&](int s) {
        {
            float x0 = aCur0.x * ASCALE, x1 = aCur0.y * ASCALE;
            float x2 = aCur0.z * ASCALE, x3 = aCur0.w * ASCALE;
            float r0 = x0 - __half2float(__float2half(x0));
            float r1 = x1 - __half2float(__float2half(x1));
            float r2 = x2 - __half2float(__float2half(x2));
            float r3 = x3 - __half2float(__float2half(x3));
            *(uint2*)(smem + s * KP_STG + SAH + ar0 * 80 + ac0 * 8) =
                make_uint2(pack_h16(x0, x1), pack_h16(x2, x3));
            *(uint2*)(smem + s * KP_STG + SAL + ar0 * 80 + ac0 * 8) =
                make_uint2(pack_h16(r0, r1), pack_h16(r2, r3));
        }
        {
            float x0 = aCur1.x * ASCALE, x1 = aCur1.y * ASCALE;
            float x2 = aCur1.z * ASCALE, x3 = aCur1.w * ASCALE;
            float r0 = x0 - __half2float(__float2half(x0));
            float r1 = x1 - __half2float(__float2half(x1));
            float r2 = x2 - __half2float(__float2half(x2));
            float r3 = x3 - __half2float(__float2half(x3));
            *(uint2*)(smem + s * KP_STG + SAH + ar1 * 80 + ac0 * 8) =
                make_uint2(pack_h16(x0, x1), pack_h16(x2, x3));
            *(uint2*)(smem + s * KP_STG + SAL + ar1 * 80 + ac0 * 8) =
                make_uint2(pack_h16(r0, r1), pack_h16(r2, r3));
        }
    };
    auto loadW = [&](int s, int k0) {
        unsigned stg = sb + s * KP_STG;
#pragma unroll
        for (int i = t; i < 1024; i += 256) {
            int row = i >> 2, c = i & 3;
            cp_async16(stg + SWH + row * 80 + c * 16,
                       Wh + (size_t)row * DW + k0 + c * 8);
        }
    };

    ldA(0);
    convSTS(0);
    loadW(0, 0);
    CP_COMMIT();
    ldA(1);
    convSTS(1);
    loadW(1, KBK);
    CP_COMMIT();
    CP_WAIT(1);
    __syncthreads();

    for (int c = 0; c < KV_NCH; c++) {
        int s = c & 1;
        if (c > 0) {
            CP_WAIT(0);
            __syncthreads();
        }
        if (c >= 1 && c + 1 < KV_NCH) {
            convSTS(1 - s);
            loadW(1 - s, (c + 1) * KBK);
            CP_COMMIT();
        }
        if (c + 2 < KV_NCH) ldA(c + 2);

        unsigned stg = sb + s * KP_STG;
        unsigned aHb = stg + SAH + wm * 80 + a_lof;
        unsigned aLb = stg + SAL + wm * 80 + a_lof;
        unsigned wHb = stg + SWH + wn * 80 + w_lof;

#pragma unroll
        for (int ks = 0; ks < 2; ks++) {
            unsigned kb = ks * 32;
            unsigned ah[2][4], al2[2][4], bh[8][2];
#pragma unroll
            for (int mt = 0; mt < 2; mt++) {
                ldsm_x4(ah[mt],  aHb + mt * (16 * 80) + kb);
                ldsm_x4(al2[mt], aLb + mt * (16 * 80) + kb);
            }
#pragma unroll
            for (int nt = 0; nt < 8; nt++)
                ldsm_x2(bh[nt], wHb + nt * (8 * 80) + kb);
            // term-major: 16 independent MMAs between same-acc reuses
#pragma unroll
            for (int nt = 0; nt < 8; nt++)
#pragma unroll
                for (int mt = 0; mt < 2; mt++) mma16816h(acc[mt][nt], ah[mt], bh[nt]);
#pragma unroll
            for (int nt = 0; nt < 8; nt++)
#pragma unroll
                for (int mt = 0; mt < 2; mt++) mma16816h(acc[mt][nt], al2[mt], bh[nt]);
        }
    }

    int gid = lane >> 2, tig = lane & 3;
#pragma unroll
    for (int nt = 0; nt < 8; nt++) {
        int col = wn + nt * 8 + tig * 2;
        float2 bv2 = *(const float2*)(bias + col);
#pragma unroll
        for (int mt = 0; mt < 2; mt++) {
            int r0 = mBase + wm + mt * 16 + gid;
            int r1 = r0 + 8;
            float x0 = (r0 < VV) ? acc[mt][nt][0] * RSCALE + bv2.x : 0.f;
            float x1 = (r0 < VV) ? acc[mt][nt][1] * RSCALE + bv2.y : 0.f;
            float x2 = (r1 < VV) ? acc[mt][nt][2] * RSCALE + bv2.x : 0.f;
            float x3 = (r1 < VV) ? acc[mt][nt][3] * RSCALE + bv2.y : 0.f;
            *(unsigned*)(oH + (size_t)r0 * DM + col) = pack_bf16(x0, x1);
            *(unsigned*)(oL + (size_t)r0 * DM + col) =
                pack_bf16(x0 - __bfloat162float(__float2bfloat16(x0)),
                          x1 - __bfloat162float(__float2bfloat16(x1)));
            *(unsigned*)(oH + (size_t)r1 * DM + col) = pack_bf16(x2, x3);
            *(unsigned*)(oL + (size_t)r1 * DM + col) =
                pack_bf16(x2 - __bfloat162float(__float2bfloat16(x2)),
                          x3 - __bfloat162float(__float2bfloat16(x3)));
        }
    }
}

// ============================================================
// split-K fp32 SGEMM (Q / O projections)
// ============================================================
__global__ __launch_bounds__(256) void sgemm64s(
    const float* __restrict__ A, const float* __restrict__ Bw,
    float* __restrict__ Cp, int M, int N, int K)
{
    __shared__ float As[16][68];
    __shared__ float Bs[16][68];
    int t = threadIdx.x, tx = t & 15, ty = t >> 4;
    int mB = blockIdx.x * 64, nB = blockIdx.y * 64;
    int kc = K / 4;
    int kBeg = blockIdx.z * kc, kEnd = kBeg + kc;
    float acc[4][4];
#pragma unroll
    for (int i = 0; i < 4; i++)
#pragma unroll
        for (int j = 0; j < 4; j++) acc[i][j] = 0.f;

    for (int k0 = kBeg; k0 < kEnd; k0 += 16) {
        {
            int row = t >> 2, kk = (t & 3) * 4;
            float4 av = *(const float4*)(A + (size_t)(mB + row) * K + k0 + kk);
            As[kk + 0][row] = av.x; As[kk + 1][row] = av.y;
            As[kk + 2][row] = av.z; As[kk + 3][row] = av.w;
        }
        {
            int kr = t >> 4, c4 = (t & 15) * 4;
            *(float4*)&Bs[kr][c4] = *(const float4*)(Bw + (size_t)(k0 + kr) * N + nB + c4);
        }
        __syncthreads();
#pragma unroll
        for (int kk = 0; kk < 16; kk++) {
            float4 a = *(const float4*)&As[kk][ty * 4];
            float4 b = *(const float4*)&Bs[kk][tx * 4];
            float am[4] = {a.x, a.y, a.z, a.w};
            float bn[4] = {b.x, b.y, b.z, b.w};
#pragma unroll
            for (int i = 0; i < 4; i++)
#pragma unroll
                for (int j = 0; j < 4; j++) acc[i][j] += am[i] * bn[j];
        }
        __syncthreads();
    }
    float* outz = Cp + (size_t)blockIdx.z * M * N;
#pragma unroll
    for (int i = 0; i < 4; i++) {
        int m = mB + ty * 4 + i;
#pragma unroll
        for (int j = 0; j < 4; j++) {
            int n = nB + tx * 4 + j;
            outz[(size_t)m * N + n] = acc[i][j];
        }
    }
}

__global__ void combine_bias(const float* __restrict__ Cp, const float* __restrict__ bias,
                             float* __restrict__ out)
{
    int i = blockIdx.x * blockDim.x + threadIdx.x;
    const int MN = BB * LL * DM;
    if (i >= MN) return;
    out[i] = Cp[i] + Cp[MN + i] + Cp[2 * MN + i] + Cp[3 * MN + i] + bias[i & (DM - 1)];
}

__global__ void combine_q(const float* __restrict__ Cp, const float* __restrict__ bias,
                          __nv_bfloat16* __restrict__ Qh, __nv_bfloat16* __restrict__ Ql)
{
    int i = blockIdx.x * blockDim.x + threadIdx.x;
    const int MN = BB * LL * DM;
    if (i >= MN) return;
    float v = Cp[i] + Cp[MN + i] + Cp[2 * MN + i] + Cp[3 * MN + i] + bias[i & (DM - 1)];
    __nv_bfloat16 h = __float2bfloat16(v);
    Qh[i] = h;
    Ql[i] = __float2bfloat16(v - __bfloat162float(h));
}

// ============================================================
// Tensor-core fused attention — term-major MMA ordering
// ============================================================
#define KSTR 80
#define OFF_QH 0
#define OFF_QL 10240
#define OFF_KV 20480
#define KVBUF 40960
#define OFF_RED (OFF_KV + 2 * KVBUF)
#define OFF_RN  (OFF_RED + 2048)
#define ATTN_SMEM (OFF_RN + 512)

__global__ void __launch_bounds__(512, 1)
attn_tc(const __nv_bfloat16* __restrict__ Qh, const __nv_bfloat16* __restrict__ Ql,
        const __nv_bfloat16* __restrict__ Kh, const __nv_bfloat16* __restrict__ Kl,
        const __nv_bfloat16* __restrict__ Vh, const __nv_bfloat16* __restrict__ Vl,
        float* __restrict__ part)
{
    extern __shared__ char smem[];
    unsigned sb = smem_u32(smem);
    float* red = (float*)(smem + OFF_RED);
    float* rn  = (float*)(smem + OFF_RN);

    int t = threadIdx.x, lane = t & 31, wid = t >> 5;
    int s = blockIdx.x, h = blockIdx.y, b = blockIdx.z;
    int gid = lane >> 2, tig = lane & 3;
    int lg = wid & 3, vg = wid >> 2;
    int wl = lg * 32, wv = vg * 32;

    {
        size_t qbase = (size_t)(b * LL) * DM + h * EE;
        int row = t >> 2, c = t & 3;
        size_t go = qbase + (size_t)row * DM + c * 8;
        unsigned d = sb + row * KSTR + c * 16;
        cp_async16(d + OFF_QH, Qh + go);
        cp_async16(d + OFF_QL, Ql + go);
    }
    CP_COMMIT();
    CP_WAIT(0);
    __syncthreads();

    unsigned qhf[2][2][4], qlf[2][2][4];
    {
        unsigned alof = (unsigned)((lane & 15) * KSTR + (lane >> 4) * 16);
#pragma unroll
        for (int mt = 0; mt < 2; mt++)
#pragma unroll
            for (int k = 0; k < 2; k++) {
                unsigned off = (wl + 16 * mt) * KSTR + alof + k * 32;
                ldsm_x4(qhf[mt][k], sb + OFF_QH + off);
                ldsm_x4(qlf[mt][k], sb + OFF_QL + off);
            }
    }

    float accO[2][4][4];
#pragma unroll
    for (int i = 0; i < 2; i++)
#pragma unroll
        for (int j = 0; j < 4; j++)
#pragma unroll
            for (int q = 0; q < 4; q++) accO[i][j][q] = 0.f;

    size_t hof = (size_t)h * EE;
    auto load_kv = [&](int buf, int v0) {
        unsigned base = sb + OFF_KV + buf * KVBUF;
        int row = t >> 2, c = t & 3;
        size_t go = (size_t)(v0 + row) * DM + hof + c * 8;
        unsigned d = base + row * KSTR + c * 16;
        cp_async16(d,         Kh + go);
        cp_async16(d + 10240, Kl + go);
        cp_async16(d + 20480, Vh + go);
        cp_async16(d + 30720, Vl + go);
    };

    load_kv(0, s * 128);
    CP_COMMIT();

    const float CC = 0.25503327723425473f;
    int l2 = lane & 15;
    unsigned kb_lof = (unsigned)((l2 & 7) * KSTR + (l2 >> 3) * 16);

    int it = 0;
    for (int tile = s; tile < NTILE; tile += SPLITS, it++) {
        CP_WAIT(0);
        __syncthreads();

        int nxt = tile + SPLITS;
        if (nxt < NTILE) {
            load_kv((it + 1) & 1, nxt * 128);
            CP_COMMIT();
        }
        unsigned kvb = sb + OFF_KV + (it & 1) * KVBUF;

        float accS[2][4][4];
#pragma unroll
        for (int mt = 0; mt < 2; mt++)
#pragma unroll
            for (int n = 0; n < 4; n++)
#pragma unroll
                for (int q = 0; q < 4; q++) accS[mt][n][q] = 0.f;

#pragma unroll
        for (int k = 0; k < 2; k++) {
            unsigned kbh[4][2], kbl[4][2];
#pragma unroll
            for (int n = 0; n < 4; n++) {
                unsigned addr = kvb + (wv + n * 8) * KSTR + kb_lof + k * 32;
                ldsm_x2(kbh[n], addr);
                ldsm_x2(kbl[n], addr + 10240);
            }
#pragma unroll
            for (int n = 0; n < 4; n++)
#pragma unroll
                for (int mt = 0; mt < 2; mt++) mma16816(accS[mt][n], qhf[mt][k], kbh[n]);
#pragma unroll
            for (int n = 0; n < 4; n++)
#pragma unroll
                for (int mt = 0; mt < 2; mt++) mma16816(accS[mt][n], qlf[mt][k], kbh[n]);
#pragma unroll
            for (int n = 0; n < 4; n++)
#pragma unroll
                for (int mt = 0; mt < 2; mt++) mma16816(accS[mt][n], qhf[mt][k], kbl[n]);
        }

        float s0[4], s1[4];
#pragma unroll
        for (int n = 0; n < 4; n++) { s0[n] = 0.f; s1[n] = 0.f; }
#pragma unroll
        for (int mt = 0; mt < 2; mt++)
#pragma unroll
            for (int n = 0; n < 4; n++) {
                accS[mt][n][0] = ex2(accS[mt][n][0] * CC);
                accS[mt][n][1] = ex2(accS[mt][n][1] * CC);
                accS[mt][n][2] = ex2(accS[mt][n][2] * CC);
                accS[mt][n][3] = ex2(accS[mt][n][3] * CC);
                s0[n] += accS[mt][n][0] + accS[mt][n][2];
                s1[n] += accS[mt][n][1] + accS[mt][n][3];
            }
#pragma unroll
        for (int n = 0; n < 4; n++) {
#pragma unroll
            for (int ofs = 4; ofs < 32; ofs <<= 1) {
                s0[n] += __shfl_xor_sync(0xffffffffu, s0[n], ofs);
                s1[n] += __shfl_xor_sync(0xffffffffu, s1[n], ofs);
            }
        }
        if (gid == 0) {
#pragma unroll
            for (int n = 0; n < 4; n++) {
                red[(wv + n * 8 + tig * 2) * 4 + lg] = s0[n];
                red[(wv + n * 8 + tig * 2 + 1) * 4 + lg] = s1[n];
            }
        }
        __syncthreads();
        if (t < 128) {
            float v = red[t * 4] + red[t * 4 + 1] + red[t * 4 + 2] + red[t * 4 + 3];
            rn[t] = 1.f / v;
        }
        __syncthreads();

#pragma unroll
        for (int n = 0; n < 4; n++) {
            float r0 = rn[wv + n * 8 + tig * 2];
            float r1 = rn[wv + n * 8 + tig * 2 + 1];
#pragma unroll
            for (int mt = 0; mt < 2; mt++) {
                accS[mt][n][0] *= r0;
                accS[mt][n][1] *= r1;
                accS[mt][n][2] *= r0;
                accS[mt][n][3] *= r1;
            }
        }

#pragma unroll
        for (int ks = 0; ks < 2; ks++) {
            unsigned vbh[4][2], vbl[4][2];
#pragma unroll
            for (int ne = 0; ne < 4; ne++) {
                unsigned addr = kvb + 20480 + (wv + ks * 16 + l2) * KSTR + ne * 16;
                ldsm_x2_t(vbh[ne], addr);
                ldsm_x2_t(vbl[ne], addr + 10240);
            }
            unsigned aph[2][4], apl[2][4];
#pragma unroll
            for (int mt = 0; mt < 2; mt++) {
                float p0 = accS[mt][2 * ks][0], p1 = accS[mt][2 * ks][1];
                float p2 = accS[mt][2 * ks][2], p3 = accS[mt][2 * ks][3];
                float p4 = accS[mt][2 * ks + 1][0], p5 = accS[mt][2 * ks + 1][1];
                float p6 = accS[mt][2 * ks + 1][2], p7 = accS[mt][2 * ks + 1][3];
                aph[mt][0] = pack_bf16(p0, p1);
                aph[mt][1] = pack_bf16(p2, p3);
                aph[mt][2] = pack_bf16(p4, p5);
                aph[mt][3] = pack_bf16(p6, p7);
                apl[mt][0] = pack_bf16(p0 - __bfloat162float(__float2bfloat16(p0)),
                                       p1 - __bfloat162float(__float2bfloat16(p1)));
                apl[mt][1] = pack_bf16(p2 - __bfloat162float(__float2bfloat16(p2)),
                                       p3 - __bfloat162float(__float2bfloat16(p3)));
                apl[mt][2] = pack_bf16(p4 - __bfloat162float(__float2bfloat16(p4)),
                                       p5 - __bfloat162float(__float2bfloat16(p5)));
                apl[mt][3] = pack_bf16(p6 - __bfloat162float(__float2bfloat16(p6)),
                                       p7 - __bfloat162float(__float2bfloat16(p7)));
            }
#pragma unroll
            for (int ne = 0; ne < 4; ne++)
#pragma unroll
                for (int mt = 0; mt < 2; mt++) mma16816(accO[mt][ne], aph[mt], vbh[ne]);
#pragma unroll
            for (int ne = 0; ne < 4; ne++)
#pragma unroll
                for (int mt = 0; mt < 2; mt++) mma16816(accO[mt][ne], aph[mt], vbl[ne]);
#pragma unroll
            for (int ne = 0; ne < 4; ne++)
#pragma unroll
                for (int mt = 0; mt < 2; mt++) mma16816(accO[mt][ne], apl[mt], vbh[ne]);
        }
    }

    float* pout = part + (size_t)(((b * HH + h) * SPLITS + s) * 4 + vg) * LL * EE;
#pragma unroll
    for (int mt = 0; mt < 2; mt++) {
        int l = wl + mt * 16 + gid;
#pragma unroll
        for (int ne = 0; ne < 4; ne++) {
            int e = ne * 8 + tig * 2;
            *(float2*)(pout + l * EE + e) = make_float2(accO[mt][ne][0], accO[mt][ne][1]);
            *(float2*)(pout + (l + 8) * EE + e) = make_float2(accO[mt][ne][2], accO[mt][ne][3]);
        }
    }
}

__global__ void reduce_part(const float* __restrict__ part, float* __restrict__ reprog)
{
    int t = blockIdx.x * blockDim.x + threadIdx.x;
    if (t >= BB * LL * DM) return;
    int e = t & 31;
    int h = (t >> 5) & 7;
    int l = (t >> 8) & 127;
    int b = t >> 15;
    const float* p = part + (size_t)(b * HH + h) * SPL4 * LL * EE + l * EE + e;
    float acc = 0.f;
#pragma unroll
    for (int s2 = 0; s2 < SPL4; s2++) acc += p[(size_t)s2 * LL * EE];
    reprog[t] = acc;
}

// ============================================================
// Launch (kv_proj at index 3 for ncu)
// ============================================================
extern "C" void kernel_launch(void* const* d_in, const int* in_sizes, int n_in,
                              void* d_out, int out_size)
{
    (void)in_sizes; (void)n_in; (void)out_size;
    const float* ts = (const float*)d_in[0];
    const float* we = (const float*)d_in[1];
    const float* Wq = (const float*)d_in[2];
    const float* bq = (const float*)d_in[3];
    const float* Wk = (const float*)d_in[4];
    const float* bk = (const float*)d_in[5];
    const float* Wv = (const float*)d_in[6];
    const float* bv = (const float*)d_in[7];
    const float* Wo = (const float*)d_in[8];
    const float* bo = (const float*)d_in[9];
    float* out = (float*)d_out;

    float *gp, *gr, *gsg;
    __half *wk16, *wv16;
    __nv_bfloat16 *kh, *kl, *vh, *vl, *qh, *ql;
    cudaGetSymbolAddress((void**)&gp, g_part);
    cudaGetSymbolAddress((void**)&gr, g_reprog);
    cudaGetSymbolAddress((void**)&gsg, g_sg);
    cudaGetSymbolAddress((void**)&wk16, g_Wk16);
    cudaGetSymbolAddress((void**)&wv16, g_Wv16);
    cudaGetSymbolAddress((void**)&kh, g_Kh);
    cudaGetSymbolAddress((void**)&kl, g_Kl);
    cudaGetSymbolAddress((void**)&vh, g_Vh);
    cudaGetSymbolAddress((void**)&vl, g_Vl);
    cudaGetSymbolAddress((void**)&qh, g_Qh);
    cudaGetSymbolAddress((void**)&ql, g_Ql);

    cudaFuncSetAttribute(kv_proj, cudaFuncAttributeMaxDynamicSharedMemorySize, KP_SMEM);
    cudaFuncSetAttribute(attn_tc, cudaFuncAttributeMaxDynamicSharedMemorySize, ATTN_SMEM);

    dim3 wb(32, 8);
    conv_w2<<<dim3(DW / 32, DM / 32, 2), wb>>>(Wk, Wv, wk16, wv16);             // idx 0
    sgemm64s<<<dim3(BB * LL / 64, DM / 64, 4), 256>>>(ts, Wq, gsg, BB * LL, DM, DM); // idx 1
    combine_q<<<(BB * LL * DM + 255) / 256, 256>>>(gsg, bq, qh, ql);            // idx 2
    kv_proj<<<dim3(VPAD / MROWS, 2), 256, KP_SMEM>>>(we, wk16, wv16,
                                                     bk, bv, kh, kl, vh, vl);   // idx 3 (profiled)
    attn_tc<<<dim3(SPLITS, HH, BB), 512, ATTN_SMEM>>>(qh, ql, kh, kl, vh, vl, gp); // idx 4
    reduce_part<<<(BB * LL * DM + 255) / 256, 256>>>(gp, gr);                   // idx 5
    sgemm64s<<<dim3(BB * LL / 64, DM / 64, 4), 256>>>(gr, Wo, gsg, BB * LL, DM, DM); // idx 6
    combine_bias<<<(BB * LL * DM + 255) / 256, 256>>>(gsg, bo, out);            // idx 7
}

// round 12
// speedup vs baseline: 1.7233x; 1.2170x over previous
#include <cuda_runtime.h>
#include <cuda_bf16.h>
#include <cuda_fp16.h>

#define BB 4
#define LL 128
#define DM 256
#define VV 50257
#define VPAD 50304          /* 393 * 128 */
#define NTILE 393
#define DW 768
#define HH 8
#define EE 32
#define SPLITS 9
#define SPL4 (SPLITS * 4)

// ---- scratch ----
__device__ float g_part[BB * HH * SPL4 * LL * EE];
__device__ float g_reprog[BB * LL * DM];
__device__ float g_sg[4 * BB * LL * DM];
__device__ __half g_Wk16[(size_t)DM * DW];
__device__ __half g_Wv16[(size_t)DM * DW];
__device__ __half g_K16[(size_t)VPAD * DM];
__device__ __half g_V16[(size_t)VPAD * DM];
__device__ __half g_Qh16[BB * LL * DM];
__device__ __half g_Ql16[BB * LL * DM];

// ============================================================
// portable PTX helpers
// ============================================================
__device__ __forceinline__ unsigned smem_u32(const void* p) {
    unsigned a;
    asm("{ .reg .u64 t; cvta.to.shared.u64 t, %1; cvt.u32.u64 %0, t; }" : "=r"(a) : "l"(p));
    return a;
}
__device__ __forceinline__ void cp_async16(unsigned dst, const void* src) {
    asm volatile("cp.async.cg.shared.global [%0], [%1], 16;" :: "r"(dst), "l"(src));
}
#define CP_COMMIT() asm volatile("cp.async.commit_group;" ::: "memory")
#define CP_WAIT(n)  asm volatile("cp.async.wait_group %0;" :: "n"(n) : "memory")

__device__ __forceinline__ void ldsm_x4(unsigned* r, unsigned addr) {
    asm volatile("ldmatrix.sync.aligned.m8n8.x4.shared.b16 {%0,%1,%2,%3}, [%4];"
                 : "=r"(r[0]), "=r"(r[1]), "=r"(r[2]), "=r"(r[3]) : "r"(addr));
}
__device__ __forceinline__ void ldsm_x2(unsigned* r, unsigned addr) {
    asm volatile("ldmatrix.sync.aligned.m8n8.x2.shared.b16 {%0,%1}, [%2];"
                 : "=r"(r[0]), "=r"(r[1]) : "r"(addr));
}
__device__ __forceinline__ void ldsm_x2_t(unsigned* r, unsigned addr) {
    asm volatile("ldmatrix.sync.aligned.m8n8.x2.trans.shared.b16 {%0,%1}, [%2];"
                 : "=r"(r[0]), "=r"(r[1]) : "r"(addr));
}
__device__ __forceinline__ void mma16816h(float* c, const unsigned* a, const unsigned* b) {
    asm volatile("mma.sync.aligned.m16n8k16.row.col.f32.f16.f16.f32 "
                 "{%0,%1,%2,%3}, {%4,%5,%6,%7}, {%8,%9}, {%0,%1,%2,%3};"
                 : "+f"(c[0]), "+f"(c[1]), "+f"(c[2]), "+f"(c[3])
                 : "r"(a[0]), "r"(a[1]), "r"(a[2]), "r"(a[3]), "r"(b[0]), "r"(b[1]));
}
__device__ __forceinline__ float ex2(float x) {
    float r;
    asm("ex2.approx.ftz.f32 %0, %1;" : "=f"(r) : "f"(x));
    return r;
}
__device__ __forceinline__ unsigned pack_h16(float a, float b) {
    __half2 t(__float2half(a), __float2half(b));
    return *(unsigned*)&t;
}

// ============================================================
// weight conversion: fp32 -> single fp16, transposed [N][K], K and V
// ============================================================
__global__ void conv_w2(const float* __restrict__ Wk, const float* __restrict__ Wv,
                        __half* __restrict__ Wk16, __half* __restrict__ Wv16)
{
    __shared__ float tile[32][33];
    const float* W = blockIdx.z ? Wv : Wk;
    __half* Wo = blockIdx.z ? Wv16 : Wk16;
    int k0 = blockIdx.x * 32, n0 = blockIdx.y * 32;
    int tx = threadIdx.x, ty = threadIdx.y;
    for (int r = ty; r < 32; r += 8)
        tile[r][tx] = W[(size_t)(k0 + r) * DM + n0 + tx];
    __syncthreads();
    for (int r = ty; r < 32; r += 8)
        Wo[(size_t)(n0 + r) * DW + k0 + tx] = __float2half(tile[tx][r]);
}

// ============================================================
// KV projection GEMM — fp16 2-term split on A; output single fp16
// ============================================================
#define MROWS 64
#define KBK 32
#define SAH 0
#define SAL 5120
#define SWH 10240
#define KP_STG 30720
#define KP_SMEM (2 * KP_STG)
#define KV_NCH (DW / KBK)
#define ASCALE 1024.0f
#define RSCALE 0.0009765625f

__global__ void __launch_bounds__(256, 2)
kv_proj(const float* __restrict__ we,
        const __half* __restrict__ Wk16, const __half* __restrict__ Wv16,
        const float* __restrict__ bk, const float* __restrict__ bv,
        __half* __restrict__ K16, __half* __restrict__ V16)
{
    extern __shared__ char smem[];
    unsigned sb = smem_u32(smem);
    int t = threadIdx.x, lane = t & 31, wid = t >> 5;
    int mBase = blockIdx.x * MROWS;
    int sel = blockIdx.y;
    const __half* Wh = sel ? Wv16 : Wk16;
    const float* bias = sel ? bv : bk;
    __half* o16 = sel ? V16 : K16;

    int wm = (wid & 1) * 32;
    int wn = (wid >> 1) * 64;

    float acc[2][8][4];
#pragma unroll
    for (int i = 0; i < 2; i++)
#pragma unroll
        for (int j = 0; j < 8; j++)
#pragma unroll
            for (int q = 0; q < 4; q++) acc[i][j][q] = 0.f;

    unsigned a_lof = (unsigned)((lane & 15) * 80 + (lane >> 4) * 16);
    int l2 = lane & 15;
    unsigned w_lof = (unsigned)((l2 & 7) * 80 + (l2 >> 3) * 16);

    int ar0 = t >> 3, ac0 = t & 7;
    int ar1 = ar0 + 32;
    bool av0 = (mBase + ar0) < VV;
    bool av1 = (mBase + ar1) < VV;
    const float* ab0 = we + (size_t)(mBase + ar0) * DW + ac0 * 4;
    const float* ab1 = we + (size_t)(mBase + ar1) * DW + ac0 * 4;

    float4 aCur0, aCur1;
    auto ldA = [&](int c) {
        aCur0 = av0 ? *(const float4*)(ab0 + c * KBK) : make_float4(0.f, 0.f, 0.f, 0.f);
        aCur1 = av1 ? *(const float4*)(ab1 + c * KBK) : make_float4(0.f, 0.f, 0.f, 0.f);
    };
    auto convSTS = [&](int s) {
        {
            float x0 = aCur0.x * ASCALE, x1 = aCur0.y * ASCALE;
            float x2 = aCur0.z * ASCALE, x3 = aCur0.w * ASCALE;
            float r0 = x0 - __half2float(__float2half(x0));
            float r1 = x1 - __half2float(__float2half(x1));
            float r2 = x2 - __half2float(__float2half(x2));
            float r3 = x3 - __half2float(__float2half(x3));
            *(uint2*)(smem + s * KP_STG + SAH + ar0 * 80 + ac0 * 8) =
                make_uint2(pack_h16(x0, x1), pack_h16(x2, x3));
            *(uint2*)(smem + s * KP_STG + SAL + ar0 * 80 + ac0 * 8) =
                make_uint2(pack_h16(r0, r1), pack_h16(r2, r3));
        }
        {
            float x0 = aCur1.x * ASCALE, x1 = aCur1.y * ASCALE;
            float x2 = aCur1.z * ASCALE, x3 = aCur1.w * ASCALE;
            float r0 = x0 - __half2float(__float2half(x0));
            float r1 = x1 - __half2float(__float2half(x1));
            float r2 = x2 - __half2float(__float2half(x2));
            float r3 = x3 - __half2float(__float2half(x3));
            *(uint2*)(smem + s * KP_STG + SAH + ar1 * 80 + ac0 * 8) =
                make_uint2(pack_h16(x0, x1), pack_h16(x2, x3));
            *(uint2*)(smem + s * KP_STG + SAL + ar1 * 80 + ac0 * 8) =
                make_uint2(pack_h16(r0, r1), pack_h16(r2, r3));
        }
    };
    auto loadW = [&](int s, int k0) {
        unsigned stg = sb + s * KP_STG;
#pragma unroll
        for (int i = t; i < 1024; i += 256) {
            int row = i >> 2, c = i & 3;
            cp_async16(stg + SWH + row * 80 + c * 16,
                       Wh + (size_t)row * DW + k0 + c * 8);
        }
    };

    ldA(0);
    convSTS(0);
    loadW(0, 0);
    CP_COMMIT();
    ldA(1);
    convSTS(1);
    loadW(1, KBK);
    CP_COMMIT();
    CP_WAIT(1);
    __syncthreads();

    for (int c = 0; c < KV_NCH; c++) {
        int s = c & 1;
        if (c > 0) {
            CP_WAIT(0);
            __syncthreads();
        }
        if (c >= 1 && c + 1 < KV_NCH) {
            convSTS(1 - s);
            loadW(1 - s, (c + 1) * KBK);
            CP_COMMIT();
        }
        if (c + 2 < KV_NCH) ldA(c + 2);

        unsigned stg = sb + s * KP_STG;
        unsigned aHb = stg + SAH + wm * 80 + a_lof;
        unsigned aLb = stg + SAL + wm * 80 + a_lof;
        unsigned wHb = stg + SWH + wn * 80 + w_lof;

#pragma unroll
        for (int ks = 0; ks < 2; ks++) {
            unsigned kb = ks * 32;
            unsigned ah[2][4], al2[2][4], bh[8][2];
#pragma unroll
            for (int mt = 0; mt < 2; mt++) {
                ldsm_x4(ah[mt],  aHb + mt * (16 * 80) + kb);
                ldsm_x4(al2[mt], aLb + mt * (16 * 80) + kb);
            }
#pragma unroll
            for (int nt = 0; nt < 8; nt++)
                ldsm_x2(bh[nt], wHb + nt * (8 * 80) + kb);
#pragma unroll
            for (int nt = 0; nt < 8; nt++)
#pragma unroll
                for (int mt = 0; mt < 2; mt++) mma16816h(acc[mt][nt], ah[mt], bh[nt]);
#pragma unroll
            for (int nt = 0; nt < 8; nt++)
#pragma unroll
                for (int mt = 0; mt < 2; mt++) mma16816h(acc[mt][nt], al2[mt], bh[nt]);
        }
    }

    int gid = lane >> 2, tig = lane & 3;
#pragma unroll
    for (int nt = 0; nt < 8; nt++) {
        int col = wn + nt * 8 + tig * 2;
        float2 bv2 = *(const float2*)(bias + col);
#pragma unroll
        for (int mt = 0; mt < 2; mt++) {
            int r0 = mBase + wm + mt * 16 + gid;
            int r1 = r0 + 8;
            float x0 = (r0 < VV) ? acc[mt][nt][0] * RSCALE + bv2.x : 0.f;
            float x1 = (r0 < VV) ? acc[mt][nt][1] * RSCALE + bv2.y : 0.f;
            float x2 = (r1 < VV) ? acc[mt][nt][2] * RSCALE + bv2.x : 0.f;
            float x3 = (r1 < VV) ? acc[mt][nt][3] * RSCALE + bv2.y : 0.f;
            *(unsigned*)(o16 + (size_t)r0 * DM + col) = pack_h16(x0, x1);
            *(unsigned*)(o16 + (size_t)r1 * DM + col) = pack_h16(x2, x3);
        }
    }
}

// ============================================================
// split-K fp32 SGEMM (Q / O projections)
// ============================================================
__global__ __launch_bounds__(256) void sgemm64s(
    const float* __restrict__ A, const float* __restrict__ Bw,
    float* __restrict__ Cp, int M, int N, int K)
{
    __shared__ float As[16][68];
    __shared__ float Bs[16][68];
    int t = threadIdx.x, tx = t & 15, ty = t >> 4;
    int mB = blockIdx.x * 64, nB = blockIdx.y * 64;
    int kc = K / 4;
    int kBeg = blockIdx.z * kc, kEnd = kBeg + kc;
    float acc[4][4];
#pragma unroll
    for (int i = 0; i < 4; i++)
#pragma unroll
        for (int j = 0; j < 4; j++) acc[i][j] = 0.f;

    for (int k0 = kBeg; k0 < kEnd; k0 += 16) {
        {
            int row = t >> 2, kk = (t & 3) * 4;
            float4 av = *(const float4*)(A + (size_t)(mB + row) * K + k0 + kk);
            As[kk + 0][row] = av.x; As[kk + 1][row] = av.y;
            As[kk + 2][row] = av.z; As[kk + 3][row] = av.w;
        }
        {
            int kr = t >> 4, c4 = (t & 15) * 4;
            *(float4*)&Bs[kr][c4] = *(const float4*)(Bw + (size_t)(k0 + kr) * N + nB + c4);
        }
        __syncthreads();
#pragma unroll
        for (int kk = 0; kk < 16; kk++) {
            float4 a = *(const float4*)&As[kk][ty * 4];
            float4 b = *(const float4*)&Bs[kk][tx * 4];
            float am[4] = {a.x, a.y, a.z, a.w};
            float bn[4] = {b.x, b.y, b.z, b.w};
#pragma unroll
            for (int i = 0; i < 4; i++)
#pragma unroll
                for (int j = 0; j < 4; j++) acc[i][j] += am[i] * bn[j];
        }
        __syncthreads();
    }
    float* outz = Cp + (size_t)blockIdx.z * M * N;
#pragma unroll
    for (int i = 0; i < 4; i++) {
        int m = mB + ty * 4 + i;
#pragma unroll
        for (int j = 0; j < 4; j++) {
            int n = nB + tx * 4 + j;
            outz[(size_t)m * N + n] = acc[i][j];
        }
    }
}

__global__ void combine_bias(const float* __restrict__ Cp, const float* __restrict__ bias,
                             float* __restrict__ out)
{
    int i = blockIdx.x * blockDim.x + threadIdx.x;
    const int MN = BB * LL * DM;
    if (i >= MN) return;
    out[i] = Cp[i] + Cp[MN + i] + Cp[2 * MN + i] + Cp[3 * MN + i] + bias[i & (DM - 1)];
}

// Q combine: fp32 -> (1024*Q) fp16 hi/lo
__global__ void combine_q(const float* __restrict__ Cp, const float* __restrict__ bias,
                          __half* __restrict__ Qh, __half* __restrict__ Ql)
{
    int i = blockIdx.x * blockDim.x + threadIdx.x;
    const int MN = BB * LL * DM;
    if (i >= MN) return;
    float v = (Cp[i] + Cp[MN + i] + Cp[2 * MN + i] + Cp[3 * MN + i] + bias[i & (DM - 1)]) * ASCALE;
    __half h = __float2half(v);
    Qh[i] = h;
    Ql[i] = __float2half(v - __half2float(h));
}

// ============================================================
// Tensor-core fused attention — fp16, 2-term splits
//   S = (Qh + Ql) · K      (Q pre-scaled x1024; CC2 absorbs it)
//   P = softmax_l, split Ph + Pl (fp16, unscaled)
//   O = (Ph + Pl) · V
// ============================================================
#define KSTR 80
#define OFF_QH 0
#define OFF_QL 10240
#define OFF_KV 20480
#define KVBUF 20480          /* K at +0, V at +10240 */
#define OFF_RED (OFF_KV + 2 * KVBUF)        /* 61440 */
#define OFF_RN  (OFF_RED + 2048)            /* 63488 */
#define ATTN_SMEM (OFF_RN + 512)            /* 64000 */

__global__ void __launch_bounds__(512, 1)
attn_tc(const __half* __restrict__ Qh, const __half* __restrict__ Ql,
        const __half* __restrict__ K16, const __half* __restrict__ V16,
        float* __restrict__ part)
{
    extern __shared__ char smem[];
    unsigned sb = smem_u32(smem);
    float* red = (float*)(smem + OFF_RED);
    float* rn  = (float*)(smem + OFF_RN);

    int t = threadIdx.x, lane = t & 31, wid = t >> 5;
    int s = blockIdx.x, h = blockIdx.y, b = blockIdx.z;
    int gid = lane >> 2, tig = lane & 3;
    int lg = wid & 3, vg = wid >> 2;
    int wl = lg * 32, wv = vg * 32;

    {
        size_t qbase = (size_t)(b * LL) * DM + h * EE;
        int row = t >> 2, c = t & 3;
        size_t go = qbase + (size_t)row * DM + c * 8;
        unsigned d = sb + row * KSTR + c * 16;
        cp_async16(d + OFF_QH, Qh + go);
        cp_async16(d + OFF_QL, Ql + go);
    }
    CP_COMMIT();
    CP_WAIT(0);
    __syncthreads();

    unsigned qhf[2][2][4], qlf[2][2][4];
    {
        unsigned alof = (unsigned)((lane & 15) * KSTR + (lane >> 4) * 16);
#pragma unroll
        for (int mt = 0; mt < 2; mt++)
#pragma unroll
            for (int k = 0; k < 2; k++) {
                unsigned off = (wl + 16 * mt) * KSTR + alof + k * 32;
                ldsm_x4(qhf[mt][k], sb + OFF_QH + off);
                ldsm_x4(qlf[mt][k], sb + OFF_QL + off);
            }
    }

    float accO[2][4][4];
#pragma unroll
    for (int i = 0; i < 2; i++)
#pragma unroll
        for (int j = 0; j < 4; j++)
#pragma unroll
            for (int q = 0; q < 4; q++) accO[i][j][q] = 0.f;

    size_t hof = (size_t)h * EE;
    auto load_kv = [&](int buf, int v0) {
        unsigned base = sb + OFF_KV + buf * KVBUF;
        int row = t >> 2, c = t & 3;
        size_t go = (size_t)(v0 + row) * DM + hof + c * 8;
        unsigned d = base + row * KSTR + c * 16;
        cp_async16(d,         K16 + go);
        cp_async16(d + 10240, V16 + go);
    };

    load_kv(0, s * 128);
    CP_COMMIT();

    const float CC2 = 2.4905593479907688e-4f;  // scale * log2(e) / 1024
    int l2 = lane & 15;
    unsigned kb_lof = (unsigned)((l2 & 7) * KSTR + (l2 >> 3) * 16);

    int it = 0;
    for (int tile = s; tile < NTILE; tile += SPLITS, it++) {
        CP_WAIT(0);
        __syncthreads();

        int nxt = tile + SPLITS;
        if (nxt < NTILE) {
            load_kv((it + 1) & 1, nxt * 128);
            CP_COMMIT();
        }
        unsigned kvb = sb + OFF_KV + (it & 1) * KVBUF;

        float accS[2][4][4];
#pragma unroll
        for (int mt = 0; mt < 2; mt++)
#pragma unroll
            for (int n = 0; n < 4; n++)
#pragma unroll
                for (int q = 0; q < 4; q++) accS[mt][n][q] = 0.f;

#pragma unroll
        for (int k = 0; k < 2; k++) {
            unsigned kbh[4][2];
#pragma unroll
            for (int n = 0; n < 4; n++)
                ldsm_x2(kbh[n], kvb + (wv + n * 8) * KSTR + kb_lof + k * 32);
            // term-major, 2 terms
#pragma unroll
            for (int n = 0; n < 4; n++)
#pragma unroll
                for (int mt = 0; mt < 2; mt++) mma16816h(accS[mt][n], qhf[mt][k], kbh[n]);
#pragma unroll
            for (int n = 0; n < 4; n++)
#pragma unroll
                for (int mt = 0; mt < 2; mt++) mma16816h(accS[mt][n], qlf[mt][k], kbh[n]);
        }

        float s0[4], s1[4];
#pragma unroll
        for (int n = 0; n < 4; n++) { s0[n] = 0.f; s1[n] = 0.f; }
#pragma unroll
        for (int mt = 0; mt < 2; mt++)
#pragma unroll
            for (int n = 0; n < 4; n++) {
                accS[mt][n][0] = ex2(accS[mt][n][0] * CC2);
                accS[mt][n][1] = ex2(accS[mt][n][1] * CC2);
                accS[mt][n][2] = ex2(accS[mt][n][2] * CC2);
                accS[mt][n][3] = ex2(accS[mt][n][3] * CC2);
                s0[n] += accS[mt][n][0] + accS[mt][n][2];
                s1[n] += accS[mt][n][1] + accS[mt][n][3];
            }
#pragma unroll
        for (int n = 0; n < 4; n++) {
#pragma unroll
            for (int ofs = 4; ofs < 32; ofs <<= 1) {
                s0[n] += __shfl_xor_sync(0xffffffffu, s0[n], ofs);
                s1[n] += __shfl_xor_sync(0xffffffffu, s1[n], ofs);
            }
        }
        if (gid == 0) {
#pragma unroll
            for (int n = 0; n < 4; n++) {
                red[(wv + n * 8 + tig * 2) * 4 + lg] = s0[n];
                red[(wv + n * 8 + tig * 2 + 1) * 4 + lg] = s1[n];
            }
        }
        __syncthreads();
        if (t < 128) {
            float v = red[t * 4] + red[t * 4 + 1] + red[t * 4 + 2] + red[t * 4 + 3];
            rn[t] = 1.f / v;
        }
        __syncthreads();

#pragma unroll
        for (int n = 0; n < 4; n++) {
            float r0 = rn[wv + n * 8 + tig * 2];
            float r1 = rn[wv + n * 8 + tig * 2 + 1];
#pragma unroll
            for (int mt = 0; mt < 2; mt++) {
                accS[mt][n][0] *= r0;
                accS[mt][n][1] *= r1;
                accS[mt][n][2] *= r0;
                accS[mt][n][3] *= r1;
            }
        }

#pragma unroll
        for (int ks = 0; ks < 2; ks++) {
            unsigned vbh[4][2];
#pragma unroll
            for (int ne = 0; ne < 4; ne++)
                ldsm_x2_t(vbh[ne], kvb + 10240 + (wv + ks * 16 + l2) * KSTR + ne * 16);
            unsigned aph[2][4], apl[2][4];
#pragma unroll
            for (int mt = 0; mt < 2; mt++) {
                float p0 = accS[mt][2 * ks][0], p1 = accS[mt][2 * ks][1];
                float p2 = accS[mt][2 * ks][2], p3 = accS[mt][2 * ks][3];
                float p4 = accS[mt][2 * ks + 1][0], p5 = accS[mt][2 * ks + 1][1];
                float p6 = accS[mt][2 * ks + 1][2], p7 = accS[mt][2 * ks + 1][3];
                aph[mt][0] = pack_h16(p0, p1);
                aph[mt][1] = pack_h16(p2, p3);
                aph[mt][2] = pack_h16(p4, p5);
                aph[mt][3] = pack_h16(p6, p7);
                apl[mt][0] = pack_h16(p0 - __half2float(__float2half(p0)),
                                      p1 - __half2float(__float2half(p1)));
                apl[mt][1] = pack_h16(p2 - __half2float(__float2half(p2)),
                                      p3 - __half2float(__float2half(p3)));
                apl[mt][2] = pack_h16(p4 - __half2float(__float2half(p4)),
                                      p5 - __half2float(__float2half(p5)));
                apl[mt][3] = pack_h16(p6 - __half2float(__float2half(p6)),
                                      p7 - __half2float(__float2half(p7)));
            }
            // term-major, 2 terms
#pragma unroll
            for (int ne = 0; ne < 4; ne++)
#pragma unroll
                for (int mt = 0; mt < 2; mt++) mma16816h(accO[mt][ne], aph[mt], vbh[ne]);
#pragma unroll
            for (int ne = 0; ne < 4; ne++)
#pragma unroll
                for (int mt = 0; mt < 2; mt++) mma16816h(accO[mt][ne], apl[mt], vbh[ne]);
        }
    }

    float* pout = part + (size_t)(((b * HH + h) * SPLITS + s) * 4 + vg) * LL * EE;
#pragma unroll
    for (int mt = 0; mt < 2; mt++) {
        int l = wl + mt * 16 + gid;
#pragma unroll
        for (int ne = 0; ne < 4; ne++) {
            int e = ne * 8 + tig * 2;
            *(float2*)(pout + l * EE + e) = make_float2(accO[mt][ne][0], accO[mt][ne][1]);
            *(float2*)(pout + (l + 8) * EE + e) = make_float2(accO[mt][ne][2], accO[mt][ne][3]);
        }
    }
}

__global__ void reduce_part(const float* __restrict__ part, float* __restrict__ reprog)
{
    int t = blockIdx.x * blockDim.x + threadIdx.x;
    if (t >= BB * LL * DM) return;
    int e = t & 31;
    int h = (t >> 5) & 7;
    int l = (t >> 8) & 127;
    int b = t >> 15;
    const float* p = part + (size_t)(b * HH + h) * SPL4 * LL * EE + l * EE + e;
    float acc = 0.f;
#pragma unroll
    for (int s2 = 0; s2 < SPL4; s2++) acc += p[(size_t)s2 * LL * EE];
    reprog[t] = acc;
}

// ============================================================
// Launch (kv_proj at index 3 for ncu)
// ============================================================
extern "C" void kernel_launch(void* const* d_in, const int* in_sizes, int n_in,
                              void* d_out, int out_size)
{
    (void)in_sizes; (void)n_in; (void)out_size;
    const float* ts = (const float*)d_in[0];
    const float* we = (const float*)d_in[1];
    const float* Wq = (const float*)d_in[2];
    const float* bq = (const float*)d_in[3];
    const float* Wk = (const float*)d_in[4];
    const float* bk = (const float*)d_in[5];
    const float* Wv = (const float*)d_in[6];
    const float* bv = (const float*)d_in[7];
    const float* Wo = (const float*)d_in[8];
    const float* bo = (const float*)d_in[9];
    float* out = (float*)d_out;

    float *gp, *gr, *gsg;
    __half *wk16, *wv16, *k16, *v16, *qh, *ql;
    cudaGetSymbolAddress((void**)&gp, g_part);
    cudaGetSymbolAddress((void**)&gr, g_reprog);
    cudaGetSymbolAddress((void**)&gsg, g_sg);
    cudaGetSymbolAddress((void**)&wk16, g_Wk16);
    cudaGetSymbolAddress((void**)&wv16, g_Wv16);
    cudaGetSymbolAddress((void**)&k16, g_K16);
    cudaGetSymbolAddress((void**)&v16, g_V16);
    cudaGetSymbolAddress((void**)&qh, g_Qh16);
    cudaGetSymbolAddress((void**)&ql, g_Ql16);

    cudaFuncSetAttribute(kv_proj, cudaFuncAttributeMaxDynamicSharedMemorySize, KP_SMEM);
    cudaFuncSetAttribute(attn_tc, cudaFuncAttributeMaxDynamicSharedMemorySize, ATTN_SMEM);

    dim3 wb(32, 8);
    conv_w2<<<dim3(DW / 32, DM / 32, 2), wb>>>(Wk, Wv, wk16, wv16);             // idx 0
    sgemm64s<<<dim3(BB * LL / 64, DM / 64, 4), 256>>>(ts, Wq, gsg, BB * LL, DM, DM); // idx 1
    combine_q<<<(BB * LL * DM + 255) / 256, 256>>>(gsg, bq, qh, ql);            // idx 2
    kv_proj<<<dim3(VPAD / MROWS, 2), 256, KP_SMEM>>>(we, wk16, wv16,
                                                     bk, bv, k16, v16);         // idx 3 (profiled)
    attn_tc<<<dim3(SPLITS, HH, BB), 512, ATTN_SMEM>>>(qh, ql, k16, v16, gp);    // idx 4
    reduce_part<<<(BB * LL * DM + 255) / 256, 256>>>(gp, gr);                   // idx 5
    sgemm64s<<<dim3(BB * LL / 64, DM / 64, 4), 256>>>(gr, Wo, gsg, BB * LL, DM, DM); // idx 6
    combine_bias<<<(BB * LL * DM + 255) / 256, 256>>>(gsg, bo, out);            // idx 7
}

// round 13
// speedup vs baseline: 1.9347x; 1.1227x over previous
#include <cuda_runtime.h>
#include <cuda_bf16.h>
#include <cuda_fp16.h>

#define BB 4
#define LL 128
#define DM 256
#define VV 50257
#define VPAD 50304          /* 393 * 128 */
#define NTILE 393
#define DW 768
#define HH 8
#define EE 32
#define SPLITS 9
#define SPL4 (SPLITS * 4)

// ---- scratch ----
__device__ float g_part[BB * HH * SPL4 * LL * EE];
__device__ float g_reprog[BB * LL * DM];
__device__ float g_sg[4 * BB * LL * DM];
__device__ __half g_Wk16[(size_t)DM * DW];
__device__ __half g_Wv16[(size_t)DM * DW];
__device__ __half g_K16[(size_t)VPAD * DM];
__device__ __half g_V16[(size_t)VPAD * DM];
__device__ __half g_Qh16[BB * LL * DM];
__device__ __half g_Ql16[BB * LL * DM];

// ============================================================
// portable PTX helpers
// ============================================================
__device__ __forceinline__ unsigned smem_u32(const void* p) {
    unsigned a;
    asm("{ .reg .u64 t; cvta.to.shared.u64 t, %1; cvt.u32.u64 %0, t; }" : "=r"(a) : "l"(p));
    return a;
}
__device__ __forceinline__ void cp_async16(unsigned dst, const void* src) {
    asm volatile("cp.async.cg.shared.global [%0], [%1], 16;" :: "r"(dst), "l"(src));
}
#define CP_COMMIT() asm volatile("cp.async.commit_group;" ::: "memory")
#define CP_WAIT(n)  asm volatile("cp.async.wait_group %0;" :: "n"(n) : "memory")

__device__ __forceinline__ void ldsm_x4(unsigned* r, unsigned addr) {
    asm volatile("ldmatrix.sync.aligned.m8n8.x4.shared.b16 {%0,%1,%2,%3}, [%4];"
                 : "=r"(r[0]), "=r"(r[1]), "=r"(r[2]), "=r"(r[3]) : "r"(addr));
}
__device__ __forceinline__ void ldsm_x2(unsigned* r, unsigned addr) {
    asm volatile("ldmatrix.sync.aligned.m8n8.x2.shared.b16 {%0,%1}, [%2];"
                 : "=r"(r[0]), "=r"(r[1]) : "r"(addr));
}
__device__ __forceinline__ void ldsm_x2_t(unsigned* r, unsigned addr) {
    asm volatile("ldmatrix.sync.aligned.m8n8.x2.trans.shared.b16 {%0,%1}, [%2];"
                 : "=r"(r[0]), "=r"(r[1]) : "r"(addr));
}
__device__ __forceinline__ void mma16816h(float* c, const unsigned* a, const unsigned* b) {
    asm volatile("mma.sync.aligned.m16n8k16.row.col.f32.f16.f16.f32 "
                 "{%0,%1,%2,%3}, {%4,%5,%6,%7}, {%8,%9}, {%0,%1,%2,%3};"
                 : "+f"(c[0]), "+f"(c[1]), "+f"(c[2]), "+f"(c[3])
                 : "r"(a[0]), "r"(a[1]), "r"(a[2]), "r"(a[3]), "r"(b[0]), "r"(b[1]));
}
__device__ __forceinline__ float ex2(float x) {
    float r;
    asm("ex2.approx.ftz.f32 %0, %1;" : "=f"(r) : "f"(x));
    return r;
}
__device__ __forceinline__ unsigned pack_h16(float a, float b) {
    __half2 t(__float2half(a), __float2half(b));
    return *(unsigned*)&t;
}

// ============================================================
// weight conversion: fp32 -> single fp16, transposed [N][K], K and V
// ============================================================
__global__ void conv_w2(const float* __restrict__ Wk, const float* __restrict__ Wv,
                        __half* __restrict__ Wk16, __half* __restrict__ Wv16)
{
    __shared__ float tile[32][33];
    const float* W = blockIdx.z ? Wv : Wk;
    __half* Wo = blockIdx.z ? Wv16 : Wk16;
    int k0 = blockIdx.x * 32, n0 = blockIdx.y * 32;
    int tx = threadIdx.x, ty = threadIdx.y;
    for (int r = ty; r < 32; r += 8)
        tile[r][tx] = W[(size_t)(k0 + r) * DM + n0 + tx];
    __syncthreads();
    for (int r = ty; r < 32; r += 8)
        Wo[(size_t)(n0 + r) * DW + k0 + tx] = __float2half(tile[tx][r]);
}

// ============================================================
// KV projection GEMM — plain fp16 (single A term, A pre-scaled x1024)
// CTA: 256 thr (8 warps), 64M x 256N, warp 32x64, 2 CTAs/SM.
// ============================================================
#define MROWS 64
#define KBK 32
#define SAH 0                        /* A: 64*80 = 5120 */
#define SWH 5120                     /* W: 256*80 = 20480 */
#define KP_STG 25600
#define KP_SMEM (2 * KP_STG)         /* 51200 */
#define KV_NCH (DW / KBK)            /* 24 */
#define ASCALE 1024.0f
#define RSCALE 0.0009765625f

__global__ void __launch_bounds__(256, 2)
kv_proj(const float* __restrict__ we,
        const __half* __restrict__ Wk16, const __half* __restrict__ Wv16,
        const float* __restrict__ bk, const float* __restrict__ bv,
        __half* __restrict__ K16, __half* __restrict__ V16)
{
    extern __shared__ char smem[];
    unsigned sb = smem_u32(smem);
    int t = threadIdx.x, lane = t & 31, wid = t >> 5;
    int mBase = blockIdx.x * MROWS;
    int sel = blockIdx.y;
    const __half* Wh = sel ? Wv16 : Wk16;
    const float* bias = sel ? bv : bk;
    __half* o16 = sel ? V16 : K16;

    int wm = (wid & 1) * 32;
    int wn = (wid >> 1) * 64;

    float acc[2][8][4];
#pragma unroll
    for (int i = 0; i < 2; i++)
#pragma unroll
        for (int j = 0; j < 8; j++)
#pragma unroll
            for (int q = 0; q < 4; q++) acc[i][j][q] = 0.f;

    unsigned a_lof = (unsigned)((lane & 15) * 80 + (lane >> 4) * 16);
    int l2 = lane & 15;
    unsigned w_lof = (unsigned)((l2 & 7) * 80 + (l2 >> 3) * 16);

    int ar0 = t >> 3, ac0 = t & 7;
    int ar1 = ar0 + 32;
    bool av0 = (mBase + ar0) < VV;
    bool av1 = (mBase + ar1) < VV;
    const float* ab0 = we + (size_t)(mBase + ar0) * DW + ac0 * 4;
    const float* ab1 = we + (size_t)(mBase + ar1) * DW + ac0 * 4;

    float4 aCur0, aCur1;
    auto ldA = [&](int c) {
        aCur0 = av0 ? *(const float4*)(ab0 + c * KBK) : make_float4(0.f, 0.f, 0.f, 0.f);
        aCur1 = av1 ? *(const float4*)(ab1 + c * KBK) : make_float4(0.f, 0.f, 0.f, 0.f);
    };
    auto convSTS = [&](int s) {
        *(uint2*)(smem + s * KP_STG + SAH + ar0 * 80 + ac0 * 8) =
            make_uint2(pack_h16(aCur0.x * ASCALE, aCur0.y * ASCALE),
                       pack_h16(aCur0.z * ASCALE, aCur0.w * ASCALE));
        *(uint2*)(smem + s * KP_STG + SAH + ar1 * 80 + ac0 * 8) =
            make_uint2(pack_h16(aCur1.x * ASCALE, aCur1.y * ASCALE),
                       pack_h16(aCur1.z * ASCALE, aCur1.w * ASCALE));
    };
    auto loadW = [&](int s, int k0) {
        unsigned stg = sb + s * KP_STG;
#pragma unroll
        for (int i = t; i < 1024; i += 256) {
            int row = i >> 2, c = i & 3;
            cp_async16(stg + SWH + row * 80 + c * 16,
                       Wh + (size_t)row * DW + k0 + c * 8);
        }
    };

    ldA(0);
    convSTS(0);
    loadW(0, 0);
    CP_COMMIT();
    ldA(1);
    convSTS(1);
    loadW(1, KBK);
    CP_COMMIT();
    CP_WAIT(1);
    __syncthreads();

    for (int c = 0; c < KV_NCH; c++) {
        int s = c & 1;
        if (c > 0) {
            CP_WAIT(0);
            __syncthreads();
        }
        if (c >= 1 && c + 1 < KV_NCH) {
            convSTS(1 - s);
            loadW(1 - s, (c + 1) * KBK);
            CP_COMMIT();
        }
        if (c + 2 < KV_NCH) ldA(c + 2);

        unsigned stg = sb + s * KP_STG;
        unsigned aHb = stg + SAH + wm * 80 + a_lof;
        unsigned wHb = stg + SWH + wn * 80 + w_lof;

#pragma unroll
        for (int ks = 0; ks < 2; ks++) {
            unsigned kb = ks * 32;
            unsigned ah[2][4], bh[8][2];
#pragma unroll
            for (int mt = 0; mt < 2; mt++)
                ldsm_x4(ah[mt], aHb + mt * (16 * 80) + kb);
#pragma unroll
            for (int nt = 0; nt < 8; nt++)
                ldsm_x2(bh[nt], wHb + nt * (8 * 80) + kb);
#pragma unroll
            for (int nt = 0; nt < 8; nt++)
#pragma unroll
                for (int mt = 0; mt < 2; mt++) mma16816h(acc[mt][nt], ah[mt], bh[nt]);
        }
    }

    int gid = lane >> 2, tig = lane & 3;
#pragma unroll
    for (int nt = 0; nt < 8; nt++) {
        int col = wn + nt * 8 + tig * 2;
        float2 bv2 = *(const float2*)(bias + col);
#pragma unroll
        for (int mt = 0; mt < 2; mt++) {
            int r0 = mBase + wm + mt * 16 + gid;
            int r1 = r0 + 8;
            float x0 = (r0 < VV) ? acc[mt][nt][0] * RSCALE + bv2.x : 0.f;
            float x1 = (r0 < VV) ? acc[mt][nt][1] * RSCALE + bv2.y : 0.f;
            float x2 = (r1 < VV) ? acc[mt][nt][2] * RSCALE + bv2.x : 0.f;
            float x3 = (r1 < VV) ? acc[mt][nt][3] * RSCALE + bv2.y : 0.f;
            *(unsigned*)(o16 + (size_t)r0 * DM + col) = pack_h16(x0, x1);
            *(unsigned*)(o16 + (size_t)r1 * DM + col) = pack_h16(x2, x3);
        }
    }
}

// ============================================================
// split-K fp32 SGEMM (Q / O projections)
// ============================================================
__global__ __launch_bounds__(256) void sgemm64s(
    const float* __restrict__ A, const float* __restrict__ Bw,
    float* __restrict__ Cp, int M, int N, int K)
{
    __shared__ float As[16][68];
    __shared__ float Bs[16][68];
    int t = threadIdx.x, tx = t & 15, ty = t >> 4;
    int mB = blockIdx.x * 64, nB = blockIdx.y * 64;
    int kc = K / 4;
    int kBeg = blockIdx.z * kc, kEnd = kBeg + kc;
    float acc[4][4];
#pragma unroll
    for (int i = 0; i < 4; i++)
#pragma unroll
        for (int j = 0; j < 4; j++) acc[i][j] = 0.f;

    for (int k0 = kBeg; k0 < kEnd; k0 += 16) {
        {
            int row = t >> 2, kk = (t & 3) * 4;
            float4 av = *(const float4*)(A + (size_t)(mB + row) * K + k0 + kk);
            As[kk + 0][row] = av.x; As[kk + 1][row] = av.y;
            As[kk + 2][row] = av.z; As[kk + 3][row] = av.w;
        }
        {
            int kr = t >> 4, c4 = (t & 15) * 4;
            *(float4*)&Bs[kr][c4] = *(const float4*)(Bw + (size_t)(k0 + kr) * N + nB + c4);
        }
        __syncthreads();
#pragma unroll
        for (int kk = 0; kk < 16; kk++) {
            float4 a = *(const float4*)&As[kk][ty * 4];
            float4 b = *(const float4*)&Bs[kk][tx * 4];
            float am[4] = {a.x, a.y, a.z, a.w};
            float bn[4] = {b.x, b.y, b.z, b.w};
#pragma unroll
            for (int i = 0; i < 4; i++)
#pragma unroll
                for (int j = 0; j < 4; j++) acc[i][j] += am[i] * bn[j];
        }
        __syncthreads();
    }
    float* outz = Cp + (size_t)blockIdx.z * M * N;
#pragma unroll
    for (int i = 0; i < 4; i++) {
        int m = mB + ty * 4 + i;
#pragma unroll
        for (int j = 0; j < 4; j++) {
            int n = nB + tx * 4 + j;
            outz[(size_t)m * N + n] = acc[i][j];
        }
    }
}

__global__ void combine_bias(const float* __restrict__ Cp, const float* __restrict__ bias,
                             float* __restrict__ out)
{
    int i = blockIdx.x * blockDim.x + threadIdx.x;
    const int MN = BB * LL * DM;
    if (i >= MN) return;
    out[i] = Cp[i] + Cp[MN + i] + Cp[2 * MN + i] + Cp[3 * MN + i] + bias[i & (DM - 1)];
}

// Q combine: fp32 -> (1024*Q) fp16 hi/lo
__global__ void combine_q(const float* __restrict__ Cp, const float* __restrict__ bias,
                          __half* __restrict__ Qh, __half* __restrict__ Ql)
{
    int i = blockIdx.x * blockDim.x + threadIdx.x;
    const int MN = BB * LL * DM;
    if (i >= MN) return;
    float v = (Cp[i] + Cp[MN + i] + Cp[2 * MN + i] + Cp[3 * MN + i] + bias[i & (DM - 1)]) * ASCALE;
    __half h = __float2half(v);
    Qh[i] = h;
    Ql[i] = __float2half(v - __half2float(h));
}

// ============================================================
// Tensor-core fused attention — fp16, 2-term splits
// ============================================================
#define KSTR 80
#define OFF_QH 0
#define OFF_QL 10240
#define OFF_KV 20480
#define KVBUF 20480          /* K at +0, V at +10240 */
#define OFF_RED (OFF_KV + 2 * KVBUF)
#define OFF_RN  (OFF_RED + 2048)
#define ATTN_SMEM (OFF_RN + 512)

__global__ void __launch_bounds__(512, 1)
attn_tc(const __half* __restrict__ Qh, const __half* __restrict__ Ql,
        const __half* __restrict__ K16, const __half* __restrict__ V16,
        float* __restrict__ part)
{
    extern __shared__ char smem[];
    unsigned sb = smem_u32(smem);
    float* red = (float*)(smem + OFF_RED);
    float* rn  = (float*)(smem + OFF_RN);

    int t = threadIdx.x, lane = t & 31, wid = t >> 5;
    int s = blockIdx.x, h = blockIdx.y, b = blockIdx.z;
    int gid = lane >> 2, tig = lane & 3;
    int lg = wid & 3, vg = wid >> 2;
    int wl = lg * 32, wv = vg * 32;

    {
        size_t qbase = (size_t)(b * LL) * DM + h * EE;
        int row = t >> 2, c = t & 3;
        size_t go = qbase + (size_t)row * DM + c * 8;
        unsigned d = sb + row * KSTR + c * 16;
        cp_async16(d + OFF_QH, Qh + go);
        cp_async16(d + OFF_QL, Ql + go);
    }
    CP_COMMIT();
    CP_WAIT(0);
    __syncthreads();

    unsigned qhf[2][2][4], qlf[2][2][4];
    {
        unsigned alof = (unsigned)((lane & 15) * KSTR + (lane >> 4) * 16);
#pragma unroll
        for (int mt = 0; mt < 2; mt++)
#pragma unroll
            for (int k = 0; k < 2; k++) {
                unsigned off = (wl + 16 * mt) * KSTR + alof + k * 32;
                ldsm_x4(qhf[mt][k], sb + OFF_QH + off);
                ldsm_x4(qlf[mt][k], sb + OFF_QL + off);
            }
    }

    float accO[2][4][4];
#pragma unroll
    for (int i = 0; i < 2; i++)
#pragma unroll
        for (int j = 0; j < 4; j++)
#pragma unroll
            for (int q = 0; q < 4; q++) accO[i][j][q] = 0.f;

    size_t hof = (size_t)h * EE;
    auto load_kv = [&](int buf, int v0) {
        unsigned base = sb + OFF_KV + buf * KVBUF;
        int row = t >> 2, c = t & 3;
        size_t go = (size_t)(v0 + row) * DM + hof + c * 8;
        unsigned d = base + row * KSTR + c * 16;
        cp_async16(d,         K16 + go);
        cp_async16(d + 10240, V16 + go);
    };

    load_kv(0, s * 128);
    CP_COMMIT();

    const float CC2 = 2.4905593479907688e-4f;  // scale * log2(e) / 1024
    int l2 = lane & 15;
    unsigned kb_lof = (unsigned)((l2 & 7) * KSTR + (l2 >> 3) * 16);

    int it = 0;
    for (int tile = s; tile < NTILE; tile += SPLITS, it++) {
        CP_WAIT(0);
        __syncthreads();

        int nxt = tile + SPLITS;
        if (nxt < NTILE) {
            load_kv((it + 1) & 1, nxt * 128);
            CP_COMMIT();
        }
        unsigned kvb = sb + OFF_KV + (it & 1) * KVBUF;

        float accS[2][4][4];
#pragma unroll
        for (int mt = 0; mt < 2; mt++)
#pragma unroll
            for (int n = 0; n < 4; n++)
#pragma unroll
                for (int q = 0; q < 4; q++) accS[mt][n][q] = 0.f;

#pragma unroll
        for (int k = 0; k < 2; k++) {
            unsigned kbh[4][2];
#pragma unroll
            for (int n = 0; n < 4; n++)
                ldsm_x2(kbh[n], kvb + (wv + n * 8) * KSTR + kb_lof + k * 32);
#pragma unroll
            for (int n = 0; n < 4; n++)
#pragma unroll
                for (int mt = 0; mt < 2; mt++) mma16816h(accS[mt][n], qhf[mt][k], kbh[n]);
#pragma unroll
            for (int n = 0; n < 4; n++)
#pragma unroll
                for (int mt = 0; mt < 2; mt++) mma16816h(accS[mt][n], qlf[mt][k], kbh[n]);
        }

        float s0[4], s1[4];
#pragma unroll
        for (int n = 0; n < 4; n++) { s0[n] = 0.f; s1[n] = 0.f; }
#pragma unroll
        for (int mt = 0; mt < 2; mt++)
#pragma unroll
            for (int n = 0; n < 4; n++) {
                accS[mt][n][0] = ex2(accS[mt][n][0] * CC2);
                accS[mt][n][1] = ex2(accS[mt][n][1] * CC2);
                accS[mt][n][2] = ex2(accS[mt][n][2] * CC2);
                accS[mt][n][3] = ex2(accS[mt][n][3] * CC2);
                s0[n] += accS[mt][n][0] + accS[mt][n][2];
                s1[n] += accS[mt][n][1] + accS[mt][n][3];
            }
#pragma unroll
        for (int n = 0; n < 4; n++) {
#pragma unroll
            for (int ofs = 4; ofs < 32; ofs <<= 1) {
                s0[n] += __shfl_xor_sync(0xffffffffu, s0[n], ofs);
                s1[n] += __shfl_xor_sync(0xffffffffu, s1[n], ofs);
            }
        }
        if (gid == 0) {
#pragma unroll
            for (int n = 0; n < 4; n++) {
                red[(wv + n * 8 + tig * 2) * 4 + lg] = s0[n];
                red[(wv + n * 8 + tig * 2 + 1) * 4 + lg] = s1[n];
            }
        }
        __syncthreads();
        if (t < 128) {
            float v = red[t * 4] + red[t * 4 + 1] + red[t * 4 + 2] + red[t * 4 + 3];
            rn[t] = 1.f / v;
        }
        __syncthreads();

#pragma unroll
        for (int n = 0; n < 4; n++) {
            float r0 = rn[wv + n * 8 + tig * 2];
            float r1 = rn[wv + n * 8 + tig * 2 + 1];
#pragma unroll
            for (int mt = 0; mt < 2; mt++) {
                accS[mt][n][0] *= r0;
                accS[mt][n][1] *= r1;
                accS[mt][n][2] *= r0;
                accS[mt][n][3] *= r1;
            }
        }

#pragma unroll
        for (int ks = 0; ks < 2; ks++) {
            unsigned vbh[4][2];
#pragma unroll
            for (int ne = 0; ne < 4; ne++)
                ldsm_x2_t(vbh[ne], kvb + 10240 + (wv + ks * 16 + l2) * KSTR + ne * 16);
            unsigned aph[2][4], apl[2][4];
#pragma unroll
            for (int mt = 0; mt < 2; mt++) {
                float p0 = accS[mt][2 * ks][0], p1 = accS[mt][2 * ks][1];
                float p2 = accS[mt][2 * ks][2], p3 = accS[mt][2 * ks][3];
                float p4 = accS[mt][2 * ks + 1][0], p5 = accS[mt][2 * ks + 1][1];
                float p6 = accS[mt][2 * ks + 1][2], p7 = accS[mt][2 * ks + 1][3];
                aph[mt][0] = pack_h16(p0, p1);
                aph[mt][1] = pack_h16(p2, p3);
                aph[mt][2] = pack_h16(p4, p5);
                aph[mt][3] = pack_h16(p6, p7);
                apl[mt][0] = pack_h16(p0 - __half2float(__float2half(p0)),
                                      p1 - __half2float(__float2half(p1)));
                apl[mt][1] = pack_h16(p2 - __half2float(__float2half(p2)),
                                      p3 - __half2float(__float2half(p3)));
                apl[mt][2] = pack_h16(p4 - __half2float(__float2half(p4)),
                                      p5 - __half2float(__float2half(p5)));
                apl[mt][3] = pack_h16(p6 - __half2float(__float2half(p6)),
                                      p7 - __half2float(__float2half(p7)));
            }
#pragma unroll
            for (int ne = 0; ne < 4; ne++)
#pragma unroll
                for (int mt = 0; mt < 2; mt++) mma16816h(accO[mt][ne], aph[mt], vbh[ne]);
#pragma unroll
            for (int ne = 0; ne < 4; ne++)
#pragma unroll
                for (int mt = 0; mt < 2; mt++) mma16816h(accO[mt][ne], apl[mt], vbh[ne]);
        }
    }

    float* pout = part + (size_t)(((b * HH + h) * SPLITS + s) * 4 + vg) * LL * EE;
#pragma unroll
    for (int mt = 0; mt < 2; mt++) {
        int l = wl + mt * 16 + gid;
#pragma unroll
        for (int ne = 0; ne < 4; ne++) {
            int e = ne * 8 + tig * 2;
            *(float2*)(pout + l * EE + e) = make_float2(accO[mt][ne][0], accO[mt][ne][1]);
            *(float2*)(pout + (l + 8) * EE + e) = make_float2(accO[mt][ne][2], accO[mt][ne][3]);
        }
    }
}

__global__ void reduce_part(const float* __restrict__ part, float* __restrict__ reprog)
{
    int t = blockIdx.x * blockDim.x + threadIdx.x;
    if (t >= BB * LL * DM) return;
    int e = t & 31;
    int h = (t >> 5) & 7;
    int l = (t >> 8) & 127;
    int b = t >> 15;
    const float* p = part + (size_t)(b * HH + h) * SPL4 * LL * EE + l * EE + e;
    float acc = 0.f;
#pragma unroll
    for (int s2 = 0; s2 < SPL4; s2++) acc += p[(size_t)s2 * LL * EE];
    reprog[t] = acc;
}

// ============================================================
// Launch (kv_proj at index 3 for ncu)
// ============================================================
extern "C" void kernel_launch(void* const* d_in, const int* in_sizes, int n_in,
                              void* d_out, int out_size)
{
    (void)in_sizes; (void)n_in; (void)out_size;
    const float* ts = (const float*)d_in[0];
    const float* we = (const float*)d_in[1];
    const float* Wq = (const float*)d_in[2];
    const float* bq = (const float*)d_in[3];
    const float* Wk = (const float*)d_in[4];
    const float* bk = (const float*)d_in[5];
    const float* Wv = (const float*)d_in[6];
    const float* bv = (const float*)d_in[7];
    const float* Wo = (const float*)d_in[8];
    const float* bo = (const float*)d_in[9];
    float* out = (float*)d_out;

    float *gp, *gr, *gsg;
    __half *wk16, *wv16, *k16, *v16, *qh, *ql;
    cudaGetSymbolAddress((void**)&gp, g_part);
    cudaGetSymbolAddress((void**)&gr, g_reprog);
    cudaGetSymbolAddress((void**)&gsg, g_sg);
    cudaGetSymbolAddress((void**)&wk16, g_Wk16);
    cudaGetSymbolAddress((void**)&wv16, g_Wv16);
    cudaGetSymbolAddress((void**)&k16, g_K16);
    cudaGetSymbolAddress((void**)&v16, g_V16);
    cudaGetSymbolAddress((void**)&qh, g_Qh16);
    cudaGetSymbolAddress((void**)&ql, g_Ql16);

    cudaFuncSetAttribute(kv_proj, cudaFuncAttributeMaxDynamicSharedMemorySize, KP_SMEM);
    cudaFuncSetAttribute(attn_tc, cudaFuncAttributeMaxDynamicSharedMemorySize, ATTN_SMEM);

    dim3 wb(32, 8);
    conv_w2<<<dim3(DW / 32, DM / 32, 2), wb>>>(Wk, Wv, wk16, wv16);             // idx 0
    sgemm64s<<<dim3(BB * LL / 64, DM / 64, 4), 256>>>(ts, Wq, gsg, BB * LL, DM, DM); // idx 1
    combine_q<<<(BB * LL * DM + 255) / 256, 256>>>(gsg, bq, qh, ql);            // idx 2
    kv_proj<<<dim3(VPAD / MROWS, 2), 256, KP_SMEM>>>(we, wk16, wv16,
                                                     bk, bv, k16, v16);         // idx 3 (profiled)
    attn_tc<<<dim3(SPLITS, HH, BB), 512, ATTN_SMEM>>>(qh, ql, k16, v16, gp);    // idx 4
    reduce_part<<<(BB * LL * DM + 255) / 256, 256>>>(gp, gr);                   // idx 5
    sgemm64s<<<dim3(BB * LL / 64, DM / 64, 4), 256>>>(gr, Wo, gsg, BB * LL, DM, DM); // idx 6
    combine_bias<<<(BB * LL * DM + 255) / 256, 256>>>(gsg, bo, out);            // idx 7
}

// round 14
// speedup vs baseline: 2.2690x; 1.1728x over previous
#include <cuda_runtime.h>
#include <cuda_bf16.h>
#include <cuda_fp16.h>

#define BB 4
#define LL 128
#define DM 256
#define VV 50257
#define VPAD 50304          /* 393 * 128 */
#define NTILE 393
#define DW 768
#define HH 8
#define EE 32
#define SPLITS 9
#define SPL4 (SPLITS * 4)

// ---- scratch ----
__device__ float g_part[BB * HH * SPL4 * LL * EE];
__device__ float g_reprog[BB * LL * DM];
__device__ float g_sg[4 * BB * LL * DM];
__device__ __half g_Wk16[(size_t)DM * DW];
__device__ __half g_Wv16[(size_t)DM * DW];
__device__ __half g_K16[(size_t)VPAD * DM];
__device__ __half g_V16[(size_t)VPAD * DM];
__device__ __half g_Qh16[BB * LL * DM];

// ============================================================
// portable PTX helpers
// ============================================================
__device__ __forceinline__ unsigned smem_u32(const void* p) {
    unsigned a;
    asm("{ .reg .u64 t; cvta.to.shared.u64 t, %1; cvt.u32.u64 %0, t; }" : "=r"(a) : "l"(p));
    return a;
}
__device__ __forceinline__ void cp_async16(unsigned dst, const void* src) {
    asm volatile("cp.async.cg.shared.global [%0], [%1], 16;" :: "r"(dst), "l"(src));
}
#define CP_COMMIT() asm volatile("cp.async.commit_group;" ::: "memory")
#define CP_WAIT(n)  asm volatile("cp.async.wait_group %0;" :: "n"(n) : "memory")

__device__ __forceinline__ void ldsm_x4(unsigned* r, unsigned addr) {
    asm volatile("ldmatrix.sync.aligned.m8n8.x4.shared.b16 {%0,%1,%2,%3}, [%4];"
                 : "=r"(r[0]), "=r"(r[1]), "=r"(r[2]), "=r"(r[3]) : "r"(addr));
}
__device__ __forceinline__ void ldsm_x2(unsigned* r, unsigned addr) {
    asm volatile("ldmatrix.sync.aligned.m8n8.x2.shared.b16 {%0,%1}, [%2];"
                 : "=r"(r[0]), "=r"(r[1]) : "r"(addr));
}
__device__ __forceinline__ void ldsm_x2_t(unsigned* r, unsigned addr) {
    asm volatile("ldmatrix.sync.aligned.m8n8.x2.trans.shared.b16 {%0,%1}, [%2];"
                 : "=r"(r[0]), "=r"(r[1]) : "r"(addr));
}
__device__ __forceinline__ void mma16816h(float* c, const unsigned* a, const unsigned* b) {
    asm volatile("mma.sync.aligned.m16n8k16.row.col.f32.f16.f16.f32 "
                 "{%0,%1,%2,%3}, {%4,%5,%6,%7}, {%8,%9}, {%0,%1,%2,%3};"
                 : "+f"(c[0]), "+f"(c[1]), "+f"(c[2]), "+f"(c[3])
                 : "r"(a[0]), "r"(a[1]), "r"(a[2]), "r"(a[3]), "r"(b[0]), "r"(b[1]));
}
__device__ __forceinline__ float ex2(float x) {
    float r;
    asm("ex2.approx.ftz.f32 %0, %1;" : "=f"(r) : "f"(x));
    return r;
}
__device__ __forceinline__ unsigned pack_h16(float a, float b) {
    __half2 t(__float2half(a), __float2half(b));
    return *(unsigned*)&t;
}

// ============================================================
// weight conversion: fp32 -> single fp16, transposed [N][K], K and V
// ============================================================
__global__ void conv_w2(const float* __restrict__ Wk, const float* __restrict__ Wv,
                        __half* __restrict__ Wk16, __half* __restrict__ Wv16)
{
    __shared__ float tile[32][33];
    const float* W = blockIdx.z ? Wv : Wk;
    __half* Wo = blockIdx.z ? Wv16 : Wk16;
    int k0 = blockIdx.x * 32, n0 = blockIdx.y * 32;
    int tx = threadIdx.x, ty = threadIdx.y;
    for (int r = ty; r < 32; r += 8)
        tile[r][tx] = W[(size_t)(k0 + r) * DM + n0 + tx];
    __syncthreads();
    for (int r = ty; r < 32; r += 8)
        Wo[(size_t)(n0 + r) * DW + k0 + tx] = __float2half(tile[tx][r]);
}

// ============================================================
// Q projection: fused fp32 GEMM + bias -> fp16 (single kernel)
// 64x64 tiles, full K=256
// ============================================================
__global__ __launch_bounds__(256) void qproj(
    const float* __restrict__ A, const float* __restrict__ Bw,
    const float* __restrict__ bias, __half* __restrict__ Qh)
{
    __shared__ float As[16][68];
    __shared__ float Bs[16][68];
    int t = threadIdx.x, tx = t & 15, ty = t >> 4;
    int mB = blockIdx.x * 64, nB = blockIdx.y * 64;
    float acc[4][4];
#pragma unroll
    for (int i = 0; i < 4; i++)
#pragma unroll
        for (int j = 0; j < 4; j++) acc[i][j] = 0.f;

    for (int k0 = 0; k0 < DM; k0 += 16) {
        {
            int row = t >> 2, kk = (t & 3) * 4;
            float4 av = *(const float4*)(A + (size_t)(mB + row) * DM + k0 + kk);
            As[kk + 0][row] = av.x; As[kk + 1][row] = av.y;
            As[kk + 2][row] = av.z; As[kk + 3][row] = av.w;
        }
        {
            int kr = t >> 4, c4 = (t & 15) * 4;
            *(float4*)&Bs[kr][c4] = *(const float4*)(Bw + (size_t)(k0 + kr) * DM + nB + c4);
        }
        __syncthreads();
#pragma unroll
        for (int kk = 0; kk < 16; kk++) {
            float4 a = *(const float4*)&As[kk][ty * 4];
            float4 b = *(const float4*)&Bs[kk][tx * 4];
            float am[4] = {a.x, a.y, a.z, a.w};
            float bn[4] = {b.x, b.y, b.z, b.w};
#pragma unroll
            for (int i = 0; i < 4; i++)
#pragma unroll
                for (int j = 0; j < 4; j++) acc[i][j] += am[i] * bn[j];
        }
        __syncthreads();
    }
#pragma unroll
    for (int i = 0; i < 4; i++) {
        int m = mB + ty * 4 + i;
#pragma unroll
        for (int j = 0; j < 4; j++) {
            int n = nB + tx * 4 + j;
            Qh[(size_t)m * DM + n] = __float2half(acc[i][j] + bias[n]);
        }
    }
}

// ============================================================
// KV projection GEMM — plain fp16 (single A term, A pre-scaled x1024)
// ============================================================
#define MROWS 64
#define KBK 32
#define SAH 0
#define SWH 5120
#define KP_STG 25600
#define KP_SMEM (2 * KP_STG)
#define KV_NCH (DW / KBK)
#define ASCALE 1024.0f
#define RSCALE 0.0009765625f

__global__ void __launch_bounds__(256, 2)
kv_proj(const float* __restrict__ we,
        const __half* __restrict__ Wk16, const __half* __restrict__ Wv16,
        const float* __restrict__ bk, const float* __restrict__ bv,
        __half* __restrict__ K16, __half* __restrict__ V16)
{
    extern __shared__ char smem[];
    unsigned sb = smem_u32(smem);
    int t = threadIdx.x, lane = t & 31, wid = t >> 5;
    int mBase = blockIdx.x * MROWS;
    int sel = blockIdx.y;
    const __half* Wh = sel ? Wv16 : Wk16;
    const float* bias = sel ? bv : bk;
    __half* o16 = sel ? V16 : K16;

    int wm = (wid & 1) * 32;
    int wn = (wid >> 1) * 64;

    float acc[2][8][4];
#pragma unroll
    for (int i = 0; i < 2; i++)
#pragma unroll
        for (int j = 0; j < 8; j++)
#pragma unroll
            for (int q = 0; q < 4; q++) acc[i][j][q] = 0.f;

    unsigned a_lof = (unsigned)((lane & 15) * 80 + (lane >> 4) * 16);
    int l2 = lane & 15;
    unsigned w_lof = (unsigned)((l2 & 7) * 80 + (l2 >> 3) * 16);

    int ar0 = t >> 3, ac0 = t & 7;
    int ar1 = ar0 + 32;
    bool av0 = (mBase + ar0) < VV;
    bool av1 = (mBase + ar1) < VV;
    const float* ab0 = we + (size_t)(mBase + ar0) * DW + ac0 * 4;
    const float* ab1 = we + (size_t)(mBase + ar1) * DW + ac0 * 4;

    float4 aCur0, aCur1;
    auto ldA = [&](int c) {
        aCur0 = av0 ? *(const float4*)(ab0 + c * KBK) : make_float4(0.f, 0.f, 0.f, 0.f);
        aCur1 = av1 ? *(const float4*)(ab1 + c * KBK) : make_float4(0.f, 0.f, 0.f, 0.f);
    };
    auto convSTS = [&](int s) {
        *(uint2*)(smem + s * KP_STG + SAH + ar0 * 80 + ac0 * 8) =
            make_uint2(pack_h16(aCur0.x * ASCALE, aCur0.y * ASCALE),
                       pack_h16(aCur0.z * ASCALE, aCur0.w * ASCALE));
        *(uint2*)(smem + s * KP_STG + SAH + ar1 * 80 + ac0 * 8) =
            make_uint2(pack_h16(aCur1.x * ASCALE, aCur1.y * ASCALE),
                       pack_h16(aCur1.z * ASCALE, aCur1.w * ASCALE));
    };
    auto loadW = [&](int s, int k0) {
        unsigned stg = sb + s * KP_STG;
#pragma unroll
        for (int i = t; i < 1024; i += 256) {
            int row = i >> 2, c = i & 3;
            cp_async16(stg + SWH + row * 80 + c * 16,
                       Wh + (size_t)row * DW + k0 + c * 8);
        }
    };

    ldA(0);
    convSTS(0);
    loadW(0, 0);
    CP_COMMIT();
    ldA(1);
    convSTS(1);
    loadW(1, KBK);
    CP_COMMIT();
    CP_WAIT(1);
    __syncthreads();

    for (int c = 0; c < KV_NCH; c++) {
        int s = c & 1;
        if (c > 0) {
            CP_WAIT(0);
            __syncthreads();
        }
        if (c >= 1 && c + 1 < KV_NCH) {
            convSTS(1 - s);
            loadW(1 - s, (c + 1) * KBK);
            CP_COMMIT();
        }
        if (c + 2 < KV_NCH) ldA(c + 2);

        unsigned stg = sb + s * KP_STG;
        unsigned aHb = stg + SAH + wm * 80 + a_lof;
        unsigned wHb = stg + SWH + wn * 80 + w_lof;

#pragma unroll
        for (int ks = 0; ks < 2; ks++) {
            unsigned kb = ks * 32;
            unsigned ah[2][4], bh[8][2];
#pragma unroll
            for (int mt = 0; mt < 2; mt++)
                ldsm_x4(ah[mt], aHb + mt * (16 * 80) + kb);
#pragma unroll
            for (int nt = 0; nt < 8; nt++)
                ldsm_x2(bh[nt], wHb + nt * (8 * 80) + kb);
#pragma unroll
            for (int nt = 0; nt < 8; nt++)
#pragma unroll
                for (int mt = 0; mt < 2; mt++) mma16816h(acc[mt][nt], ah[mt], bh[nt]);
        }
    }

    int gid = lane >> 2, tig = lane & 3;
#pragma unroll
    for (int nt = 0; nt < 8; nt++) {
        int col = wn + nt * 8 + tig * 2;
        float2 bv2 = *(const float2*)(bias + col);
#pragma unroll
        for (int mt = 0; mt < 2; mt++) {
            int r0 = mBase + wm + mt * 16 + gid;
            int r1 = r0 + 8;
            float x0 = (r0 < VV) ? acc[mt][nt][0] * RSCALE + bv2.x : 0.f;
            float x1 = (r0 < VV) ? acc[mt][nt][1] * RSCALE + bv2.y : 0.f;
            float x2 = (r1 < VV) ? acc[mt][nt][2] * RSCALE + bv2.x : 0.f;
            float x3 = (r1 < VV) ? acc[mt][nt][3] * RSCALE + bv2.y : 0.f;
            *(unsigned*)(o16 + (size_t)r0 * DM + col) = pack_h16(x0, x1);
            *(unsigned*)(o16 + (size_t)r1 * DM + col) = pack_h16(x2, x3);
        }
    }
}

// ============================================================
// split-K fp32 SGEMM (O projection)
// ============================================================
__global__ __launch_bounds__(256) void sgemm64s(
    const float* __restrict__ A, const float* __restrict__ Bw,
    float* __restrict__ Cp, int M, int N, int K)
{
    __shared__ float As[16][68];
    __shared__ float Bs[16][68];
    int t = threadIdx.x, tx = t & 15, ty = t >> 4;
    int mB = blockIdx.x * 64, nB = blockIdx.y * 64;
    int kc = K / 4;
    int kBeg = blockIdx.z * kc, kEnd = kBeg + kc;
    float acc[4][4];
#pragma unroll
    for (int i = 0; i < 4; i++)
#pragma unroll
        for (int j = 0; j < 4; j++) acc[i][j] = 0.f;

    for (int k0 = kBeg; k0 < kEnd; k0 += 16) {
        {
            int row = t >> 2, kk = (t & 3) * 4;
            float4 av = *(const float4*)(A + (size_t)(mB + row) * K + k0 + kk);
            As[kk + 0][row] = av.x; As[kk + 1][row] = av.y;
            As[kk + 2][row] = av.z; As[kk + 3][row] = av.w;
        }
        {
            int kr = t >> 4, c4 = (t & 15) * 4;
            *(float4*)&Bs[kr][c4] = *(const float4*)(Bw + (size_t)(k0 + kr) * N + nB + c4);
        }
        __syncthreads();
#pragma unroll
        for (int kk = 0; kk < 16; kk++) {
            float4 a = *(const float4*)&As[kk][ty * 4];
            float4 b = *(const float4*)&Bs[kk][tx * 4];
            float am[4] = {a.x, a.y, a.z, a.w};
            float bn[4] = {b.x, b.y, b.z, b.w};
#pragma unroll
            for (int i = 0; i < 4; i++)
#pragma unroll
                for (int j = 0; j < 4; j++) acc[i][j] += am[i] * bn[j];
        }
        __syncthreads();
    }
    float* outz = Cp + (size_t)blockIdx.z * M * N;
#pragma unroll
    for (int i = 0; i < 4; i++) {
        int m = mB + ty * 4 + i;
#pragma unroll
        for (int j = 0; j < 4; j++) {
            int n = nB + tx * 4 + j;
            outz[(size_t)m * N + n] = acc[i][j];
        }
    }
}

__global__ void combine_bias(const float* __restrict__ Cp, const float* __restrict__ bias,
                             float* __restrict__ out)
{
    int i = blockIdx.x * blockDim.x + threadIdx.x;
    const int MN = BB * LL * DM;
    if (i >= MN) return;
    out[i] = Cp[i] + Cp[MN + i] + Cp[2 * MN + i] + Cp[3 * MN + i] + bias[i & (DM - 1)];
}

// ============================================================
// Tensor-core fused attention — all-fp16 single-term
//   S = Q16 · K16 ; P = softmax_l(S) -> fp16 ; O = P16 · V16
// ============================================================
#define KSTR 80
#define OFF_QH 0
#define OFF_KV 10240
#define KVBUF 20480          /* K at +0, V at +10240 */
#define OFF_RED (OFF_KV + 2 * KVBUF)        /* 51200 */
#define OFF_RN  (OFF_RED + 2048)            /* 53248 */
#define ATTN_SMEM (OFF_RN + 512)            /* 53760 */

__global__ void __launch_bounds__(512, 1)
attn_tc(const __half* __restrict__ Qh,
        const __half* __restrict__ K16, const __half* __restrict__ V16,
        float* __restrict__ part)
{
    extern __shared__ char smem[];
    unsigned sb = smem_u32(smem);
    float* red = (float*)(smem + OFF_RED);
    float* rn  = (float*)(smem + OFF_RN);

    int t = threadIdx.x, lane = t & 31, wid = t >> 5;
    int s = blockIdx.x, h = blockIdx.y, b = blockIdx.z;
    int gid = lane >> 2, tig = lane & 3;
    int lg = wid & 3, vg = wid >> 2;
    int wl = lg * 32, wv = vg * 32;

    {
        size_t qbase = (size_t)(b * LL) * DM + h * EE;
        int row = t >> 2, c = t & 3;
        size_t go = qbase + (size_t)row * DM + c * 8;
        cp_async16(sb + OFF_QH + row * KSTR + c * 16, Qh + go);
    }
    CP_COMMIT();
    CP_WAIT(0);
    __syncthreads();

    unsigned qhf[2][2][4];
    {
        unsigned alof = (unsigned)((lane & 15) * KSTR + (lane >> 4) * 16);
#pragma unroll
        for (int mt = 0; mt < 2; mt++)
#pragma unroll
            for (int k = 0; k < 2; k++) {
                unsigned off = (wl + 16 * mt) * KSTR + alof + k * 32;
                ldsm_x4(qhf[mt][k], sb + OFF_QH + off);
            }
    }

    float accO[2][4][4];
#pragma unroll
    for (int i = 0; i < 2; i++)
#pragma unroll
        for (int j = 0; j < 4; j++)
#pragma unroll
            for (int q = 0; q < 4; q++) accO[i][j][q] = 0.f;

    size_t hof = (size_t)h * EE;
    auto load_kv = [&](int buf, int v0) {
        unsigned base = sb + OFF_KV + buf * KVBUF;
        int row = t >> 2, c = t & 3;
        size_t go = (size_t)(v0 + row) * DM + hof + c * 8;
        unsigned d = base + row * KSTR + c * 16;
        cp_async16(d,         K16 + go);
        cp_async16(d + 10240, V16 + go);
    };

    load_kv(0, s * 128);
    CP_COMMIT();

    const float CC = 0.25503327723425473f;  // scale * log2(e)
    int l2 = lane & 15;
    unsigned kb_lof = (unsigned)((l2 & 7) * KSTR + (l2 >> 3) * 16);

    int it = 0;
    for (int tile = s; tile < NTILE; tile += SPLITS, it++) {
        CP_WAIT(0);
        __syncthreads();

        int nxt = tile + SPLITS;
        if (nxt < NTILE) {
            load_kv((it + 1) & 1, nxt * 128);
            CP_COMMIT();
        }
        unsigned kvb = sb + OFF_KV + (it & 1) * KVBUF;

        float accS[2][4][4];
#pragma unroll
        for (int mt = 0; mt < 2; mt++)
#pragma unroll
            for (int n = 0; n < 4; n++)
#pragma unroll
                for (int q = 0; q < 4; q++) accS[mt][n][q] = 0.f;

#pragma unroll
        for (int k = 0; k < 2; k++) {
            unsigned kbh[4][2];
#pragma unroll
            for (int n = 0; n < 4; n++)
                ldsm_x2(kbh[n], kvb + (wv + n * 8) * KSTR + kb_lof + k * 32);
#pragma unroll
            for (int n = 0; n < 4; n++)
#pragma unroll
                for (int mt = 0; mt < 2; mt++) mma16816h(accS[mt][n], qhf[mt][k], kbh[n]);
        }

        float s0[4], s1[4];
#pragma unroll
        for (int n = 0; n < 4; n++) { s0[n] = 0.f; s1[n] = 0.f; }
#pragma unroll
        for (int mt = 0; mt < 2; mt++)
#pragma unroll
            for (int n = 0; n < 4; n++) {
                accS[mt][n][0] = ex2(accS[mt][n][0] * CC);
                accS[mt][n][1] = ex2(accS[mt][n][1] * CC);
                accS[mt][n][2] = ex2(accS[mt][n][2] * CC);
                accS[mt][n][3] = ex2(accS[mt][n][3] * CC);
                s0[n] += accS[mt][n][0] + accS[mt][n][2];
                s1[n] += accS[mt][n][1] + accS[mt][n][3];
            }
#pragma unroll
        for (int n = 0; n < 4; n++) {
#pragma unroll
            for (int ofs = 4; ofs < 32; ofs <<= 1) {
                s0[n] += __shfl_xor_sync(0xffffffffu, s0[n], ofs);
                s1[n] += __shfl_xor_sync(0xffffffffu, s1[n], ofs);
            }
        }
        if (gid == 0) {
#pragma unroll
            for (int n = 0; n < 4; n++) {
                red[(wv + n * 8 + tig * 2) * 4 + lg] = s0[n];
                red[(wv + n * 8 + tig * 2 + 1) * 4 + lg] = s1[n];
            }
        }
        __syncthreads();
        if (t < 128) {
            float v = red[t * 4] + red[t * 4 + 1] + red[t * 4 + 2] + red[t * 4 + 3];
            rn[t] = 1.f / v;
        }
        __syncthreads();

#pragma unroll
        for (int n = 0; n < 4; n++) {
            float r0 = rn[wv + n * 8 + tig * 2];
            float r1 = rn[wv + n * 8 + tig * 2 + 1];
#pragma unroll
            for (int mt = 0; mt < 2; mt++) {
                accS[mt][n][0] *= r0;
                accS[mt][n][1] *= r1;
                accS[mt][n][2] *= r0;
                accS[mt][n][3] *= r1;
            }
        }

#pragma unroll
        for (int ks = 0; ks < 2; ks++) {
            unsigned vbh[4][2];
#pragma unroll
            for (int ne = 0; ne < 4; ne++)
                ldsm_x2_t(vbh[ne], kvb + 10240 + (wv + ks * 16 + l2) * KSTR + ne * 16);
            unsigned aph[2][4];
#pragma unroll
            for (int mt = 0; mt < 2; mt++) {
                aph[mt][0] = pack_h16(accS[mt][2 * ks][0], accS[mt][2 * ks][1]);
                aph[mt][1] = pack_h16(accS[mt][2 * ks][2], accS[mt][2 * ks][3]);
                aph[mt][2] = pack_h16(accS[mt][2 * ks + 1][0], accS[mt][2 * ks + 1][1]);
                aph[mt][3] = pack_h16(accS[mt][2 * ks + 1][2], accS[mt][2 * ks + 1][3]);
            }
#pragma unroll
            for (int ne = 0; ne < 4; ne++)
#pragma unroll
                for (int mt = 0; mt < 2; mt++) mma16816h(accO[mt][ne], aph[mt], vbh[ne]);
        }
    }

    float* pout = part + (size_t)(((b * HH + h) * SPLITS + s) * 4 + vg) * LL * EE;
#pragma unroll
    for (int mt = 0; mt < 2; mt++) {
        int l = wl + mt * 16 + gid;
#pragma unroll
        for (int ne = 0; ne < 4; ne++) {
            int e = ne * 8 + tig * 2;
            *(float2*)(pout + l * EE + e) = make_float2(accO[mt][ne][0], accO[mt][ne][1]);
            *(float2*)(pout + (l + 8) * EE + e) = make_float2(accO[mt][ne][2], accO[mt][ne][3]);
        }
    }
}

__global__ void reduce_part(const float* __restrict__ part, float* __restrict__ reprog)
{
    int t = blockIdx.x * blockDim.x + threadIdx.x;
    if (t >= BB * LL * DM) return;
    int e = t & 31;
    int h = (t >> 5) & 7;
    int l = (t >> 8) & 127;
    int b = t >> 15;
    const float* p = part + (size_t)(b * HH + h) * SPL4 * LL * EE + l * EE + e;
    float acc = 0.f;
#pragma unroll
    for (int s2 = 0; s2 < SPL4; s2++) acc += p[(size_t)s2 * LL * EE];
    reprog[t] = acc;
}

// ============================================================
// Launch (attn_tc at launch index 3 for ncu)
// ============================================================
extern "C" void kernel_launch(void* const* d_in, const int* in_sizes, int n_in,
                              void* d_out, int out_size)
{
    (void)in_sizes; (void)n_in; (void)out_size;
    const float* ts = (const float*)d_in[0];
    const float* we = (const float*)d_in[1];
    const float* Wq = (const float*)d_in[2];
    const float* bq = (const float*)d_in[3];
    const float* Wk = (const float*)d_in[4];
    const float* bk = (const float*)d_in[5];
    const float* Wv = (const float*)d_in[6];
    const float* bv = (const float*)d_in[7];
    const float* Wo = (const float*)d_in[8];
    const float* bo = (const float*)d_in[9];
    float* out = (float*)d_out;

    float *gp, *gr, *gsg;
    __half *wk16, *wv16, *k16, *v16, *qh;
    cudaGetSymbolAddress((void**)&gp, g_part);
    cudaGetSymbolAddress((void**)&gr, g_reprog);
    cudaGetSymbolAddress((void**)&gsg, g_sg);
    cudaGetSymbolAddress((void**)&wk16, g_Wk16);
    cudaGetSymbolAddress((void**)&wv16, g_Wv16);
    cudaGetSymbolAddress((void**)&k16, g_K16);
    cudaGetSymbolAddress((void**)&v16, g_V16);
    cudaGetSymbolAddress((void**)&qh, g_Qh16);

    cudaFuncSetAttribute(kv_proj, cudaFuncAttributeMaxDynamicSharedMemorySize, KP_SMEM);
    cudaFuncSetAttribute(attn_tc, cudaFuncAttributeMaxDynamicSharedMemorySize, ATTN_SMEM);

    dim3 wb(32, 8);
    conv_w2<<<dim3(DW / 32, DM / 32, 2), wb>>>(Wk, Wv, wk16, wv16);             // idx 0
    qproj<<<dim3(BB * LL / 64, DM / 64), 256>>>(ts, Wq, bq, qh);                // idx 1
    kv_proj<<<dim3(VPAD / MROWS, 2), 256, KP_SMEM>>>(we, wk16, wv16,
                                                     bk, bv, k16, v16);         // idx 2
    attn_tc<<<dim3(SPLITS, HH, BB), 512, ATTN_SMEM>>>(qh, k16, v16, gp);        // idx 3 (profiled)
    reduce_part<<<(BB * LL * DM + 255) / 256, 256>>>(gp, gr);                   // idx 4
    sgemm64s<<<dim3(BB * LL / 64, DM / 64, 4), 256>>>(gr, Wo, gsg, BB * LL, DM, DM); // idx 5
    combine_bias<<<(BB * LL * DM + 255) / 256, 256>>>(gsg, bo, out);            // idx 6
}

// round 15
// speedup vs baseline: 2.2738x; 1.0021x over previous
#include <cuda_runtime.h>
#include <cuda_bf16.h>
#include <cuda_fp16.h>

#define BB 4
#define LL 128
#define DM 256
#define VV 50257
#define VPAD 50304          /* 393 * 128 */
#define NTILE 393
#define DW 768
#define HH 8
#define EE 32
#define SPLITS 9
#define SPL2 (SPLITS * 2)

// ---- scratch ----
__device__ float g_part[BB * HH * SPL2 * LL * EE];
__device__ float g_reprog[BB * LL * DM];
__device__ float g_sg[4 * BB * LL * DM];
__device__ __half g_Wk16[(size_t)DM * DW];
__device__ __half g_Wv16[(size_t)DM * DW];
__device__ __half g_K16[(size_t)VPAD * DM];
__device__ __half g_V16[(size_t)VPAD * DM];
__device__ __half g_Qh16[BB * LL * DM];

// ============================================================
// portable PTX helpers
// ============================================================
__device__ __forceinline__ unsigned smem_u32(const void* p) {
    unsigned a;
    asm("{ .reg .u64 t; cvta.to.shared.u64 t, %1; cvt.u32.u64 %0, t; }" : "=r"(a) : "l"(p));
    return a;
}
__device__ __forceinline__ void cp_async16(unsigned dst, const void* src) {
    asm volatile("cp.async.cg.shared.global [%0], [%1], 16;" :: "r"(dst), "l"(src));
}
#define CP_COMMIT() asm volatile("cp.async.commit_group;" ::: "memory")
#define CP_WAIT(n)  asm volatile("cp.async.wait_group %0;" :: "n"(n) : "memory")

__device__ __forceinline__ void ldsm_x4(unsigned* r, unsigned addr) {
    asm volatile("ldmatrix.sync.aligned.m8n8.x4.shared.b16 {%0,%1,%2,%3}, [%4];"
                 : "=r"(r[0]), "=r"(r[1]), "=r"(r[2]), "=r"(r[3]) : "r"(addr));
}
__device__ __forceinline__ void ldsm_x2_t(unsigned* r, unsigned addr) {
    asm volatile("ldmatrix.sync.aligned.m8n8.x2.trans.shared.b16 {%0,%1}, [%2];"
                 : "=r"(r[0]), "=r"(r[1]) : "r"(addr));
}
__device__ __forceinline__ void mma16816h(float* c, const unsigned* a, const unsigned* b) {
    asm volatile("mma.sync.aligned.m16n8k16.row.col.f32.f16.f16.f32 "
                 "{%0,%1,%2,%3}, {%4,%5,%6,%7}, {%8,%9}, {%0,%1,%2,%3};"
                 : "+f"(c[0]), "+f"(c[1]), "+f"(c[2]), "+f"(c[3])
                 : "r"(a[0]), "r"(a[1]), "r"(a[2]), "r"(a[3]), "r"(b[0]), "r"(b[1]));
}
__device__ __forceinline__ float ex2(float x) {
    float r;
    asm("ex2.approx.ftz.f32 %0, %1;" : "=f"(r) : "f"(x));
    return r;
}
__device__ __forceinline__ unsigned pack_h16(float a, float b) {
    __half2 t(__float2half(a), __float2half(b));
    return *(unsigned*)&t;
}

// ============================================================
// weight conversion: fp32 -> single fp16, transposed [N][K], K and V
// ============================================================
__global__ void conv_w2(const float* __restrict__ Wk, const float* __restrict__ Wv,
                        __half* __restrict__ Wk16, __half* __restrict__ Wv16)
{
    __shared__ float tile[32][33];
    const float* W = blockIdx.z ? Wv : Wk;
    __half* Wo = blockIdx.z ? Wv16 : Wk16;
    int k0 = blockIdx.x * 32, n0 = blockIdx.y * 32;
    int tx = threadIdx.x, ty = threadIdx.y;
    for (int r = ty; r < 32; r += 8)
        tile[r][tx] = W[(size_t)(k0 + r) * DM + n0 + tx];
    __syncthreads();
    for (int r = ty; r < 32; r += 8)
        Wo[(size_t)(n0 + r) * DW + k0 + tx] = __float2half(tile[tx][r]);
}

// ============================================================
// Q projection: fused fp32 GEMM + bias -> fp16
// ============================================================
__global__ __launch_bounds__(256) void qproj(
    const float* __restrict__ A, const float* __restrict__ Bw,
    const float* __restrict__ bias, __half* __restrict__ Qh)
{
    __shared__ float As[16][68];
    __shared__ float Bs[16][68];
    int t = threadIdx.x, tx = t & 15, ty = t >> 4;
    int mB = blockIdx.x * 64, nB = blockIdx.y * 64;
    float acc[4][4];
#pragma unroll
    for (int i = 0; i < 4; i++)
#pragma unroll
        for (int j = 0; j < 4; j++) acc[i][j] = 0.f;

    for (int k0 = 0; k0 < DM; k0 += 16) {
        {
            int row = t >> 2, kk = (t & 3) * 4;
            float4 av = *(const float4*)(A + (size_t)(mB + row) * DM + k0 + kk);
            As[kk + 0][row] = av.x; As[kk + 1][row] = av.y;
            As[kk + 2][row] = av.z; As[kk + 3][row] = av.w;
        }
        {
            int kr = t >> 4, c4 = (t & 15) * 4;
            *(float4*)&Bs[kr][c4] = *(const float4*)(Bw + (size_t)(k0 + kr) * DM + nB + c4);
        }
        __syncthreads();
#pragma unroll
        for (int kk = 0; kk < 16; kk++) {
            float4 a = *(const float4*)&As[kk][ty * 4];
            float4 b = *(const float4*)&Bs[kk][tx * 4];
            float am[4] = {a.x, a.y, a.z, a.w};
            float bn[4] = {b.x, b.y, b.z, b.w};
#pragma unroll
            for (int i = 0; i < 4; i++)
#pragma unroll
                for (int j = 0; j < 4; j++) acc[i][j] += am[i] * bn[j];
        }
        __syncthreads();
    }
#pragma unroll
    for (int i = 0; i < 4; i++) {
        int m = mB + ty * 4 + i;
#pragma unroll
        for (int j = 0; j < 4; j++) {
            int n = nB + tx * 4 + j;
            Qh[(size_t)m * DM + n] = __float2half(acc[i][j] + bias[n]);
        }
    }
}

// ============================================================
// KV projection GEMM — plain fp16, x4-paired W loads
// ============================================================
#define MROWS 64
#define KBK 32
#define SAH 0
#define SWH 5120
#define KP_STG 25600
#define KP_SMEM (2 * KP_STG)
#define KV_NCH (DW / KBK)
#define ASCALE 1024.0f
#define RSCALE 0.0009765625f

__global__ void __launch_bounds__(256, 2)
kv_proj(const float* __restrict__ we,
        const __half* __restrict__ Wk16, const __half* __restrict__ Wv16,
        const float* __restrict__ bk, const float* __restrict__ bv,
        __half* __restrict__ K16, __half* __restrict__ V16)
{
    extern __shared__ char smem[];
    unsigned sb = smem_u32(smem);
    int t = threadIdx.x, lane = t & 31, wid = t >> 5;
    int mBase = blockIdx.x * MROWS;
    int sel = blockIdx.y;
    const __half* Wh = sel ? Wv16 : Wk16;
    const float* bias = sel ? bv : bk;
    __half* o16 = sel ? V16 : K16;

    int wm = (wid & 1) * 32;
    int wn = (wid >> 1) * 64;

    float acc[2][8][4];
#pragma unroll
    for (int i = 0; i < 2; i++)
#pragma unroll
        for (int j = 0; j < 8; j++)
#pragma unroll
            for (int q = 0; q < 4; q++) acc[i][j][q] = 0.f;

    unsigned a_lof = (unsigned)((lane & 15) * 80 + (lane >> 4) * 16);
    // x4-paired B loads: lanes 0-15 matrix pair (rows nt*8..), lanes 16-31 next 8 rows
    unsigned w_lof4 = (unsigned)((((lane >> 4) * 8) + (lane & 7)) * 80 + ((lane >> 3) & 1) * 16);

    int ar0 = t >> 3, ac0 = t & 7;
    int ar1 = ar0 + 32;
    bool av0 = (mBase + ar0) < VV;
    bool av1 = (mBase + ar1) < VV;
    const float* ab0 = we + (size_t)(mBase + ar0) * DW + ac0 * 4;
    const float* ab1 = we + (size_t)(mBase + ar1) * DW + ac0 * 4;

    float4 aCur0, aCur1;
    auto ldA = [&](int c) {
        aCur0 = av0 ? *(const float4*)(ab0 + c * KBK) : make_float4(0.f, 0.f, 0.f, 0.f);
        aCur1 = av1 ? *(const float4*)(ab1 + c * KBK) : make_float4(0.f, 0.f, 0.f, 0.f);
    };
    auto convSTS = [&](int s) {
        *(uint2*)(smem + s * KP_STG + SAH + ar0 * 80 + ac0 * 8) =
            make_uint2(pack_h16(aCur0.x * ASCALE, aCur0.y * ASCALE),
                       pack_h16(aCur0.z * ASCALE, aCur0.w * ASCALE));
        *(uint2*)(smem + s * KP_STG + SAH + ar1 * 80 + ac0 * 8) =
            make_uint2(pack_h16(aCur1.x * ASCALE, aCur1.y * ASCALE),
                       pack_h16(aCur1.z * ASCALE, aCur1.w * ASCALE));
    };
    auto loadW = [&](int s, int k0) {
        unsigned stg = sb + s * KP_STG;
#pragma unroll
        for (int i = t; i < 1024; i += 256) {
            int row = i >> 2, c = i & 3;
            cp_async16(stg + SWH + row * 80 + c * 16,
                       Wh + (size_t)row * DW + k0 + c * 8);
        }
    };

    ldA(0);
    convSTS(0);
    loadW(0, 0);
    CP_COMMIT();
    ldA(1);
    convSTS(1);
    loadW(1, KBK);
    CP_COMMIT();
    CP_WAIT(1);
    __syncthreads();

    for (int c = 0; c < KV_NCH; c++) {
        int s = c & 1;
        if (c > 0) {
            CP_WAIT(0);
            __syncthreads();
        }
        if (c >= 1 && c + 1 < KV_NCH) {
            convSTS(1 - s);
            loadW(1 - s, (c + 1) * KBK);
            CP_COMMIT();
        }
        if (c + 2 < KV_NCH) ldA(c + 2);

        unsigned stg = sb + s * KP_STG;
        unsigned aHb = stg + SAH + wm * 80 + a_lof;
        unsigned wHb4 = stg + SWH + wn * 80 + w_lof4;

#pragma unroll
        for (int ks = 0; ks < 2; ks++) {
            unsigned kb = ks * 32;
            unsigned ah[2][4], bh[8][2];
#pragma unroll
            for (int mt = 0; mt < 2; mt++)
                ldsm_x4(ah[mt], aHb + mt * (16 * 80) + kb);
#pragma unroll
            for (int nt2 = 0; nt2 < 4; nt2++) {
                unsigned tmp[4];
                ldsm_x4(tmp, wHb4 + nt2 * (16 * 80) + kb);
                bh[2 * nt2][0] = tmp[0]; bh[2 * nt2][1] = tmp[1];
                bh[2 * nt2 + 1][0] = tmp[2]; bh[2 * nt2 + 1][1] = tmp[3];
            }
#pragma unroll
            for (int nt = 0; nt < 8; nt++)
#pragma unroll
                for (int mt = 0; mt < 2; mt++) mma16816h(acc[mt][nt], ah[mt], bh[nt]);
        }
    }

    int gid = lane >> 2, tig = lane & 3;
#pragma unroll
    for (int nt = 0; nt < 8; nt++) {
        int col = wn + nt * 8 + tig * 2;
        float2 bv2 = *(const float2*)(bias + col);
#pragma unroll
        for (int mt = 0; mt < 2; mt++) {
            int r0 = mBase + wm + mt * 16 + gid;
            int r1 = r0 + 8;
            float x0 = (r0 < VV) ? acc[mt][nt][0] * RSCALE + bv2.x : 0.f;
            float x1 = (r0 < VV) ? acc[mt][nt][1] * RSCALE + bv2.y : 0.f;
            float x2 = (r1 < VV) ? acc[mt][nt][2] * RSCALE + bv2.x : 0.f;
            float x3 = (r1 < VV) ? acc[mt][nt][3] * RSCALE + bv2.y : 0.f;
            *(unsigned*)(o16 + (size_t)r0 * DM + col) = pack_h16(x0, x1);
            *(unsigned*)(o16 + (size_t)r1 * DM + col) = pack_h16(x2, x3);
        }
    }
}

// ============================================================
// split-K fp32 SGEMM (O projection)
// ============================================================
__global__ __launch_bounds__(256) void sgemm64s(
    const float* __restrict__ A, const float* __restrict__ Bw,
    float* __restrict__ Cp, int M, int N, int K)
{
    __shared__ float As[16][68];
    __shared__ float Bs[16][68];
    int t = threadIdx.x, tx = t & 15, ty = t >> 4;
    int mB = blockIdx.x * 64, nB = blockIdx.y * 64;
    int kc = K / 4;
    int kBeg = blockIdx.z * kc, kEnd = kBeg + kc;
    float acc[4][4];
#pragma unroll
    for (int i = 0; i < 4; i++)
#pragma unroll
        for (int j = 0; j < 4; j++) acc[i][j] = 0.f;

    for (int k0 = kBeg; k0 < kEnd; k0 += 16) {
        {
            int row = t >> 2, kk = (t & 3) * 4;
            float4 av = *(const float4*)(A + (size_t)(mB + row) * K + k0 + kk);
            As[kk + 0][row] = av.x; As[kk + 1][row] = av.y;
            As[kk + 2][row] = av.z; As[kk + 3][row] = av.w;
        }
        {
            int kr = t >> 4, c4 = (t & 15) * 4;
            *(float4*)&Bs[kr][c4] = *(const float4*)(Bw + (size_t)(k0 + kr) * N + nB + c4);
        }
        __syncthreads();
#pragma unroll
        for (int kk = 0; kk < 16; kk++) {
            float4 a = *(const float4*)&As[kk][ty * 4];
            float4 b = *(const float4*)&Bs[kk][tx * 4];
            float am[4] = {a.x, a.y, a.z, a.w};
            float bn[4] = {b.x, b.y, b.z, b.w};
#pragma unroll
            for (int i = 0; i < 4; i++)
#pragma unroll
                for (int j = 0; j < 4; j++) acc[i][j] += am[i] * bn[j];
        }
        __syncthreads();
    }
    float* outz = Cp + (size_t)blockIdx.z * M * N;
#pragma unroll
    for (int i = 0; i < 4; i++) {
        int m = mB + ty * 4 + i;
#pragma unroll
        for (int j = 0; j < 4; j++) {
            int n = nB + tx * 4 + j;
            outz[(size_t)m * N + n] = acc[i][j];
        }
    }
}

__global__ void combine_bias(const float* __restrict__ Cp, const float* __restrict__ bias,
                             float* __restrict__ out)
{
    int i = blockIdx.x * blockDim.x + threadIdx.x;
    const int MN = BB * LL * DM;
    if (i >= MN) return;
    out[i] = Cp[i] + Cp[MN + i] + Cp[2 * MN + i] + Cp[3 * MN + i] + bias[i & (DM - 1)];
}

// ============================================================
// Tensor-core fused attention — fp16 single-term, 8 warps,
// 2 CTAs/SM (4 lg x 2 vg; warp tile 32l x 64v)
// ============================================================
#define KSTR 80
#define OFF_QH 0
#define OFF_KV 10240
#define KVBUF 20480
#define OFF_RED (OFF_KV + 2 * KVBUF)        /* 51200 */
#define OFF_RN  (OFF_RED + 2048)            /* 53248 */
#define ATTN_SMEM (OFF_RN + 512)            /* 53760 */

__global__ void __launch_bounds__(256, 2)
attn_tc(const __half* __restrict__ Qh,
        const __half* __restrict__ K16, const __half* __restrict__ V16,
        float* __restrict__ part)
{
    extern __shared__ char smem[];
    unsigned sb = smem_u32(smem);
    float* red = (float*)(smem + OFF_RED);
    float* rn  = (float*)(smem + OFF_RN);

    int t = threadIdx.x, lane = t & 31, wid = t >> 5;
    int s = blockIdx.x, h = blockIdx.y, b = blockIdx.z;
    int gid = lane >> 2, tig = lane & 3;
    int lg = wid & 3, vg = wid >> 2;
    int wl = lg * 32, wv = vg * 64;

    // ---- Q load: 128 rows x 64B ----
    {
        size_t qbase = (size_t)(b * LL) * DM + h * EE;
#pragma unroll
        for (int j = 0; j < 2; j++) {
            int idx = t + j * 256;
            int row = idx >> 2, c = idx & 3;
            cp_async16(sb + OFF_QH + row * KSTR + c * 16,
                       Qh + qbase + (size_t)row * DM + c * 8);
        }
    }
    CP_COMMIT();
    CP_WAIT(0);
    __syncthreads();

    unsigned qhf[2][2][4];
    {
        unsigned alof = (unsigned)((lane & 15) * KSTR + (lane >> 4) * 16);
#pragma unroll
        for (int mt = 0; mt < 2; mt++)
#pragma unroll
            for (int k = 0; k < 2; k++) {
                unsigned off = (wl + 16 * mt) * KSTR + alof + k * 32;
                ldsm_x4(qhf[mt][k], sb + OFF_QH + off);
            }
    }

    float accO[2][4][4];
#pragma unroll
    for (int i = 0; i < 2; i++)
#pragma unroll
        for (int j = 0; j < 4; j++)
#pragma unroll
            for (int q = 0; q < 4; q++) accO[i][j][q] = 0.f;

    size_t hof = (size_t)h * EE;
    auto load_kv = [&](int buf, int v0) {
        unsigned base = sb + OFF_KV + buf * KVBUF;
#pragma unroll
        for (int j = 0; j < 2; j++) {
            int idx = t + j * 256;
            int row = idx >> 2, c = idx & 3;
            size_t go = (size_t)(v0 + row) * DM + hof + c * 8;
            unsigned d = base + row * KSTR + c * 16;
            cp_async16(d,         K16 + go);
            cp_async16(d + 10240, V16 + go);
        }
    };

    load_kv(0, s * 128);
    CP_COMMIT();

    const float CC = 0.25503327723425473f;  // scale * log2(e)
    int l2 = lane & 15;
    unsigned kb_lof4 = (unsigned)((((lane >> 4) * 8) + (lane & 7)) * KSTR + ((lane >> 3) & 1) * 16);

    int it = 0;
    for (int tile = s; tile < NTILE; tile += SPLITS, it++) {
        CP_WAIT(0);
        __syncthreads();

        int nxt = tile + SPLITS;
        if (nxt < NTILE) {
            load_kv((it + 1) & 1, nxt * 128);
            CP_COMMIT();
        }
        unsigned kvb = sb + OFF_KV + (it & 1) * KVBUF;

        float accS[2][8][4];
#pragma unroll
        for (int mt = 0; mt < 2; mt++)
#pragma unroll
            for (int n = 0; n < 8; n++)
#pragma unroll
                for (int q = 0; q < 4; q++) accS[mt][n][q] = 0.f;

#pragma unroll
        for (int k = 0; k < 2; k++) {
            unsigned kbh[8][2];
#pragma unroll
            for (int n2 = 0; n2 < 4; n2++) {
                unsigned tmp[4];
                ldsm_x4(tmp, kvb + (wv + n2 * 16) * KSTR + kb_lof4 + k * 32);
                kbh[2 * n2][0] = tmp[0]; kbh[2 * n2][1] = tmp[1];
                kbh[2 * n2 + 1][0] = tmp[2]; kbh[2 * n2 + 1][1] = tmp[3];
            }
#pragma unroll
            for (int n = 0; n < 8; n++)
#pragma unroll
                for (int mt = 0; mt < 2; mt++) mma16816h(accS[mt][n], qhf[mt][k], kbh[n]);
        }

        // ---- softmax over l ----
        float s0[8], s1[8];
#pragma unroll
        for (int n = 0; n < 8; n++) { s0[n] = 0.f; s1[n] = 0.f; }
#pragma unroll
        for (int mt = 0; mt < 2; mt++)
#pragma unroll
            for (int n = 0; n < 8; n++) {
                accS[mt][n][0] = ex2(accS[mt][n][0] * CC);
                accS[mt][n][1] = ex2(accS[mt][n][1] * CC);
                accS[mt][n][2] = ex2(accS[mt][n][2] * CC);
                accS[mt][n][3] = ex2(accS[mt][n][3] * CC);
                s0[n] += accS[mt][n][0] + accS[mt][n][2];
                s1[n] += accS[mt][n][1] + accS[mt][n][3];
            }
#pragma unroll
        for (int n = 0; n < 8; n++) {
#pragma unroll
            for (int ofs = 4; ofs < 32; ofs <<= 1) {
                s0[n] += __shfl_xor_sync(0xffffffffu, s0[n], ofs);
                s1[n] += __shfl_xor_sync(0xffffffffu, s1[n], ofs);
            }
        }
        if (gid == 0) {
#pragma unroll
            for (int n = 0; n < 8; n++) {
                red[(wv + n * 8 + tig * 2) * 4 + lg] = s0[n];
                red[(wv + n * 8 + tig * 2 + 1) * 4 + lg] = s1[n];
            }
        }
        __syncthreads();
        if (t < 128) {
            float v = red[t * 4] + red[t * 4 + 1] + red[t * 4 + 2] + red[t * 4 + 3];
            rn[t] = 1.f / v;
        }
        __syncthreads();

#pragma unroll
        for (int n = 0; n < 8; n++) {
            float r0 = rn[wv + n * 8 + tig * 2];
            float r1 = rn[wv + n * 8 + tig * 2 + 1];
#pragma unroll
            for (int mt = 0; mt < 2; mt++) {
                accS[mt][n][0] *= r0;
                accS[mt][n][1] *= r1;
                accS[mt][n][2] *= r0;
                accS[mt][n][3] *= r1;
            }
        }

        // ---- O GEMM over warp's 64 v ----
#pragma unroll
        for (int ks = 0; ks < 4; ks++) {
            unsigned vbh[4][2];
#pragma unroll
            for (int ne = 0; ne < 4; ne++)
                ldsm_x2_t(vbh[ne], kvb + 10240 + (wv + ks * 16 + l2) * KSTR + ne * 16);
            unsigned aph[2][4];
#pragma unroll
            for (int mt = 0; mt < 2; mt++) {
                aph[mt][0] = pack_h16(accS[mt][2 * ks][0], accS[mt][2 * ks][1]);
                aph[mt][1] = pack_h16(accS[mt][2 * ks][2], accS[mt][2 * ks][3]);
                aph[mt][2] = pack_h16(accS[mt][2 * ks + 1][0], accS[mt][2 * ks + 1][1]);
                aph[mt][3] = pack_h16(accS[mt][2 * ks + 1][2], accS[mt][2 * ks + 1][3]);
            }
#pragma unroll
            for (int ne = 0; ne < 4; ne++)
#pragma unroll
                for (int mt = 0; mt < 2; mt++) mma16816h(accO[mt][ne], aph[mt], vbh[ne]);
        }
    }

    float* pout = part + (size_t)(((b * HH + h) * SPLITS + s) * 2 + vg) * LL * EE;
#pragma unroll
    for (int mt = 0; mt < 2; mt++) {
        int l = wl + mt * 16 + gid;
#pragma unroll
        for (int ne = 0; ne < 4; ne++) {
            int e = ne * 8 + tig * 2;
            *(float2*)(pout + l * EE + e) = make_float2(accO[mt][ne][0], accO[mt][ne][1]);
            *(float2*)(pout + (l + 8) * EE + e) = make_float2(accO[mt][ne][2], accO[mt][ne][3]);
        }
    }
}

__global__ void reduce_part(const float* __restrict__ part, float* __restrict__ reprog)
{
    int t = blockIdx.x * blockDim.x + threadIdx.x;
    if (t >= BB * LL * DM) return;
    int e = t & 31;
    int h = (t >> 5) & 7;
    int l = (t >> 8) & 127;
    int b = t >> 15;
    const float* p = part + (size_t)(b * HH + h) * SPL2 * LL * EE + l * EE + e;
    float acc = 0.f;
#pragma unroll
    for (int s2 = 0; s2 < SPL2; s2++) acc += p[(size_t)s2 * LL * EE];
    reprog[t] = acc;
}

// ============================================================
// Launch (attn_tc at launch index 3 for ncu)
// ============================================================
extern "C" void kernel_launch(void* const* d_in, const int* in_sizes, int n_in,
                              void* d_out, int out_size)
{
    (void)in_sizes; (void)n_in; (void)out_size;
    const float* ts = (const float*)d_in[0];
    const float* we = (const float*)d_in[1];
    const float* Wq = (const float*)d_in[2];
    const float* bq = (const float*)d_in[3];
    const float* Wk = (const float*)d_in[4];
    const float* bk = (const float*)d_in[5];
    const float* Wv = (const float*)d_in[6];
    const float* bv = (const float*)d_in[7];
    const float* Wo = (const float*)d_in[8];
    const float* bo = (const float*)d_in[9];
    float* out = (float*)d_out;

    float *gp, *gr, *gsg;
    __half *wk16, *wv16, *k16, *v16, *qh;
    cudaGetSymbolAddress((void**)&gp, g_part);
    cudaGetSymbolAddress((void**)&gr, g_reprog);
    cudaGetSymbolAddress((void**)&gsg, g_sg);
    cudaGetSymbolAddress((void**)&wk16, g_Wk16);
    cudaGetSymbolAddress((void**)&wv16, g_Wv16);
    cudaGetSymbolAddress((void**)&k16, g_K16);
    cudaGetSymbolAddress((void**)&v16, g_V16);
    cudaGetSymbolAddress((void**)&qh, g_Qh16);

    cudaFuncSetAttribute(kv_proj, cudaFuncAttributeMaxDynamicSharedMemorySize, KP_SMEM);
    cudaFuncSetAttribute(attn_tc, cudaFuncAttributeMaxDynamicSharedMemorySize, ATTN_SMEM);

    dim3 wb(32, 8);
    conv_w2<<<dim3(DW / 32, DM / 32, 2), wb>>>(Wk, Wv, wk16, wv16);             // idx 0
    qproj<<<dim3(BB * LL / 64, DM / 64), 256>>>(ts, Wq, bq, qh);                // idx 1
    kv_proj<<<dim3(VPAD / MROWS, 2), 256, KP_SMEM>>>(we, wk16, wv16,
                                                     bk, bv, k16, v16);         // idx 2
    attn_tc<<<dim3(SPLITS, HH, BB), 256, ATTN_SMEM>>>(qh, k16, v16, gp);        // idx 3 (profiled)
    reduce_part<<<(BB * LL * DM + 255) / 256, 256>>>(gp, gr);                   // idx 4
    sgemm64s<<<dim3(BB * LL / 64, DM / 64, 4), 256>>>(gr, Wo, gsg, BB * LL, DM, DM); // idx 5
    combine_bias<<<(BB * LL * DM + 255) / 256, 256>>>(gsg, bo, out);            // idx 6
}